// round 2
// baseline (speedup 1.0000x reference)
#include <cuda_runtime.h>
#include <math.h>

#define BATCH 2
#define S_LEN 2048
#define DM 1024
#define NH 16
#define NKV 4
#define HD 64
#define KV_W 512   // 2 * NKV * HD

// ---------------- scratch (device globals; no allocs allowed) ----------------
__device__ float g_q_raw[BATCH * S_LEN * DM];     // X @ Wq            [4096,1024]
__device__ float g_kv_raw[BATCH * S_LEN * KV_W];  // X @ Wkv           [4096,512]
__device__ float g_qh[BATCH * NH * S_LEN * HD];   // normed+roped q    [b,h,s,d]
__device__ float g_kh[BATCH * NKV * S_LEN * HD];  // normed+roped k    [b,kh,s,d]
__device__ float g_vh[BATCH * NKV * S_LEN * HD];  // v                 [b,kh,s,d]
__device__ float g_ao[BATCH * S_LEN * DM];        // attention output  [b,s,h*d]

// ---------------- SGEMM: C[M,N] = A[M,K] @ B[K,N], all row-major -------------
#define BM 128
#define BN 128
#define BK 16
#define TM 8
#define TN 8

__global__ __launch_bounds__(256) void sgemm128(const float* __restrict__ A,
                                                const float* __restrict__ B,
                                                float* __restrict__ C,
                                                int M, int N, int K) {
    __shared__ __align__(16) float As[BK][BM];
    __shared__ __align__(16) float Bs[BK][BN];

    int tid = threadIdx.x;
    int bm = blockIdx.y, bn = blockIdx.x;
    const float* Ab = A + (size_t)bm * BM * K;
    const float* Bb = B + (size_t)bn * BN;

    int tr = tid >> 4;        // 0..15
    int tc = tid & 15;        // 0..15

    float acc[TM][TN];
#pragma unroll
    for (int i = 0; i < TM; i++)
#pragma unroll
        for (int j = 0; j < TN; j++) acc[i][j] = 0.0f;

    for (int k0 = 0; k0 < K; k0 += BK) {
        // load A tile (128x16) transposed into As[16][128]
#pragma unroll
        for (int i = 0; i < 2; i++) {
            int idx = tid + i * 256;           // float4 index, 0..511
            int row = idx >> 2;                // 0..127
            int kc = (idx & 3) * 4;            // 0,4,8,12
            float4 v = *(const float4*)(Ab + (size_t)row * K + k0 + kc);
            As[kc + 0][row] = v.x;
            As[kc + 1][row] = v.y;
            As[kc + 2][row] = v.z;
            As[kc + 3][row] = v.w;
        }
        // load B tile (16x128)
#pragma unroll
        for (int i = 0; i < 2; i++) {
            int idx = tid + i * 256;           // 0..511
            int row = idx >> 5;                // 0..15
            int c4 = (idx & 31) * 4;           // 0..124
            *(float4*)(&Bs[row][c4]) =
                *(const float4*)(Bb + (size_t)(k0 + row) * N + c4);
        }
        __syncthreads();

#pragma unroll
        for (int k = 0; k < BK; k++) {
            float a[TM], b[TN];
#pragma unroll
            for (int i = 0; i < TM; i += 4) {
                float4 v = *(const float4*)(&As[k][tr * TM + i]);
                a[i] = v.x; a[i + 1] = v.y; a[i + 2] = v.z; a[i + 3] = v.w;
            }
#pragma unroll
            for (int j = 0; j < TN; j += 4) {
                float4 v = *(const float4*)(&Bs[k][tc * TN + j]);
                b[j] = v.x; b[j + 1] = v.y; b[j + 2] = v.z; b[j + 3] = v.w;
            }
#pragma unroll
            for (int i = 0; i < TM; i++)
#pragma unroll
                for (int j = 0; j < TN; j++)
                    acc[i][j] = fmaf(a[i], b[j], acc[i][j]);
        }
        __syncthreads();
    }

    float* Cb = C + (size_t)(bm * BM + tr * TM) * N + bn * BN + tc * TN;
#pragma unroll
    for (int i = 0; i < TM; i++) {
#pragma unroll
        for (int j = 0; j < TN; j += 4) {
            float4 v;
            v.x = acc[i][j]; v.y = acc[i][j + 1]; v.z = acc[i][j + 2]; v.w = acc[i][j + 3];
            *(float4*)(Cb + (size_t)i * N + j) = v;
        }
    }
}

// ---------------- RMSNorm + RoPE (one warp per (b,s,head) row) ----------------
// in:  [B*S, in_ld] with head h at columns h*64..h*64+63
// out: [b, nheads, s, 64]
__device__ const double c_inv8[8] = {
    1.0, 0.74989420933245582, 0.56234132519034912, 0.42169650342858224,
    0.31622776601683794, 0.23713737056616552, 0.17782794100389229,
    0.13335214321633241};
__device__ const double c_p10[4] = {1.0, 0.1, 0.01, 0.001};

__global__ void normrope_kernel(const float* __restrict__ in,
                                float* __restrict__ outp,
                                const float* __restrict__ scale,
                                int nheads, int in_ld) {
    int gw = (blockIdx.x * blockDim.x + threadIdx.x) >> 5;
    int lane = threadIdx.x & 31;
    int total = BATCH * S_LEN * nheads;
    if (gw >= total) return;
    int h = gw % nheads;
    int s = (gw / nheads) % S_LEN;
    int b = gw / (nheads * S_LEN);

    const float* ip = in + ((size_t)(b * S_LEN + s)) * in_ld + h * HD;
    float x1 = ip[lane];
    float x2 = ip[lane + 32];
    float ss = x1 * x1 + x2 * x2;
#pragma unroll
    for (int o = 16; o; o >>= 1) ss += __shfl_xor_sync(0xffffffffu, ss, o);
    float inv = rsqrtf(ss * (1.0f / 64.0f) + 1e-5f);
    x1 *= inv * scale[lane];
    x2 *= inv * scale[lane + 32];

    // inv_freq[j] = 10000^(-j/32) = 10^(-j/8), computed exactly then rounded
    float invf = (float)(c_inv8[lane & 7] * c_p10[lane >> 3]);
    float f = (float)s * invf;
    float c, sn;
    sincosf(f, &sn, &c);   // NOTE: sincosf(x, SIN*, COS*) — sin comes first!

    float* op = outp + (((size_t)(b * nheads + h)) * S_LEN + s) * HD;
    op[lane] = x1 * c - x2 * sn;
    op[lane + 32] = x1 * sn + x2 * c;
}

// ---------------- V rearrange: kv_raw cols [256:512] -> [b,kh,s,d] -----------
__global__ void vcopy_kernel() {
    int idx = blockIdx.x * blockDim.x + threadIdx.x;   // float4 index
    int total = BATCH * NKV * S_LEN * (HD / 4);
    if (idx >= total) return;
    int c4 = idx & 15;
    int tmp = idx >> 4;
    int s = tmp % S_LEN;
    int bk = tmp / S_LEN;             // b*NKV + kvh
    int kvh = bk % NKV;
    int b = bk / NKV;
    float4 v = *(const float4*)(g_kv_raw + ((size_t)(b * S_LEN + s)) * KV_W +
                                (NKV * HD) + kvh * HD + c4 * 4);
    *(float4*)(g_vh + ((size_t)bk * S_LEN + s) * HD + c4 * 4) = v;
}

// ---------------- causal GQA flash attention ---------------------------------
// 128 query rows / CTA, 2 threads per row (32 dims each), key tiles of 64.
__global__ __launch_bounds__(256) void attn_kernel() {
    __shared__ __align__(16) float Ks[64][64];
    __shared__ __align__(16) float Vs[64][64];

    int b = blockIdx.z, h = blockIdx.y;
    int mb = (int)(gridDim.x - 1) - (int)blockIdx.x;  // heavy blocks first
    int kvh = h >> 2;
    int t = threadIdx.x;
    int rl = t >> 1;
    int half = t & 1;
    int d0 = half * 32;
    int row = mb * 128 + rl;

    const float* qp = g_qh + (((size_t)(b * NH + h)) * S_LEN + row) * HD + d0;
    float q[32];
#pragma unroll
    for (int i = 0; i < 8; i++) {
        float4 v = *(const float4*)(qp + i * 4);
        q[i * 4 + 0] = v.x * 0.125f;
        q[i * 4 + 1] = v.y * 0.125f;
        q[i * 4 + 2] = v.z * 0.125f;
        q[i * 4 + 3] = v.w * 0.125f;
    }
    const float* kb = g_kh + ((size_t)(b * NKV + kvh)) * S_LEN * HD;
    const float* vb = g_vh + ((size_t)(b * NKV + kvh)) * S_LEN * HD;

    float m_i = -1e30f, l_i = 0.0f;
    float o[32];
#pragma unroll
    for (int i = 0; i < 32; i++) o[i] = 0.0f;

    int ntiles = mb * 2 + 2;
    for (int nt = 0; nt < ntiles; nt++) {
        int n0 = nt * 64;
#pragma unroll
        for (int i = 0; i < 4; i++) {
            int idx = t + i * 256;            // float4 index 0..1023
            int rr = idx >> 4;                // 0..63
            int cc = (idx & 15) * 4;          // 0..60
            *(float4*)(&Ks[rr][cc]) = *(const float4*)(kb + (size_t)(n0 + rr) * HD + cc);
            *(float4*)(&Vs[rr][cc]) = *(const float4*)(vb + (size_t)(n0 + rr) * HD + cc);
        }
        __syncthreads();

        float sv[64];
        float tmax = -1e30f;
#pragma unroll
        for (int n = 0; n < 64; n++) {
            float p = 0.0f;
#pragma unroll
            for (int dd = 0; dd < 32; dd += 4) {
                float4 k4 = *(const float4*)(&Ks[n][d0 + dd]);
                p = fmaf(q[dd + 0], k4.x, p);
                p = fmaf(q[dd + 1], k4.y, p);
                p = fmaf(q[dd + 2], k4.z, p);
                p = fmaf(q[dd + 3], k4.w, p);
            }
            p += __shfl_xor_sync(0xffffffffu, p, 1);
            if (n0 + n > row) p = -1e30f;     // causal mask
            sv[n] = p;
            tmax = fmaxf(tmax, p);
        }

        float m_new = fmaxf(m_i, tmax);
        float corr = expf(m_i - m_new);
        l_i *= corr;
#pragma unroll
        for (int i = 0; i < 32; i++) o[i] *= corr;

#pragma unroll
        for (int n = 0; n < 64; n++) {
            float pn = expf(sv[n] - m_new);
            l_i += pn;
#pragma unroll
            for (int dd = 0; dd < 32; dd += 4) {
                float4 v4 = *(const float4*)(&Vs[n][d0 + dd]);
                o[dd + 0] = fmaf(pn, v4.x, o[dd + 0]);
                o[dd + 1] = fmaf(pn, v4.y, o[dd + 1]);
                o[dd + 2] = fmaf(pn, v4.z, o[dd + 2]);
                o[dd + 3] = fmaf(pn, v4.w, o[dd + 3]);
            }
        }
        m_i = m_new;
        __syncthreads();
    }

    float invl = 1.0f / l_i;
    float* op = g_ao + ((size_t)(b * S_LEN + row)) * DM + h * HD + d0;
#pragma unroll
    for (int i = 0; i < 8; i++) {
        float4 v;
        v.x = o[i * 4 + 0] * invl;
        v.y = o[i * 4 + 1] * invl;
        v.z = o[i * 4 + 2] * invl;
        v.w = o[i * 4 + 3] * invl;
        *(float4*)(op + i * 4) = v;
    }
}

// ---------------- launcher ----------------------------------------------------
extern "C" void kernel_launch(void* const* d_in, const int* in_sizes, int n_in,
                              void* d_out, int out_size) {
    const float* x   = (const float*)d_in[0];
    const float* Wq  = (const float*)d_in[1];
    const float* Wkv = (const float*)d_in[2];
    const float* Wo  = (const float*)d_in[3];
    const float* qs  = (const float*)d_in[4];
    const float* ks  = (const float*)d_in[5];
    float* out = (float*)d_out;

    float *pqraw, *pkvraw, *pqh, *pkh, *pao;
    cudaGetSymbolAddress((void**)&pqraw, g_q_raw);
    cudaGetSymbolAddress((void**)&pkvraw, g_kv_raw);
    cudaGetSymbolAddress((void**)&pqh, g_qh);
    cudaGetSymbolAddress((void**)&pkh, g_kh);
    cudaGetSymbolAddress((void**)&pao, g_ao);

    int M = BATCH * S_LEN;  // 4096

    // 1) projections
    sgemm128<<<dim3(DM / BN, M / BM), 256>>>(x, Wq, pqraw, M, DM, DM);
    sgemm128<<<dim3(KV_W / BN, M / BM), 256>>>(x, Wkv, pkvraw, M, KV_W, DM);

    // 2) rmsnorm + rope
    normrope_kernel<<<(M * NH * 32 + 255) / 256, 256>>>(pqraw, pqh, qs, NH, DM);
    normrope_kernel<<<(M * NKV * 32 + 255) / 256, 256>>>(pkvraw, pkh, ks, NKV, KV_W);

    // 3) v rearrange
    vcopy_kernel<<<(BATCH * NKV * S_LEN * (HD / 4) + 255) / 256, 256>>>();

    // 4) causal GQA attention
    attn_kernel<<<dim3(S_LEN / 128, NH, BATCH), 256>>>();

    // 5) output projection
    sgemm128<<<dim3(DM / BN, M / BM), 256>>>(pao, Wo, out, M, DM, DM);
}

// round 3
// speedup vs baseline: 1.2077x; 1.2077x over previous
#include <cuda_runtime.h>
#include <cuda_bf16.h>
#include <math.h>
#include <stdint.h>

#define BATCH 2
#define S_LEN 2048
#define DM 1024
#define NH 16
#define NKV 4
#define HD 64
#define KV_W 512   // 2 * NKV * HD

// ---------------- scratch (device globals; no allocs allowed) ----------------
__device__ float g_q_raw[BATCH * S_LEN * DM];     // X @ Wq            [4096,1024]
__device__ float g_kv_raw[BATCH * S_LEN * KV_W];  // X @ Wkv           [4096,512]
__device__ float g_qh[BATCH * NH * S_LEN * HD];   // normed+roped q    [b,h,s,d]
__device__ float g_kh[BATCH * NKV * S_LEN * HD];  // normed+roped k    [b,kh,s,d]
__device__ float g_vh[BATCH * NKV * S_LEN * HD];  // v                 [b,kh,s,d]
__device__ float g_ao[BATCH * S_LEN * DM];        // attention output  [b,s,h*d]

// bf16 split buffers (hi/lo) for tensor-core GEMMs
__device__ __nv_bfloat16 g_xh[BATCH * S_LEN * DM];
__device__ __nv_bfloat16 g_xl[BATCH * S_LEN * DM];
__device__ __nv_bfloat16 g_wqh[DM * DM];
__device__ __nv_bfloat16 g_wql[DM * DM];
__device__ __nv_bfloat16 g_wkvh[DM * KV_W];
__device__ __nv_bfloat16 g_wkvl[DM * KV_W];
__device__ __nv_bfloat16 g_woh[DM * DM];
__device__ __nv_bfloat16 g_wol[DM * DM];
__device__ __nv_bfloat16 g_aoh[BATCH * S_LEN * DM];
__device__ __nv_bfloat16 g_aol[BATCH * S_LEN * DM];

// ---------------- fp32 -> (hi, lo) bf16 split --------------------------------
__global__ void cvt_split(const float* __restrict__ in,
                          __nv_bfloat16* __restrict__ hi,
                          __nv_bfloat16* __restrict__ lo, int n4) {
    int i = blockIdx.x * blockDim.x + threadIdx.x;
    if (i >= n4) return;
    float4 v = *(const float4*)(in + (size_t)i * 4);
    __nv_bfloat16 h0 = __float2bfloat16(v.x);
    __nv_bfloat16 h1 = __float2bfloat16(v.y);
    __nv_bfloat16 h2 = __float2bfloat16(v.z);
    __nv_bfloat16 h3 = __float2bfloat16(v.w);
    __nv_bfloat16 l0 = __float2bfloat16(v.x - __bfloat162float(h0));
    __nv_bfloat16 l1 = __float2bfloat16(v.y - __bfloat162float(h1));
    __nv_bfloat16 l2 = __float2bfloat16(v.z - __bfloat162float(h2));
    __nv_bfloat16 l3 = __float2bfloat16(v.w - __bfloat162float(h3));
    __nv_bfloat162* hp = (__nv_bfloat162*)(hi + (size_t)i * 4);
    __nv_bfloat162* lp = (__nv_bfloat162*)(lo + (size_t)i * 4);
    hp[0] = __nv_bfloat162(h0, h1); hp[1] = __nv_bfloat162(h2, h3);
    lp[0] = __nv_bfloat162(l0, l1); lp[1] = __nv_bfloat162(l2, l3);
}

// ---------------- mma helpers ------------------------------------------------
__device__ __forceinline__ uint32_t smem_u32(const void* p) {
    return (uint32_t)__cvta_generic_to_shared(p);
}
__device__ __forceinline__ void ldsm_x4(uint32_t& r0, uint32_t& r1,
                                        uint32_t& r2, uint32_t& r3, uint32_t a) {
    asm volatile("ldmatrix.sync.aligned.m8n8.x4.shared.b16 {%0,%1,%2,%3},[%4];"
                 : "=r"(r0), "=r"(r1), "=r"(r2), "=r"(r3) : "r"(a));
}
__device__ __forceinline__ void ldsm_x4_t(uint32_t& r0, uint32_t& r1,
                                          uint32_t& r2, uint32_t& r3, uint32_t a) {
    asm volatile("ldmatrix.sync.aligned.m8n8.x4.trans.shared.b16 {%0,%1,%2,%3},[%4];"
                 : "=r"(r0), "=r"(r1), "=r"(r2), "=r"(r3) : "r"(a));
}
__device__ __forceinline__ void mma_bf16(float* c, const uint32_t* a,
                                         const uint32_t* b) {
    asm volatile(
        "mma.sync.aligned.m16n8k16.row.col.f32.bf16.bf16.f32 "
        "{%0,%1,%2,%3},{%4,%5,%6,%7},{%8,%9},{%0,%1,%2,%3};"
        : "+f"(c[0]), "+f"(c[1]), "+f"(c[2]), "+f"(c[3])
        : "r"(a[0]), "r"(a[1]), "r"(a[2]), "r"(a[3]), "r"(b[0]), "r"(b[1]));
}

// ---------------- 3x bf16-split tensor-core GEMM -----------------------------
// C[M,N](f32) = A[M,K](f32-as-splits) @ B[K,N]
// virtual K' = 3K: seg0 Ah*Bh, seg1 Ah*Bl, seg2 Al*Bh
#define GBM 128
#define GBN 128
#define GBK 32

__global__ __launch_bounds__(256) void gemm_bf16_3x(
    const __nv_bfloat16* __restrict__ Ah, const __nv_bfloat16* __restrict__ Al,
    const __nv_bfloat16* __restrict__ Bh, const __nv_bfloat16* __restrict__ Bl,
    float* __restrict__ C, int M, int N, int K) {
    __shared__ __align__(16) __nv_bfloat16 As[GBM][GBK + 8];   // stride 40
    __shared__ __align__(16) __nv_bfloat16 Bs[GBK][GBN + 8];   // stride 136

    int tid = threadIdx.x;
    int wid = tid >> 5, lane = tid & 31;
    int bm = blockIdx.y * GBM, bn = blockIdx.x * GBN;
    int wm = (wid & 1) * 64;        // warp m offset in tile
    int wn = (wid >> 1) * 32;       // warp n offset in tile

    float acc[4][4][4];
#pragma unroll
    for (int i = 0; i < 4; i++)
#pragma unroll
        for (int j = 0; j < 4; j++)
#pragma unroll
            for (int e = 0; e < 4; e++) acc[i][j][e] = 0.0f;

    for (int kk = 0; kk < 3 * K; kk += GBK) {
        int seg = kk / K;
        int kl = kk - seg * K;
        const __nv_bfloat16* Aseg = (seg < 2) ? Ah : Al;
        const __nv_bfloat16* Bseg = (seg == 1) ? Bl : Bh;

        // load A tile 128x32 (8 bf16 per thread per iter)
#pragma unroll
        for (int i = 0; i < 2; i++) {
            int idx = tid + i * 256;          // 0..511
            int r = idx >> 2;                 // 0..127
            int c8 = (idx & 3) * 8;           // 0,8,16,24
            *(uint4*)&As[r][c8] =
                *(const uint4*)(Aseg + (size_t)(bm + r) * K + kl + c8);
        }
        // load B tile 32x128
#pragma unroll
        for (int i = 0; i < 2; i++) {
            int idx = tid + i * 256;          // 0..511
            int r = idx >> 4;                 // 0..31
            int c8 = (idx & 15) * 8;          // 0..120
            *(uint4*)&Bs[r][c8] =
                *(const uint4*)(Bseg + (size_t)(kl + r) * N + bn + c8);
        }
        __syncthreads();

#pragma unroll
        for (int k0 = 0; k0 < GBK; k0 += 16) {
            uint32_t a[4][4];
#pragma unroll
            for (int mt = 0; mt < 4; mt++) {
                int row = wm + mt * 16 + (lane & 15);
                int col = k0 + (lane >> 4) * 8;
                ldsm_x4(a[mt][0], a[mt][1], a[mt][2], a[mt][3],
                        smem_u32(&As[row][col]));
            }
            uint32_t b[4][2];
#pragma unroll
            for (int np = 0; np < 2; np++) {
                int r = k0 + (lane & 15);
                int col = wn + np * 16 + (lane >> 4) * 8;
                uint32_t t0, t1, t2, t3;
                ldsm_x4_t(t0, t1, t2, t3, smem_u32(&Bs[r][col]));
                b[np * 2 + 0][0] = t0; b[np * 2 + 0][1] = t1;
                b[np * 2 + 1][0] = t2; b[np * 2 + 1][1] = t3;
            }
#pragma unroll
            for (int mt = 0; mt < 4; mt++)
#pragma unroll
                for (int nt = 0; nt < 4; nt++)
                    mma_bf16(acc[mt][nt], a[mt], b[nt]);
        }
        __syncthreads();
    }

    // store C
    int g = lane >> 2, tg = lane & 3;
#pragma unroll
    for (int mt = 0; mt < 4; mt++) {
#pragma unroll
        for (int nt = 0; nt < 4; nt++) {
            int row = bm + wm + mt * 16 + g;
            int col = bn + wn + nt * 8 + tg * 2;
            *(float2*)&C[(size_t)row * N + col] =
                make_float2(acc[mt][nt][0], acc[mt][nt][1]);
            *(float2*)&C[(size_t)(row + 8) * N + col] =
                make_float2(acc[mt][nt][2], acc[mt][nt][3]);
        }
    }
}

// ---------------- RMSNorm + RoPE (one warp per (b,s,head) row) ----------------
__device__ const double c_inv8[8] = {
    1.0, 0.74989420933245582, 0.56234132519034912, 0.42169650342858224,
    0.31622776601683794, 0.23713737056616552, 0.17782794100389229,
    0.13335214321633241};
__device__ const double c_p10[4] = {1.0, 0.1, 0.01, 0.001};

__global__ void normrope_kernel(const float* __restrict__ in,
                                float* __restrict__ outp,
                                const float* __restrict__ scale,
                                int nheads, int in_ld) {
    int gw = (blockIdx.x * blockDim.x + threadIdx.x) >> 5;
    int lane = threadIdx.x & 31;
    int total = BATCH * S_LEN * nheads;
    if (gw >= total) return;
    int h = gw % nheads;
    int s = (gw / nheads) % S_LEN;
    int b = gw / (nheads * S_LEN);

    const float* ip = in + ((size_t)(b * S_LEN + s)) * in_ld + h * HD;
    float x1 = ip[lane];
    float x2 = ip[lane + 32];
    float ss = x1 * x1 + x2 * x2;
#pragma unroll
    for (int o = 16; o; o >>= 1) ss += __shfl_xor_sync(0xffffffffu, ss, o);
    float inv = rsqrtf(ss * (1.0f / 64.0f) + 1e-5f);
    x1 *= inv * scale[lane];
    x2 *= inv * scale[lane + 32];

    float invf = (float)(c_inv8[lane & 7] * c_p10[lane >> 3]);
    float f = (float)s * invf;
    float c, sn;
    sincosf(f, &sn, &c);   // sincosf(x, SIN*, COS*)

    float* op = outp + (((size_t)(b * nheads + h)) * S_LEN + s) * HD;
    op[lane] = x1 * c - x2 * sn;
    op[lane + 32] = x1 * sn + x2 * c;
}

// ---------------- V rearrange: kv_raw cols [256:512] -> [b,kh,s,d] -----------
__global__ void vcopy_kernel() {
    int idx = blockIdx.x * blockDim.x + threadIdx.x;   // float4 index
    int total = BATCH * NKV * S_LEN * (HD / 4);
    if (idx >= total) return;
    int c4 = idx & 15;
    int tmp = idx >> 4;
    int s = tmp % S_LEN;
    int bk = tmp / S_LEN;             // b*NKV + kvh
    int kvh = bk % NKV;
    int b = bk / NKV;
    float4 v = *(const float4*)(g_kv_raw + ((size_t)(b * S_LEN + s)) * KV_W +
                                (NKV * HD) + kvh * HD + c4 * 4);
    *(float4*)(g_vh + ((size_t)bk * S_LEN + s) * HD + c4 * 4) = v;
}

// ---------------- causal GQA flash attention (fp32) ---------------------------
__global__ __launch_bounds__(256) void attn_kernel() {
    __shared__ __align__(16) float Ks[64][64];
    __shared__ __align__(16) float Vs[64][64];

    int b = blockIdx.z, h = blockIdx.y;
    int mb = (int)(gridDim.x - 1) - (int)blockIdx.x;  // heavy blocks first
    int kvh = h >> 2;
    int t = threadIdx.x;
    int rl = t >> 1;
    int half = t & 1;
    int d0 = half * 32;
    int row = mb * 128 + rl;

    const float* qp = g_qh + (((size_t)(b * NH + h)) * S_LEN + row) * HD + d0;
    float q[32];
#pragma unroll
    for (int i = 0; i < 8; i++) {
        float4 v = *(const float4*)(qp + i * 4);
        q[i * 4 + 0] = v.x * 0.125f;
        q[i * 4 + 1] = v.y * 0.125f;
        q[i * 4 + 2] = v.z * 0.125f;
        q[i * 4 + 3] = v.w * 0.125f;
    }
    const float* kb = g_kh + ((size_t)(b * NKV + kvh)) * S_LEN * HD;
    const float* vb = g_vh + ((size_t)(b * NKV + kvh)) * S_LEN * HD;

    float m_i = -1e30f, l_i = 0.0f;
    float o[32];
#pragma unroll
    for (int i = 0; i < 32; i++) o[i] = 0.0f;

    int ntiles = mb * 2 + 2;
    for (int nt = 0; nt < ntiles; nt++) {
        int n0 = nt * 64;
#pragma unroll
        for (int i = 0; i < 4; i++) {
            int idx = t + i * 256;            // float4 index 0..1023
            int rr = idx >> 4;                // 0..63
            int cc = (idx & 15) * 4;          // 0..60
            *(float4*)(&Ks[rr][cc]) = *(const float4*)(kb + (size_t)(n0 + rr) * HD + cc);
            *(float4*)(&Vs[rr][cc]) = *(const float4*)(vb + (size_t)(n0 + rr) * HD + cc);
        }
        __syncthreads();

        float sv[64];
        float tmax = -1e30f;
#pragma unroll
        for (int n = 0; n < 64; n++) {
            float p = 0.0f;
#pragma unroll
            for (int dd = 0; dd < 32; dd += 4) {
                float4 k4 = *(const float4*)(&Ks[n][d0 + dd]);
                p = fmaf(q[dd + 0], k4.x, p);
                p = fmaf(q[dd + 1], k4.y, p);
                p = fmaf(q[dd + 2], k4.z, p);
                p = fmaf(q[dd + 3], k4.w, p);
            }
            p += __shfl_xor_sync(0xffffffffu, p, 1);
            if (n0 + n > row) p = -1e30f;     // causal mask
            sv[n] = p;
            tmax = fmaxf(tmax, p);
        }

        float m_new = fmaxf(m_i, tmax);
        float corr = expf(m_i - m_new);
        l_i *= corr;
#pragma unroll
        for (int i = 0; i < 32; i++) o[i] *= corr;

#pragma unroll
        for (int n = 0; n < 64; n++) {
            float pn = expf(sv[n] - m_new);
            l_i += pn;
#pragma unroll
            for (int dd = 0; dd < 32; dd += 4) {
                float4 v4 = *(const float4*)(&Vs[n][d0 + dd]);
                o[dd + 0] = fmaf(pn, v4.x, o[dd + 0]);
                o[dd + 1] = fmaf(pn, v4.y, o[dd + 1]);
                o[dd + 2] = fmaf(pn, v4.z, o[dd + 2]);
                o[dd + 3] = fmaf(pn, v4.w, o[dd + 3]);
            }
        }
        m_i = m_new;
        __syncthreads();
    }

    float invl = 1.0f / l_i;
    float* op = g_ao + ((size_t)(b * S_LEN + row)) * DM + h * HD + d0;
#pragma unroll
    for (int i = 0; i < 8; i++) {
        float4 v;
        v.x = o[i * 4 + 0] * invl;
        v.y = o[i * 4 + 1] * invl;
        v.z = o[i * 4 + 2] * invl;
        v.w = o[i * 4 + 3] * invl;
        *(float4*)(op + i * 4) = v;
    }
}

// ---------------- launcher ----------------------------------------------------
extern "C" void kernel_launch(void* const* d_in, const int* in_sizes, int n_in,
                              void* d_out, int out_size) {
    const float* x   = (const float*)d_in[0];
    const float* Wq  = (const float*)d_in[1];
    const float* Wkv = (const float*)d_in[2];
    const float* Wo  = (const float*)d_in[3];
    const float* qs  = (const float*)d_in[4];
    const float* ks  = (const float*)d_in[5];
    float* out = (float*)d_out;

    float *pqraw, *pkvraw, *pqh, *pkh, *pao;
    cudaGetSymbolAddress((void**)&pqraw, g_q_raw);
    cudaGetSymbolAddress((void**)&pkvraw, g_kv_raw);
    cudaGetSymbolAddress((void**)&pqh, g_qh);
    cudaGetSymbolAddress((void**)&pkh, g_kh);
    cudaGetSymbolAddress((void**)&pao, g_ao);

    __nv_bfloat16 *pxh, *pxl, *pwqh, *pwql, *pwkvh, *pwkvl, *pwoh, *pwol, *paoh, *paol;
    cudaGetSymbolAddress((void**)&pxh, g_xh);
    cudaGetSymbolAddress((void**)&pxl, g_xl);
    cudaGetSymbolAddress((void**)&pwqh, g_wqh);
    cudaGetSymbolAddress((void**)&pwql, g_wql);
    cudaGetSymbolAddress((void**)&pwkvh, g_wkvh);
    cudaGetSymbolAddress((void**)&pwkvl, g_wkvl);
    cudaGetSymbolAddress((void**)&pwoh, g_woh);
    cudaGetSymbolAddress((void**)&pwol, g_wol);
    cudaGetSymbolAddress((void**)&paoh, g_aoh);
    cudaGetSymbolAddress((void**)&paol, g_aol);

    int M = BATCH * S_LEN;  // 4096

    // 0) split-convert inputs to bf16 hi/lo
    cvt_split<<<(M * DM / 4 + 255) / 256, 256>>>(x, pxh, pxl, M * DM / 4);
    cvt_split<<<(DM * DM / 4 + 255) / 256, 256>>>(Wq, pwqh, pwql, DM * DM / 4);
    cvt_split<<<(DM * KV_W / 4 + 255) / 256, 256>>>(Wkv, pwkvh, pwkvl, DM * KV_W / 4);
    cvt_split<<<(DM * DM / 4 + 255) / 256, 256>>>(Wo, pwoh, pwol, DM * DM / 4);

    // 1) projections (tensor cores, 3x bf16 split)
    gemm_bf16_3x<<<dim3(DM / GBN, M / GBM), 256>>>(pxh, pxl, pwqh, pwql, pqraw, M, DM, DM);
    gemm_bf16_3x<<<dim3(KV_W / GBN, M / GBM), 256>>>(pxh, pxl, pwkvh, pwkvl, pkvraw, M, KV_W, DM);

    // 2) rmsnorm + rope
    normrope_kernel<<<(M * NH * 32 + 255) / 256, 256>>>(pqraw, pqh, qs, NH, DM);
    normrope_kernel<<<(M * NKV * 32 + 255) / 256, 256>>>(pkvraw, pkh, ks, NKV, KV_W);

    // 3) v rearrange
    vcopy_kernel<<<(BATCH * NKV * S_LEN * (HD / 4) + 255) / 256, 256>>>();

    // 4) causal GQA attention
    attn_kernel<<<dim3(S_LEN / 128, NH, BATCH), 256>>>();

    // 5) output projection (convert attention output, then tensor GEMM)
    cvt_split<<<(M * DM / 4 + 255) / 256, 256>>>(pao, paoh, paol, M * DM / 4);
    gemm_bf16_3x<<<dim3(DM / GBN, M / GBM), 256>>>(paoh, paol, pwoh, pwol, out, M, DM, DM);
}

// round 4
// speedup vs baseline: 3.6514x; 3.0234x over previous
#include <cuda_runtime.h>
#include <cuda_bf16.h>
#include <math.h>
#include <stdint.h>

#define BATCH 2
#define S_LEN 2048
#define DM 1024
#define NH 16
#define NKV 4
#define HD 64
#define KV_W 512   // 2 * NKV * HD

// ---------------- scratch (device globals; no allocs allowed) ----------------
__device__ float g_q_raw[BATCH * S_LEN * DM];     // X @ Wq
__device__ float g_kv_raw[BATCH * S_LEN * KV_W];  // X @ Wkv
__device__ float g_ao[BATCH * S_LEN * DM];        // attention output [b,s,h*d]

// bf16 split buffers for projection GEMMs
__device__ __nv_bfloat16 g_xh[BATCH * S_LEN * DM];
__device__ __nv_bfloat16 g_xl[BATCH * S_LEN * DM];
__device__ __nv_bfloat16 g_wqh[DM * DM];
__device__ __nv_bfloat16 g_wql[DM * DM];
__device__ __nv_bfloat16 g_wkvh[DM * KV_W];
__device__ __nv_bfloat16 g_wkvl[DM * KV_W];
__device__ __nv_bfloat16 g_woh[DM * DM];
__device__ __nv_bfloat16 g_wol[DM * DM];
__device__ __nv_bfloat16 g_aoh[BATCH * S_LEN * DM];
__device__ __nv_bfloat16 g_aol[BATCH * S_LEN * DM];

// bf16 split Q/K/V for attention  [b,h,s,d] / [b,kvh,s,d]
__device__ __nv_bfloat16 g_qhi[BATCH * NH * S_LEN * HD];
__device__ __nv_bfloat16 g_qlo[BATCH * NH * S_LEN * HD];
__device__ __nv_bfloat16 g_khi[BATCH * NKV * S_LEN * HD];
__device__ __nv_bfloat16 g_klo[BATCH * NKV * S_LEN * HD];
__device__ __nv_bfloat16 g_vhi[BATCH * NKV * S_LEN * HD];
__device__ __nv_bfloat16 g_vlo[BATCH * NKV * S_LEN * HD];

// ---------------- fp32 -> (hi, lo) bf16 split --------------------------------
__global__ void cvt_split(const float* __restrict__ in,
                          __nv_bfloat16* __restrict__ hi,
                          __nv_bfloat16* __restrict__ lo, int n4) {
    int i = blockIdx.x * blockDim.x + threadIdx.x;
    if (i >= n4) return;
    float4 v = *(const float4*)(in + (size_t)i * 4);
    __nv_bfloat16 h0 = __float2bfloat16(v.x);
    __nv_bfloat16 h1 = __float2bfloat16(v.y);
    __nv_bfloat16 h2 = __float2bfloat16(v.z);
    __nv_bfloat16 h3 = __float2bfloat16(v.w);
    __nv_bfloat16 l0 = __float2bfloat16(v.x - __bfloat162float(h0));
    __nv_bfloat16 l1 = __float2bfloat16(v.y - __bfloat162float(h1));
    __nv_bfloat16 l2 = __float2bfloat16(v.z - __bfloat162float(h2));
    __nv_bfloat16 l3 = __float2bfloat16(v.w - __bfloat162float(h3));
    __nv_bfloat162* hp = (__nv_bfloat162*)(hi + (size_t)i * 4);
    __nv_bfloat162* lp = (__nv_bfloat162*)(lo + (size_t)i * 4);
    hp[0] = __nv_bfloat162(h0, h1); hp[1] = __nv_bfloat162(h2, h3);
    lp[0] = __nv_bfloat162(l0, l1); lp[1] = __nv_bfloat162(l2, l3);
}

// ---------------- mma helpers ------------------------------------------------
__device__ __forceinline__ uint32_t smem_u32(const void* p) {
    return (uint32_t)__cvta_generic_to_shared(p);
}
__device__ __forceinline__ void ldsm_x4(uint32_t& r0, uint32_t& r1,
                                        uint32_t& r2, uint32_t& r3, uint32_t a) {
    asm volatile("ldmatrix.sync.aligned.m8n8.x4.shared.b16 {%0,%1,%2,%3},[%4];"
                 : "=r"(r0), "=r"(r1), "=r"(r2), "=r"(r3) : "r"(a));
}
__device__ __forceinline__ void ldsm_x4_t(uint32_t& r0, uint32_t& r1,
                                          uint32_t& r2, uint32_t& r3, uint32_t a) {
    asm volatile("ldmatrix.sync.aligned.m8n8.x4.trans.shared.b16 {%0,%1,%2,%3},[%4];"
                 : "=r"(r0), "=r"(r1), "=r"(r2), "=r"(r3) : "r"(a));
}
__device__ __forceinline__ void mma_bf16(float* c, const uint32_t* a,
                                         const uint32_t* b) {
    asm volatile(
        "mma.sync.aligned.m16n8k16.row.col.f32.bf16.bf16.f32 "
        "{%0,%1,%2,%3},{%4,%5,%6,%7},{%8,%9},{%0,%1,%2,%3};"
        : "+f"(c[0]), "+f"(c[1]), "+f"(c[2]), "+f"(c[3])
        : "r"(a[0]), "r"(a[1]), "r"(a[2]), "r"(a[3]), "r"(b[0]), "r"(b[1]));
}

// ---------------- 3x bf16-split tensor-core GEMM -----------------------------
#define GBM 128
#define GBN 128
#define GBK 32

__global__ __launch_bounds__(256) void gemm_bf16_3x(
    const __nv_bfloat16* __restrict__ Ah, const __nv_bfloat16* __restrict__ Al,
    const __nv_bfloat16* __restrict__ Bh, const __nv_bfloat16* __restrict__ Bl,
    float* __restrict__ C, int M, int N, int K) {
    __shared__ __align__(16) __nv_bfloat16 As[GBM][GBK + 8];
    __shared__ __align__(16) __nv_bfloat16 Bs[GBK][GBN + 8];

    int tid = threadIdx.x;
    int wid = tid >> 5, lane = tid & 31;
    int bm = blockIdx.y * GBM, bn = blockIdx.x * GBN;
    int wm = (wid & 1) * 64;
    int wn = (wid >> 1) * 32;

    float acc[4][4][4];
#pragma unroll
    for (int i = 0; i < 4; i++)
#pragma unroll
        for (int j = 0; j < 4; j++)
#pragma unroll
            for (int e = 0; e < 4; e++) acc[i][j][e] = 0.0f;

    for (int kk = 0; kk < 3 * K; kk += GBK) {
        int seg = kk / K;
        int kl = kk - seg * K;
        const __nv_bfloat16* Aseg = (seg < 2) ? Ah : Al;
        const __nv_bfloat16* Bseg = (seg == 1) ? Bl : Bh;

#pragma unroll
        for (int i = 0; i < 2; i++) {
            int idx = tid + i * 256;
            int r = idx >> 2;
            int c8 = (idx & 3) * 8;
            *(uint4*)&As[r][c8] =
                *(const uint4*)(Aseg + (size_t)(bm + r) * K + kl + c8);
        }
#pragma unroll
        for (int i = 0; i < 2; i++) {
            int idx = tid + i * 256;
            int r = idx >> 4;
            int c8 = (idx & 15) * 8;
            *(uint4*)&Bs[r][c8] =
                *(const uint4*)(Bseg + (size_t)(kl + r) * N + bn + c8);
        }
        __syncthreads();

#pragma unroll
        for (int k0 = 0; k0 < GBK; k0 += 16) {
            uint32_t a[4][4];
#pragma unroll
            for (int mt = 0; mt < 4; mt++) {
                int row = wm + mt * 16 + (lane & 15);
                int col = k0 + (lane >> 4) * 8;
                ldsm_x4(a[mt][0], a[mt][1], a[mt][2], a[mt][3],
                        smem_u32(&As[row][col]));
            }
            uint32_t b[4][2];
#pragma unroll
            for (int np = 0; np < 2; np++) {
                int r = k0 + (lane & 15);
                int col = wn + np * 16 + (lane >> 4) * 8;
                uint32_t t0, t1, t2, t3;
                ldsm_x4_t(t0, t1, t2, t3, smem_u32(&Bs[r][col]));
                b[np * 2 + 0][0] = t0; b[np * 2 + 0][1] = t1;
                b[np * 2 + 1][0] = t2; b[np * 2 + 1][1] = t3;
            }
#pragma unroll
            for (int mt = 0; mt < 4; mt++)
#pragma unroll
                for (int nt = 0; nt < 4; nt++)
                    mma_bf16(acc[mt][nt], a[mt], b[nt]);
        }
        __syncthreads();
    }

    int g = lane >> 2, tg = lane & 3;
#pragma unroll
    for (int mt = 0; mt < 4; mt++) {
#pragma unroll
        for (int nt = 0; nt < 4; nt++) {
            int row = bm + wm + mt * 16 + g;
            int col = bn + wn + nt * 8 + tg * 2;
            *(float2*)&C[(size_t)row * N + col] =
                make_float2(acc[mt][nt][0], acc[mt][nt][1]);
            *(float2*)&C[(size_t)(row + 8) * N + col] =
                make_float2(acc[mt][nt][2], acc[mt][nt][3]);
        }
    }
}

// ---------------- RMSNorm + RoPE -> bf16 hi/lo split --------------------------
__device__ const double c_inv8[8] = {
    1.0, 0.74989420933245582, 0.56234132519034912, 0.42169650342858224,
    0.31622776601683794, 0.23713737056616552, 0.17782794100389229,
    0.13335214321633241};
__device__ const double c_p10[4] = {1.0, 0.1, 0.01, 0.001};

__global__ void normrope_kernel(const float* __restrict__ in,
                                __nv_bfloat16* __restrict__ ohi,
                                __nv_bfloat16* __restrict__ olo,
                                const float* __restrict__ scale,
                                int nheads, int in_ld, float post) {
    int gw = (blockIdx.x * blockDim.x + threadIdx.x) >> 5;
    int lane = threadIdx.x & 31;
    int total = BATCH * S_LEN * nheads;
    if (gw >= total) return;
    int h = gw % nheads;
    int s = (gw / nheads) % S_LEN;
    int b = gw / (nheads * S_LEN);

    const float* ip = in + ((size_t)(b * S_LEN + s)) * in_ld + h * HD;
    float x1 = ip[lane];
    float x2 = ip[lane + 32];
    float ss = x1 * x1 + x2 * x2;
#pragma unroll
    for (int o = 16; o; o >>= 1) ss += __shfl_xor_sync(0xffffffffu, ss, o);
    float inv = rsqrtf(ss * (1.0f / 64.0f) + 1e-5f);
    x1 *= inv * scale[lane];
    x2 *= inv * scale[lane + 32];

    float invf = (float)(c_inv8[lane & 7] * c_p10[lane >> 3]);
    float f = (float)s * invf;
    float c, sn;
    sincosf(f, &sn, &c);   // sincosf(x, SIN*, COS*)

    float y1 = (x1 * c - x2 * sn) * post;
    float y2 = (x1 * sn + x2 * c) * post;

    size_t base = (((size_t)(b * nheads + h)) * S_LEN + s) * HD;
    __nv_bfloat16 h1 = __float2bfloat16(y1);
    __nv_bfloat16 h2 = __float2bfloat16(y2);
    ohi[base + lane] = h1;
    ohi[base + lane + 32] = h2;
    olo[base + lane] = __float2bfloat16(y1 - __bfloat162float(h1));
    olo[base + lane + 32] = __float2bfloat16(y2 - __bfloat162float(h2));
}

// ---------------- V rearrange + bf16 split ------------------------------------
__global__ void vcopy_kernel() {
    int idx = blockIdx.x * blockDim.x + threadIdx.x;   // float4 index
    int total = BATCH * NKV * S_LEN * (HD / 4);
    if (idx >= total) return;
    int c4 = idx & 15;
    int tmp = idx >> 4;
    int s = tmp % S_LEN;
    int bk = tmp / S_LEN;
    int kvh = bk % NKV;
    int b = bk / NKV;
    float4 v = *(const float4*)(g_kv_raw + ((size_t)(b * S_LEN + s)) * KV_W +
                                (NKV * HD) + kvh * HD + c4 * 4);
    size_t o = ((size_t)bk * S_LEN + s) * HD + c4 * 4;
    __nv_bfloat16 h0 = __float2bfloat16(v.x);
    __nv_bfloat16 h1 = __float2bfloat16(v.y);
    __nv_bfloat16 h2 = __float2bfloat16(v.z);
    __nv_bfloat16 h3 = __float2bfloat16(v.w);
    *(__nv_bfloat162*)(g_vhi + o) = __nv_bfloat162(h0, h1);
    *(__nv_bfloat162*)(g_vhi + o + 2) = __nv_bfloat162(h2, h3);
    *(__nv_bfloat162*)(g_vlo + o) = __nv_bfloat162(
        __float2bfloat16(v.x - __bfloat162float(h0)),
        __float2bfloat16(v.y - __bfloat162float(h1)));
    *(__nv_bfloat162*)(g_vlo + o + 2) = __nv_bfloat162(
        __float2bfloat16(v.z - __bfloat162float(h2)),
        __float2bfloat16(v.w - __bfloat162float(h3)));
}

// ---------------- tensor-core causal GQA flash attention -----------------------
// CTA: 128 q rows, 8 warps x 16 rows each. Key tiles of 64.
// S = Qh*Kh + Qh*Kl + Ql*Kh ; O += Ph*Vh + Ph*Vl + Pl*Vh
#define SPAD 72   // 64 + 8

__global__ __launch_bounds__(256) void attn_mma_kernel() {
    __shared__ __align__(16) __nv_bfloat16 sbuf[4][64][SPAD];  // 36.9 KB

    int b = blockIdx.z, h = blockIdx.y;
    int mb = (int)(gridDim.x - 1) - (int)blockIdx.x;  // heavy CTAs first
    int kvh = h >> 2;
    int tid = threadIdx.x;
    int wid = tid >> 5, lane = tid & 31;
    int g = lane >> 2, tg = lane & 3;

    const __nv_bfloat16* qhi = g_qhi + (((size_t)(b * NH + h)) * S_LEN + mb * 128) * HD;
    const __nv_bfloat16* qlo = g_qlo + (((size_t)(b * NH + h)) * S_LEN + mb * 128) * HD;
    const __nv_bfloat16* khi = g_khi + ((size_t)(b * NKV + kvh)) * S_LEN * HD;
    const __nv_bfloat16* klo = g_klo + ((size_t)(b * NKV + kvh)) * S_LEN * HD;
    const __nv_bfloat16* vhi = g_vhi + ((size_t)(b * NKV + kvh)) * S_LEN * HD;
    const __nv_bfloat16* vlo = g_vlo + ((size_t)(b * NKV + kvh)) * S_LEN * HD;

    // ---- phase 0: stage Q tile [128][64] hi+lo through smem, grab a-frags ----
    __nv_bfloat16* qs = &sbuf[0][0][0];   // treated as [256][SPAD]
#pragma unroll
    for (int i = 0; i < 4; i++) {
        int idx = tid + i * 256;          // 0..1023 uint4
        int r = idx >> 3;                 // 0..127
        int c8 = (idx & 7) * 8;
        *(uint4*)(qs + (size_t)r * SPAD + c8) = *(const uint4*)(qhi + (size_t)r * HD + c8);
        *(uint4*)(qs + (size_t)(r + 128) * SPAD + c8) = *(const uint4*)(qlo + (size_t)r * HD + c8);
    }
    __syncthreads();

    uint32_t qha[4][4], qla[4][4];
    {
        int row = wid * 16 + (lane & 15);
#pragma unroll
        for (int kt = 0; kt < 4; kt++) {
            int col = kt * 16 + (lane >> 4) * 8;
            ldsm_x4(qha[kt][0], qha[kt][1], qha[kt][2], qha[kt][3],
                    smem_u32(qs + (size_t)row * SPAD + col));
            ldsm_x4(qla[kt][0], qla[kt][1], qla[kt][2], qla[kt][3],
                    smem_u32(qs + (size_t)(row + 128) * SPAD + col));
        }
    }
    __syncthreads();

    // ---- state ----
    float oacc[8][4];
#pragma unroll
    for (int nt = 0; nt < 8; nt++)
#pragma unroll
        for (int e = 0; e < 4; e++) oacc[nt][e] = 0.0f;
    float m_i[2] = {-1e30f, -1e30f};
    float l_i[2] = {0.0f, 0.0f};

    int grow = mb * 128 + wid * 16;       // warp's first global q row
    int row0 = grow + g, row1 = grow + g + 8;

    int ntiles = mb * 2 + 2;
    for (int t = 0; t < ntiles; t++) {
        int n0 = t * 64;
        // load K/V hi/lo tiles [64][64]
        {
            const __nv_bfloat16* srcs[4] = {khi, klo, vhi, vlo};
#pragma unroll
            for (int a = 0; a < 4; a++) {
#pragma unroll
                for (int i = 0; i < 2; i++) {
                    int idx = tid + i * 256;      // 0..511
                    int r = idx >> 3;             // 0..63
                    int c8 = (idx & 7) * 8;
                    *(uint4*)&sbuf[a][r][c8] =
                        *(const uint4*)(srcs[a] + (size_t)(n0 + r) * HD + c8);
                }
            }
        }
        __syncthreads();

        // ---- S = Q K^T (3-term split) ----
        float sacc[8][4];
#pragma unroll
        for (int nt = 0; nt < 8; nt++)
#pragma unroll
            for (int e = 0; e < 4; e++) sacc[nt][e] = 0.0f;

#pragma unroll
        for (int kt = 0; kt < 4; kt++) {
            uint32_t kb[8][2];
            // Kh b-frags: non-trans ldmatrix (Ks is [key][dim], dim=k contiguous)
            {
                int rr = (lane & 7) + ((lane >> 4) << 3);
                int cc = kt * 16 + (((lane >> 3) & 1) << 3);
#pragma unroll
                for (int nb = 0; nb < 4; nb++) {
                    uint32_t t0, t1, t2, t3;
                    ldsm_x4(t0, t1, t2, t3, smem_u32(&sbuf[0][nb * 16 + rr][cc]));
                    kb[nb * 2 + 0][0] = t0; kb[nb * 2 + 0][1] = t1;
                    kb[nb * 2 + 1][0] = t2; kb[nb * 2 + 1][1] = t3;
                }
            }
#pragma unroll
            for (int nt = 0; nt < 8; nt++) {
                mma_bf16(sacc[nt], qha[kt], kb[nt]);
                mma_bf16(sacc[nt], qla[kt], kb[nt]);
            }
            // Kl b-frags
            {
                int rr = (lane & 7) + ((lane >> 4) << 3);
                int cc = kt * 16 + (((lane >> 3) & 1) << 3);
#pragma unroll
                for (int nb = 0; nb < 4; nb++) {
                    uint32_t t0, t1, t2, t3;
                    ldsm_x4(t0, t1, t2, t3, smem_u32(&sbuf[1][nb * 16 + rr][cc]));
                    kb[nb * 2 + 0][0] = t0; kb[nb * 2 + 0][1] = t1;
                    kb[nb * 2 + 1][0] = t2; kb[nb * 2 + 1][1] = t3;
                }
            }
#pragma unroll
            for (int nt = 0; nt < 8; nt++)
                mma_bf16(sacc[nt], qha[kt], kb[nt]);
        }

        // ---- causal mask + online softmax ----
        float rm[2] = {-1e30f, -1e30f};
#pragma unroll
        for (int nt = 0; nt < 8; nt++) {
            int col = n0 + nt * 8 + tg * 2;
            if (col > row0) sacc[nt][0] = -1e30f;
            if (col + 1 > row0) sacc[nt][1] = -1e30f;
            if (col > row1) sacc[nt][2] = -1e30f;
            if (col + 1 > row1) sacc[nt][3] = -1e30f;
            rm[0] = fmaxf(rm[0], fmaxf(sacc[nt][0], sacc[nt][1]));
            rm[1] = fmaxf(rm[1], fmaxf(sacc[nt][2], sacc[nt][3]));
        }
#pragma unroll
        for (int o = 1; o <= 2; o <<= 1) {
            rm[0] = fmaxf(rm[0], __shfl_xor_sync(0xffffffffu, rm[0], o));
            rm[1] = fmaxf(rm[1], __shfl_xor_sync(0xffffffffu, rm[1], o));
        }
        float m_new0 = fmaxf(m_i[0], rm[0]);
        float m_new1 = fmaxf(m_i[1], rm[1]);
        float corr0 = __expf(m_i[0] - m_new0);
        float corr1 = __expf(m_i[1] - m_new1);
        float ls0 = 0.0f, ls1 = 0.0f;
#pragma unroll
        for (int nt = 0; nt < 8; nt++) {
            sacc[nt][0] = __expf(sacc[nt][0] - m_new0);
            sacc[nt][1] = __expf(sacc[nt][1] - m_new0);
            sacc[nt][2] = __expf(sacc[nt][2] - m_new1);
            sacc[nt][3] = __expf(sacc[nt][3] - m_new1);
            ls0 += sacc[nt][0] + sacc[nt][1];
            ls1 += sacc[nt][2] + sacc[nt][3];
        }
#pragma unroll
        for (int o = 1; o <= 2; o <<= 1) {
            ls0 += __shfl_xor_sync(0xffffffffu, ls0, o);
            ls1 += __shfl_xor_sync(0xffffffffu, ls1, o);
        }
        l_i[0] = l_i[0] * corr0 + ls0;
        l_i[1] = l_i[1] * corr1 + ls1;
        m_i[0] = m_new0; m_i[1] = m_new1;
#pragma unroll
        for (int nt = 0; nt < 8; nt++) {
            oacc[nt][0] *= corr0; oacc[nt][1] *= corr0;
            oacc[nt][2] *= corr1; oacc[nt][3] *= corr1;
        }

        // ---- O += P V (3-term split); P a-frags straight from sacc ----
#pragma unroll
        for (int kt = 0; kt < 4; kt++) {
            uint32_t pha[4], pla[4];
#pragma unroll
            for (int half = 0; half < 2; half++) {
                const float* pp = sacc[kt * 2 + half];
                __nv_bfloat16 h0 = __float2bfloat16(pp[0]);
                __nv_bfloat16 h1 = __float2bfloat16(pp[1]);
                __nv_bfloat16 h2 = __float2bfloat16(pp[2]);
                __nv_bfloat16 h3 = __float2bfloat16(pp[3]);
                __nv_bfloat162 a01(h0, h1), a23(h2, h3);
                pha[half * 2 + 0 + 0] = *(uint32_t*)&a01;      // rows g
                pha[half * 2 + 1] = *(uint32_t*)&a23;           // rows g+8
                __nv_bfloat162 l01(__float2bfloat16(pp[0] - __bfloat162float(h0)),
                                   __float2bfloat16(pp[1] - __bfloat162float(h1)));
                __nv_bfloat162 l23(__float2bfloat16(pp[2] - __bfloat162float(h2)),
                                   __float2bfloat16(pp[3] - __bfloat162float(h3)));
                pla[half * 2 + 0] = *(uint32_t*)&l01;
                pla[half * 2 + 1] = *(uint32_t*)&l23;
            }
            uint32_t vb[8][2];
            // Vh b-frags: trans ldmatrix (Vs is [key][dim], dim=n contiguous)
            {
                int rr = kt * 16 + (lane & 15);
                int c0 = (lane >> 4) * 8;
#pragma unroll
                for (int nb = 0; nb < 4; nb++) {
                    uint32_t t0, t1, t2, t3;
                    ldsm_x4_t(t0, t1, t2, t3, smem_u32(&sbuf[2][rr][nb * 16 + c0]));
                    vb[nb * 2 + 0][0] = t0; vb[nb * 2 + 0][1] = t1;
                    vb[nb * 2 + 1][0] = t2; vb[nb * 2 + 1][1] = t3;
                }
            }
#pragma unroll
            for (int nt = 0; nt < 8; nt++) {
                mma_bf16(oacc[nt], pha, vb[nt]);
                mma_bf16(oacc[nt], pla, vb[nt]);
            }
            // Vl b-frags
            {
                int rr = kt * 16 + (lane & 15);
                int c0 = (lane >> 4) * 8;
#pragma unroll
                for (int nb = 0; nb < 4; nb++) {
                    uint32_t t0, t1, t2, t3;
                    ldsm_x4_t(t0, t1, t2, t3, smem_u32(&sbuf[3][rr][nb * 16 + c0]));
                    vb[nb * 2 + 0][0] = t0; vb[nb * 2 + 0][1] = t1;
                    vb[nb * 2 + 1][0] = t2; vb[nb * 2 + 1][1] = t3;
                }
            }
#pragma unroll
            for (int nt = 0; nt < 8; nt++)
                mma_bf16(oacc[nt], pha, vb[nt]);
        }
        __syncthreads();
    }

    // ---- epilogue ----
    float inv0 = 1.0f / l_i[0];
    float inv1 = 1.0f / l_i[1];
#pragma unroll
    for (int nt = 0; nt < 8; nt++) {
        int col = h * HD + nt * 8 + tg * 2;
        *(float2*)&g_ao[((size_t)(b * S_LEN + row0)) * DM + col] =
            make_float2(oacc[nt][0] * inv0, oacc[nt][1] * inv0);
        *(float2*)&g_ao[((size_t)(b * S_LEN + row1)) * DM + col] =
            make_float2(oacc[nt][2] * inv1, oacc[nt][3] * inv1);
    }
}

// ---------------- launcher ----------------------------------------------------
extern "C" void kernel_launch(void* const* d_in, const int* in_sizes, int n_in,
                              void* d_out, int out_size) {
    const float* x   = (const float*)d_in[0];
    const float* Wq  = (const float*)d_in[1];
    const float* Wkv = (const float*)d_in[2];
    const float* Wo  = (const float*)d_in[3];
    const float* qs  = (const float*)d_in[4];
    const float* ks  = (const float*)d_in[5];
    float* out = (float*)d_out;

    float *pqraw, *pkvraw, *pao;
    cudaGetSymbolAddress((void**)&pqraw, g_q_raw);
    cudaGetSymbolAddress((void**)&pkvraw, g_kv_raw);
    cudaGetSymbolAddress((void**)&pao, g_ao);

    __nv_bfloat16 *pxh, *pxl, *pwqh, *pwql, *pwkvh, *pwkvl, *pwoh, *pwol, *paoh, *paol;
    cudaGetSymbolAddress((void**)&pxh, g_xh);
    cudaGetSymbolAddress((void**)&pxl, g_xl);
    cudaGetSymbolAddress((void**)&pwqh, g_wqh);
    cudaGetSymbolAddress((void**)&pwql, g_wql);
    cudaGetSymbolAddress((void**)&pwkvh, g_wkvh);
    cudaGetSymbolAddress((void**)&pwkvl, g_wkvl);
    cudaGetSymbolAddress((void**)&pwoh, g_woh);
    cudaGetSymbolAddress((void**)&pwol, g_wol);
    cudaGetSymbolAddress((void**)&paoh, g_aoh);
    cudaGetSymbolAddress((void**)&paol, g_aol);

    __nv_bfloat16 *pqhi, *pqlo, *pkhi, *pklo;
    cudaGetSymbolAddress((void**)&pqhi, g_qhi);
    cudaGetSymbolAddress((void**)&pqlo, g_qlo);
    cudaGetSymbolAddress((void**)&pkhi, g_khi);
    cudaGetSymbolAddress((void**)&pklo, g_klo);

    int M = BATCH * S_LEN;  // 4096

    // 0) split-convert inputs to bf16 hi/lo
    cvt_split<<<(M * DM / 4 + 255) / 256, 256>>>(x, pxh, pxl, M * DM / 4);
    cvt_split<<<(DM * DM / 4 + 255) / 256, 256>>>(Wq, pwqh, pwql, DM * DM / 4);
    cvt_split<<<(DM * KV_W / 4 + 255) / 256, 256>>>(Wkv, pwkvh, pwkvl, DM * KV_W / 4);
    cvt_split<<<(DM * DM / 4 + 255) / 256, 256>>>(Wo, pwoh, pwol, DM * DM / 4);

    // 1) projections (tensor cores, 3x bf16 split)
    gemm_bf16_3x<<<dim3(DM / GBN, M / GBM), 256>>>(pxh, pxl, pwqh, pwql, pqraw, M, DM, DM);
    gemm_bf16_3x<<<dim3(KV_W / GBN, M / GBM), 256>>>(pxh, pxl, pwkvh, pwkvl, pkvraw, M, KV_W, DM);

    // 2) rmsnorm + rope -> bf16 split (q pre-scaled by 1/8)
    normrope_kernel<<<(M * NH * 32 + 255) / 256, 256>>>(pqraw, pqhi, pqlo, qs, NH, DM, 0.125f);
    normrope_kernel<<<(M * NKV * 32 + 255) / 256, 256>>>(pkvraw, pkhi, pklo, ks, NKV, KV_W, 1.0f);

    // 3) v rearrange + split
    vcopy_kernel<<<(BATCH * NKV * S_LEN * (HD / 4) + 255) / 256, 256>>>();

    // 4) tensor-core causal GQA attention
    attn_mma_kernel<<<dim3(S_LEN / 128, NH, BATCH), 256>>>();

    // 5) output projection
    cvt_split<<<(M * DM / 4 + 255) / 256, 256>>>(pao, paoh, paol, M * DM / 4);
    gemm_bf16_3x<<<dim3(DM / GBN, M / GBM), 256>>>(paoh, paol, pwoh, pwol, out, M, DM, DM);
}

// round 5
// speedup vs baseline: 3.9702x; 1.0873x over previous
#include <cuda_runtime.h>
#include <cuda_bf16.h>
#include <math.h>
#include <stdint.h>

#define BATCH 2
#define S_LEN 2048
#define DM 1024
#define NH 16
#define NKV 4
#define HD 64
#define KV_W 512   // 2 * NKV * HD

// ---------------- scratch (device globals; no allocs allowed) ----------------
__device__ float g_q_raw[BATCH * S_LEN * DM];     // X @ Wq
__device__ float g_kv_raw[BATCH * S_LEN * KV_W];  // X @ Wkv

// bf16 split buffers for projection GEMMs
__device__ __nv_bfloat16 g_xh[BATCH * S_LEN * DM];
__device__ __nv_bfloat16 g_xl[BATCH * S_LEN * DM];
__device__ __nv_bfloat16 g_wqh[DM * DM];
__device__ __nv_bfloat16 g_wql[DM * DM];
__device__ __nv_bfloat16 g_wkvh[DM * KV_W];
__device__ __nv_bfloat16 g_wkvl[DM * KV_W];
__device__ __nv_bfloat16 g_woh[DM * DM];
__device__ __nv_bfloat16 g_wol[DM * DM];
__device__ __nv_bfloat16 g_aoh[BATCH * S_LEN * DM];
__device__ __nv_bfloat16 g_aol[BATCH * S_LEN * DM];

// bf16 split Q/K/V for attention  [b,h,s,d] / [b,kvh,s,d]
__device__ __nv_bfloat16 g_qhi[BATCH * NH * S_LEN * HD];
__device__ __nv_bfloat16 g_qlo[BATCH * NH * S_LEN * HD];
__device__ __nv_bfloat16 g_khi[BATCH * NKV * S_LEN * HD];
__device__ __nv_bfloat16 g_klo[BATCH * NKV * S_LEN * HD];
__device__ __nv_bfloat16 g_vhi[BATCH * NKV * S_LEN * HD];
__device__ __nv_bfloat16 g_vlo[BATCH * NKV * S_LEN * HD];

// ---------------- cp.async helpers --------------------------------------------
__device__ __forceinline__ uint32_t smem_u32(const void* p) {
    return (uint32_t)__cvta_generic_to_shared(p);
}
__device__ __forceinline__ void cpa16(uint32_t s, const void* g) {
    asm volatile("cp.async.cg.shared.global [%0], [%1], 16;" :: "r"(s), "l"(g));
}
#define CP_COMMIT asm volatile("cp.async.commit_group;")
#define CP_WAIT0  asm volatile("cp.async.wait_group 0;")

// ---------------- fp32 -> (hi, lo) bf16 split --------------------------------
__global__ void cvt_split(const float* __restrict__ in,
                          __nv_bfloat16* __restrict__ hi,
                          __nv_bfloat16* __restrict__ lo, int n4) {
    int i = blockIdx.x * blockDim.x + threadIdx.x;
    if (i >= n4) return;
    float4 v = *(const float4*)(in + (size_t)i * 4);
    __nv_bfloat16 h0 = __float2bfloat16(v.x);
    __nv_bfloat16 h1 = __float2bfloat16(v.y);
    __nv_bfloat16 h2 = __float2bfloat16(v.z);
    __nv_bfloat16 h3 = __float2bfloat16(v.w);
    __nv_bfloat16 l0 = __float2bfloat16(v.x - __bfloat162float(h0));
    __nv_bfloat16 l1 = __float2bfloat16(v.y - __bfloat162float(h1));
    __nv_bfloat16 l2 = __float2bfloat16(v.z - __bfloat162float(h2));
    __nv_bfloat16 l3 = __float2bfloat16(v.w - __bfloat162float(h3));
    __nv_bfloat162* hp = (__nv_bfloat162*)(hi + (size_t)i * 4);
    __nv_bfloat162* lp = (__nv_bfloat162*)(lo + (size_t)i * 4);
    hp[0] = __nv_bfloat162(h0, h1); hp[1] = __nv_bfloat162(h2, h3);
    lp[0] = __nv_bfloat162(l0, l1); lp[1] = __nv_bfloat162(l2, l3);
}

// ---------------- mma helpers ------------------------------------------------
__device__ __forceinline__ void ldsm_x4(uint32_t& r0, uint32_t& r1,
                                        uint32_t& r2, uint32_t& r3, uint32_t a) {
    asm volatile("ldmatrix.sync.aligned.m8n8.x4.shared.b16 {%0,%1,%2,%3},[%4];"
                 : "=r"(r0), "=r"(r1), "=r"(r2), "=r"(r3) : "r"(a));
}
__device__ __forceinline__ void ldsm_x4_t(uint32_t& r0, uint32_t& r1,
                                          uint32_t& r2, uint32_t& r3, uint32_t a) {
    asm volatile("ldmatrix.sync.aligned.m8n8.x4.trans.shared.b16 {%0,%1,%2,%3},[%4];"
                 : "=r"(r0), "=r"(r1), "=r"(r2), "=r"(r3) : "r"(a));
}
__device__ __forceinline__ void mma_bf16(float* c, const uint32_t* a,
                                         const uint32_t* b) {
    asm volatile(
        "mma.sync.aligned.m16n8k16.row.col.f32.bf16.bf16.f32 "
        "{%0,%1,%2,%3},{%4,%5,%6,%7},{%8,%9},{%0,%1,%2,%3};"
        : "+f"(c[0]), "+f"(c[1]), "+f"(c[2]), "+f"(c[3])
        : "r"(a[0]), "r"(a[1]), "r"(a[2]), "r"(a[3]), "r"(b[0]), "r"(b[1]));
}

// ---------------- 3x bf16-split tensor-core GEMM (cp.async pipelined) ---------
#define GBM 128
#define GBN 128
#define GBK 32

__global__ __launch_bounds__(256) void gemm_bf16_3x(
    const __nv_bfloat16* __restrict__ Ah, const __nv_bfloat16* __restrict__ Al,
    const __nv_bfloat16* __restrict__ Bh, const __nv_bfloat16* __restrict__ Bl,
    float* __restrict__ C, int M, int N, int K) {
    __shared__ __align__(16) __nv_bfloat16 As[2][GBM][GBK + 8];   // 2 x 10 KB
    __shared__ __align__(16) __nv_bfloat16 Bs[2][GBK][GBN + 8];   // 2 x 8.5 KB

    int tid = threadIdx.x;
    int wid = tid >> 5, lane = tid & 31;
    int bm = blockIdx.y * GBM, bn = blockIdx.x * GBN;
    int wm = (wid & 1) * 64;
    int wn = (wid >> 1) * 32;

    // per-thread load coordinates (2 uint4 each for A and B)
    int ar0 = tid >> 2, ac0 = (tid & 3) * 8;
    int ar1 = (tid + 256) >> 2, ac1 = ((tid + 256) & 3) * 8;
    int br0 = tid >> 4, bc0 = (tid & 15) * 8;
    int br1 = (tid + 256) >> 4, bc1 = ((tid + 256) & 15) * 8;

    int T = 3 * K / GBK;

    auto prefetch = [&](int t, int buf) {
        int kk = t * GBK;
        int seg = kk / K;
        int kl = kk - seg * K;
        const __nv_bfloat16* Aseg = (seg < 2) ? Ah : Al;
        const __nv_bfloat16* Bseg = (seg == 1) ? Bl : Bh;
        cpa16(smem_u32(&As[buf][ar0][ac0]), Aseg + (size_t)(bm + ar0) * K + kl + ac0);
        cpa16(smem_u32(&As[buf][ar1][ac1]), Aseg + (size_t)(bm + ar1) * K + kl + ac1);
        cpa16(smem_u32(&Bs[buf][br0][bc0]), Bseg + (size_t)(kl + br0) * N + bn + bc0);
        cpa16(smem_u32(&Bs[buf][br1][bc1]), Bseg + (size_t)(kl + br1) * N + bn + bc1);
    };

    float acc[4][4][4];
#pragma unroll
    for (int i = 0; i < 4; i++)
#pragma unroll
        for (int j = 0; j < 4; j++)
#pragma unroll
            for (int e = 0; e < 4; e++) acc[i][j][e] = 0.0f;

    prefetch(0, 0);
    CP_COMMIT;

    for (int t = 0; t < T; t++) {
        int buf = t & 1;
        CP_WAIT0;
        __syncthreads();
        if (t + 1 < T) {
            prefetch(t + 1, buf ^ 1);
            CP_COMMIT;
        }

#pragma unroll
        for (int k0 = 0; k0 < GBK; k0 += 16) {
            uint32_t a[4][4];
#pragma unroll
            for (int mt = 0; mt < 4; mt++) {
                int row = wm + mt * 16 + (lane & 15);
                int col = k0 + (lane >> 4) * 8;
                ldsm_x4(a[mt][0], a[mt][1], a[mt][2], a[mt][3],
                        smem_u32(&As[buf][row][col]));
            }
            uint32_t b[4][2];
#pragma unroll
            for (int np = 0; np < 2; np++) {
                int r = k0 + (lane & 15);
                int col = wn + np * 16 + (lane >> 4) * 8;
                uint32_t t0, t1, t2, t3;
                ldsm_x4_t(t0, t1, t2, t3, smem_u32(&Bs[buf][r][col]));
                b[np * 2 + 0][0] = t0; b[np * 2 + 0][1] = t1;
                b[np * 2 + 1][0] = t2; b[np * 2 + 1][1] = t3;
            }
#pragma unroll
            for (int mt = 0; mt < 4; mt++)
#pragma unroll
                for (int nt = 0; nt < 4; nt++)
                    mma_bf16(acc[mt][nt], a[mt], b[nt]);
        }
    }

    int g = lane >> 2, tg = lane & 3;
#pragma unroll
    for (int mt = 0; mt < 4; mt++) {
#pragma unroll
        for (int nt = 0; nt < 4; nt++) {
            int row = bm + wm + mt * 16 + g;
            int col = bn + wn + nt * 8 + tg * 2;
            *(float2*)&C[(size_t)row * N + col] =
                make_float2(acc[mt][nt][0], acc[mt][nt][1]);
            *(float2*)&C[(size_t)(row + 8) * N + col] =
                make_float2(acc[mt][nt][2], acc[mt][nt][3]);
        }
    }
}

// ---------------- RMSNorm + RoPE -> bf16 hi/lo split --------------------------
__device__ const double c_inv8[8] = {
    1.0, 0.74989420933245582, 0.56234132519034912, 0.42169650342858224,
    0.31622776601683794, 0.23713737056616552, 0.17782794100389229,
    0.13335214321633241};
__device__ const double c_p10[4] = {1.0, 0.1, 0.01, 0.001};

__global__ void normrope_kernel(const float* __restrict__ in,
                                __nv_bfloat16* __restrict__ ohi,
                                __nv_bfloat16* __restrict__ olo,
                                const float* __restrict__ scale,
                                int nheads, int in_ld, float post) {
    int gw = (blockIdx.x * blockDim.x + threadIdx.x) >> 5;
    int lane = threadIdx.x & 31;
    int total = BATCH * S_LEN * nheads;
    if (gw >= total) return;
    int h = gw % nheads;
    int s = (gw / nheads) % S_LEN;
    int b = gw / (nheads * S_LEN);

    const float* ip = in + ((size_t)(b * S_LEN + s)) * in_ld + h * HD;
    float x1 = ip[lane];
    float x2 = ip[lane + 32];
    float ss = x1 * x1 + x2 * x2;
#pragma unroll
    for (int o = 16; o; o >>= 1) ss += __shfl_xor_sync(0xffffffffu, ss, o);
    float inv = rsqrtf(ss * (1.0f / 64.0f) + 1e-5f);
    x1 *= inv * scale[lane];
    x2 *= inv * scale[lane + 32];

    float invf = (float)(c_inv8[lane & 7] * c_p10[lane >> 3]);
    float f = (float)s * invf;
    float c, sn;
    sincosf(f, &sn, &c);   // sincosf(x, SIN*, COS*)

    float y1 = (x1 * c - x2 * sn) * post;
    float y2 = (x1 * sn + x2 * c) * post;

    size_t base = (((size_t)(b * nheads + h)) * S_LEN + s) * HD;
    __nv_bfloat16 h1 = __float2bfloat16(y1);
    __nv_bfloat16 h2 = __float2bfloat16(y2);
    ohi[base + lane] = h1;
    ohi[base + lane + 32] = h2;
    olo[base + lane] = __float2bfloat16(y1 - __bfloat162float(h1));
    olo[base + lane + 32] = __float2bfloat16(y2 - __bfloat162float(h2));
}

// ---------------- V rearrange + bf16 split ------------------------------------
__global__ void vcopy_kernel() {
    int idx = blockIdx.x * blockDim.x + threadIdx.x;   // float4 index
    int total = BATCH * NKV * S_LEN * (HD / 4);
    if (idx >= total) return;
    int c4 = idx & 15;
    int tmp = idx >> 4;
    int s = tmp % S_LEN;
    int bk = tmp / S_LEN;
    int kvh = bk % NKV;
    int b = bk / NKV;
    float4 v = *(const float4*)(g_kv_raw + ((size_t)(b * S_LEN + s)) * KV_W +
                                (NKV * HD) + kvh * HD + c4 * 4);
    size_t o = ((size_t)bk * S_LEN + s) * HD + c4 * 4;
    __nv_bfloat16 h0 = __float2bfloat16(v.x);
    __nv_bfloat16 h1 = __float2bfloat16(v.y);
    __nv_bfloat16 h2 = __float2bfloat16(v.z);
    __nv_bfloat16 h3 = __float2bfloat16(v.w);
    *(__nv_bfloat162*)(g_vhi + o) = __nv_bfloat162(h0, h1);
    *(__nv_bfloat162*)(g_vhi + o + 2) = __nv_bfloat162(h2, h3);
    *(__nv_bfloat162*)(g_vlo + o) = __nv_bfloat162(
        __float2bfloat16(v.x - __bfloat162float(h0)),
        __float2bfloat16(v.y - __bfloat162float(h1)));
    *(__nv_bfloat162*)(g_vlo + o + 2) = __nv_bfloat162(
        __float2bfloat16(v.z - __bfloat162float(h2)),
        __float2bfloat16(v.w - __bfloat162float(h3)));
}

// ---------------- tensor-core causal GQA flash attention -----------------------
#define SPAD 72   // 64 + 8

__global__ __launch_bounds__(256) void attn_mma_kernel() {
    __shared__ __align__(16) __nv_bfloat16 sbuf[4][64][SPAD];  // 36.9 KB

    int b = blockIdx.z, h = blockIdx.y;
    int mb = (int)(gridDim.x - 1) - (int)blockIdx.x;  // heavy CTAs first
    int kvh = h >> 2;
    int tid = threadIdx.x;
    int wid = tid >> 5, lane = tid & 31;
    int g = lane >> 2, tg = lane & 3;

    const __nv_bfloat16* qhi = g_qhi + (((size_t)(b * NH + h)) * S_LEN + mb * 128) * HD;
    const __nv_bfloat16* qlo = g_qlo + (((size_t)(b * NH + h)) * S_LEN + mb * 128) * HD;
    const __nv_bfloat16* khi = g_khi + ((size_t)(b * NKV + kvh)) * S_LEN * HD;
    const __nv_bfloat16* klo = g_klo + ((size_t)(b * NKV + kvh)) * S_LEN * HD;
    const __nv_bfloat16* vhi = g_vhi + ((size_t)(b * NKV + kvh)) * S_LEN * HD;
    const __nv_bfloat16* vlo = g_vlo + ((size_t)(b * NKV + kvh)) * S_LEN * HD;

    // ---- phase 0: stage Q tile [128][64] hi+lo through smem, grab a-frags ----
    __nv_bfloat16* qs = &sbuf[0][0][0];   // treated as [256][SPAD]
#pragma unroll
    for (int i = 0; i < 4; i++) {
        int idx = tid + i * 256;          // 0..1023 uint4
        int r = idx >> 3;                 // 0..127
        int c8 = (idx & 7) * 8;
        cpa16(smem_u32(qs + (size_t)r * SPAD + c8), qhi + (size_t)r * HD + c8);
        cpa16(smem_u32(qs + (size_t)(r + 128) * SPAD + c8), qlo + (size_t)r * HD + c8);
    }
    CP_COMMIT; CP_WAIT0;
    __syncthreads();

    uint32_t qha[4][4], qla[4][4];
    {
        int row = wid * 16 + (lane & 15);
#pragma unroll
        for (int kt = 0; kt < 4; kt++) {
            int col = kt * 16 + (lane >> 4) * 8;
            ldsm_x4(qha[kt][0], qha[kt][1], qha[kt][2], qha[kt][3],
                    smem_u32(qs + (size_t)row * SPAD + col));
            ldsm_x4(qla[kt][0], qla[kt][1], qla[kt][2], qla[kt][3],
                    smem_u32(qs + (size_t)(row + 128) * SPAD + col));
        }
    }
    __syncthreads();

    float oacc[8][4];
#pragma unroll
    for (int nt = 0; nt < 8; nt++)
#pragma unroll
        for (int e = 0; e < 4; e++) oacc[nt][e] = 0.0f;
    float m_i[2] = {-1e30f, -1e30f};
    float l_i[2] = {0.0f, 0.0f};

    int grow = mb * 128 + wid * 16;
    int row0 = grow + g, row1 = grow + g + 8;

    int ntiles = mb * 2 + 2;
    for (int t = 0; t < ntiles; t++) {
        int n0 = t * 64;
        {
            const __nv_bfloat16* srcs[4] = {khi, klo, vhi, vlo};
#pragma unroll
            for (int a = 0; a < 4; a++) {
#pragma unroll
                for (int i = 0; i < 2; i++) {
                    int idx = tid + i * 256;      // 0..511
                    int r = idx >> 3;             // 0..63
                    int c8 = (idx & 7) * 8;
                    cpa16(smem_u32(&sbuf[a][r][c8]),
                          srcs[a] + (size_t)(n0 + r) * HD + c8);
                }
            }
        }
        CP_COMMIT; CP_WAIT0;
        __syncthreads();

        // ---- S = Q K^T (3-term split) ----
        float sacc[8][4];
#pragma unroll
        for (int nt = 0; nt < 8; nt++)
#pragma unroll
            for (int e = 0; e < 4; e++) sacc[nt][e] = 0.0f;

#pragma unroll
        for (int kt = 0; kt < 4; kt++) {
            uint32_t kb[8][2];
            {
                int rr = (lane & 7) + ((lane >> 4) << 3);
                int cc = kt * 16 + (((lane >> 3) & 1) << 3);
#pragma unroll
                for (int nb = 0; nb < 4; nb++) {
                    uint32_t t0, t1, t2, t3;
                    ldsm_x4(t0, t1, t2, t3, smem_u32(&sbuf[0][nb * 16 + rr][cc]));
                    kb[nb * 2 + 0][0] = t0; kb[nb * 2 + 0][1] = t1;
                    kb[nb * 2 + 1][0] = t2; kb[nb * 2 + 1][1] = t3;
                }
            }
#pragma unroll
            for (int nt = 0; nt < 8; nt++) {
                mma_bf16(sacc[nt], qha[kt], kb[nt]);
                mma_bf16(sacc[nt], qla[kt], kb[nt]);
            }
            {
                int rr = (lane & 7) + ((lane >> 4) << 3);
                int cc = kt * 16 + (((lane >> 3) & 1) << 3);
#pragma unroll
                for (int nb = 0; nb < 4; nb++) {
                    uint32_t t0, t1, t2, t3;
                    ldsm_x4(t0, t1, t2, t3, smem_u32(&sbuf[1][nb * 16 + rr][cc]));
                    kb[nb * 2 + 0][0] = t0; kb[nb * 2 + 0][1] = t1;
                    kb[nb * 2 + 1][0] = t2; kb[nb * 2 + 1][1] = t3;
                }
            }
#pragma unroll
            for (int nt = 0; nt < 8; nt++)
                mma_bf16(sacc[nt], qha[kt], kb[nt]);
        }

        // ---- causal mask + online softmax ----
        float rm[2] = {-1e30f, -1e30f};
#pragma unroll
        for (int nt = 0; nt < 8; nt++) {
            int col = n0 + nt * 8 + tg * 2;
            if (col > row0) sacc[nt][0] = -1e30f;
            if (col + 1 > row0) sacc[nt][1] = -1e30f;
            if (col > row1) sacc[nt][2] = -1e30f;
            if (col + 1 > row1) sacc[nt][3] = -1e30f;
            rm[0] = fmaxf(rm[0], fmaxf(sacc[nt][0], sacc[nt][1]));
            rm[1] = fmaxf(rm[1], fmaxf(sacc[nt][2], sacc[nt][3]));
        }
#pragma unroll
        for (int o = 1; o <= 2; o <<= 1) {
            rm[0] = fmaxf(rm[0], __shfl_xor_sync(0xffffffffu, rm[0], o));
            rm[1] = fmaxf(rm[1], __shfl_xor_sync(0xffffffffu, rm[1], o));
        }
        float m_new0 = fmaxf(m_i[0], rm[0]);
        float m_new1 = fmaxf(m_i[1], rm[1]);
        float corr0 = __expf(m_i[0] - m_new0);
        float corr1 = __expf(m_i[1] - m_new1);
        float ls0 = 0.0f, ls1 = 0.0f;
#pragma unroll
        for (int nt = 0; nt < 8; nt++) {
            sacc[nt][0] = __expf(sacc[nt][0] - m_new0);
            sacc[nt][1] = __expf(sacc[nt][1] - m_new0);
            sacc[nt][2] = __expf(sacc[nt][2] - m_new1);
            sacc[nt][3] = __expf(sacc[nt][3] - m_new1);
            ls0 += sacc[nt][0] + sacc[nt][1];
            ls1 += sacc[nt][2] + sacc[nt][3];
        }
#pragma unroll
        for (int o = 1; o <= 2; o <<= 1) {
            ls0 += __shfl_xor_sync(0xffffffffu, ls0, o);
            ls1 += __shfl_xor_sync(0xffffffffu, ls1, o);
        }
        l_i[0] = l_i[0] * corr0 + ls0;
        l_i[1] = l_i[1] * corr1 + ls1;
        m_i[0] = m_new0; m_i[1] = m_new1;
#pragma unroll
        for (int nt = 0; nt < 8; nt++) {
            oacc[nt][0] *= corr0; oacc[nt][1] *= corr0;
            oacc[nt][2] *= corr1; oacc[nt][3] *= corr1;
        }

        // ---- O += P V (3-term split) ----
#pragma unroll
        for (int kt = 0; kt < 4; kt++) {
            uint32_t pha[4], pla[4];
#pragma unroll
            for (int half = 0; half < 2; half++) {
                const float* pp = sacc[kt * 2 + half];
                __nv_bfloat16 h0 = __float2bfloat16(pp[0]);
                __nv_bfloat16 h1 = __float2bfloat16(pp[1]);
                __nv_bfloat16 h2 = __float2bfloat16(pp[2]);
                __nv_bfloat16 h3 = __float2bfloat16(pp[3]);
                __nv_bfloat162 a01(h0, h1), a23(h2, h3);
                pha[half * 2 + 0] = *(uint32_t*)&a01;
                pha[half * 2 + 1] = *(uint32_t*)&a23;
                __nv_bfloat162 l01(__float2bfloat16(pp[0] - __bfloat162float(h0)),
                                   __float2bfloat16(pp[1] - __bfloat162float(h1)));
                __nv_bfloat162 l23(__float2bfloat16(pp[2] - __bfloat162float(h2)),
                                   __float2bfloat16(pp[3] - __bfloat162float(h3)));
                pla[half * 2 + 0] = *(uint32_t*)&l01;
                pla[half * 2 + 1] = *(uint32_t*)&l23;
            }
            uint32_t vb[8][2];
            {
                int rr = kt * 16 + (lane & 15);
                int c0 = (lane >> 4) * 8;
#pragma unroll
                for (int nb = 0; nb < 4; nb++) {
                    uint32_t t0, t1, t2, t3;
                    ldsm_x4_t(t0, t1, t2, t3, smem_u32(&sbuf[2][rr][nb * 16 + c0]));
                    vb[nb * 2 + 0][0] = t0; vb[nb * 2 + 0][1] = t1;
                    vb[nb * 2 + 1][0] = t2; vb[nb * 2 + 1][1] = t3;
                }
            }
#pragma unroll
            for (int nt = 0; nt < 8; nt++) {
                mma_bf16(oacc[nt], pha, vb[nt]);
                mma_bf16(oacc[nt], pla, vb[nt]);
            }
            {
                int rr = kt * 16 + (lane & 15);
                int c0 = (lane >> 4) * 8;
#pragma unroll
                for (int nb = 0; nb < 4; nb++) {
                    uint32_t t0, t1, t2, t3;
                    ldsm_x4_t(t0, t1, t2, t3, smem_u32(&sbuf[3][rr][nb * 16 + c0]));
                    vb[nb * 2 + 0][0] = t0; vb[nb * 2 + 0][1] = t1;
                    vb[nb * 2 + 1][0] = t2; vb[nb * 2 + 1][1] = t3;
                }
            }
#pragma unroll
            for (int nt = 0; nt < 8; nt++)
                mma_bf16(oacc[nt], pha, vb[nt]);
        }
        __syncthreads();
    }

    // ---- epilogue: write bf16 hi/lo splits directly ----
    float inv0 = 1.0f / l_i[0];
    float inv1 = 1.0f / l_i[1];
#pragma unroll
    for (int nt = 0; nt < 8; nt++) {
        int col = h * HD + nt * 8 + tg * 2;
        size_t o0 = ((size_t)(b * S_LEN + row0)) * DM + col;
        size_t o1 = ((size_t)(b * S_LEN + row1)) * DM + col;
        float y00 = oacc[nt][0] * inv0, y01 = oacc[nt][1] * inv0;
        float y10 = oacc[nt][2] * inv1, y11 = oacc[nt][3] * inv1;
        __nv_bfloat16 h00 = __float2bfloat16(y00), h01 = __float2bfloat16(y01);
        __nv_bfloat16 h10 = __float2bfloat16(y10), h11 = __float2bfloat16(y11);
        *(__nv_bfloat162*)&g_aoh[o0] = __nv_bfloat162(h00, h01);
        *(__nv_bfloat162*)&g_aoh[o1] = __nv_bfloat162(h10, h11);
        *(__nv_bfloat162*)&g_aol[o0] = __nv_bfloat162(
            __float2bfloat16(y00 - __bfloat162float(h00)),
            __float2bfloat16(y01 - __bfloat162float(h01)));
        *(__nv_bfloat162*)&g_aol[o1] = __nv_bfloat162(
            __float2bfloat16(y10 - __bfloat162float(h10)),
            __float2bfloat16(y11 - __bfloat162float(h11)));
    }
}

// ---------------- launcher ----------------------------------------------------
extern "C" void kernel_launch(void* const* d_in, const int* in_sizes, int n_in,
                              void* d_out, int out_size) {
    const float* x   = (const float*)d_in[0];
    const float* Wq  = (const float*)d_in[1];
    const float* Wkv = (const float*)d_in[2];
    const float* Wo  = (const float*)d_in[3];
    const float* qs  = (const float*)d_in[4];
    const float* ks  = (const float*)d_in[5];
    float* out = (float*)d_out;

    float *pqraw, *pkvraw;
    cudaGetSymbolAddress((void**)&pqraw, g_q_raw);
    cudaGetSymbolAddress((void**)&pkvraw, g_kv_raw);

    __nv_bfloat16 *pxh, *pxl, *pwqh, *pwql, *pwkvh, *pwkvl, *pwoh, *pwol, *paoh, *paol;
    cudaGetSymbolAddress((void**)&pxh, g_xh);
    cudaGetSymbolAddress((void**)&pxl, g_xl);
    cudaGetSymbolAddress((void**)&pwqh, g_wqh);
    cudaGetSymbolAddress((void**)&pwql, g_wql);
    cudaGetSymbolAddress((void**)&pwkvh, g_wkvh);
    cudaGetSymbolAddress((void**)&pwkvl, g_wkvl);
    cudaGetSymbolAddress((void**)&pwoh, g_woh);
    cudaGetSymbolAddress((void**)&pwol, g_wol);
    cudaGetSymbolAddress((void**)&paoh, g_aoh);
    cudaGetSymbolAddress((void**)&paol, g_aol);

    __nv_bfloat16 *pqhi, *pqlo, *pkhi, *pklo;
    cudaGetSymbolAddress((void**)&pqhi, g_qhi);
    cudaGetSymbolAddress((void**)&pqlo, g_qlo);
    cudaGetSymbolAddress((void**)&pkhi, g_khi);
    cudaGetSymbolAddress((void**)&pklo, g_klo);

    int M = BATCH * S_LEN;  // 4096

    // 0) split-convert inputs to bf16 hi/lo
    cvt_split<<<(M * DM / 4 + 255) / 256, 256>>>(x, pxh, pxl, M * DM / 4);
    cvt_split<<<(DM * DM / 4 + 255) / 256, 256>>>(Wq, pwqh, pwql, DM * DM / 4);
    cvt_split<<<(DM * KV_W / 4 + 255) / 256, 256>>>(Wkv, pwkvh, pwkvl, DM * KV_W / 4);
    cvt_split<<<(DM * DM / 4 + 255) / 256, 256>>>(Wo, pwoh, pwol, DM * DM / 4);

    // 1) projections (tensor cores, 3x bf16 split, cp.async pipelined)
    gemm_bf16_3x<<<dim3(DM / GBN, M / GBM), 256>>>(pxh, pxl, pwqh, pwql, pqraw, M, DM, DM);
    gemm_bf16_3x<<<dim3(KV_W / GBN, M / GBM), 256>>>(pxh, pxl, pwkvh, pwkvl, pkvraw, M, KV_W, DM);

    // 2) rmsnorm + rope -> bf16 split (q pre-scaled by 1/8)
    normrope_kernel<<<(M * NH * 32 + 255) / 256, 256>>>(pqraw, pqhi, pqlo, qs, NH, DM, 0.125f);
    normrope_kernel<<<(M * NKV * 32 + 255) / 256, 256>>>(pkvraw, pkhi, pklo, ks, NKV, KV_W, 1.0f);

    // 3) v rearrange + split
    vcopy_kernel<<<(BATCH * NKV * S_LEN * (HD / 4) + 255) / 256, 256>>>();

    // 4) tensor-core causal GQA attention (writes bf16 splits directly)
    attn_mma_kernel<<<dim3(S_LEN / 128, NH, BATCH), 256>>>();

    // 5) output projection
    gemm_bf16_3x<<<dim3(DM / GBN, M / GBM), 256>>>(paoh, paol, pwoh, pwol, out, M, DM, DM);
}

// round 7
// speedup vs baseline: 4.0532x; 1.0209x over previous
#include <cuda_runtime.h>
#include <cuda_bf16.h>
#include <math.h>
#include <stdint.h>

#define BATCH 2
#define S_LEN 2048
#define DM 1024
#define NH 16
#define NKV 4
#define HD 64
#define KV_W 512     // 2 * NKV * HD
#define QKV_W 1536   // DM + KV_W

// ---------------- scratch (device globals; no allocs allowed) ----------------
__device__ float g_qkv_raw[BATCH * S_LEN * QKV_W];  // X @ [Wq | Wkv]

// bf16 split buffers
__device__ __nv_bfloat16 g_xh[BATCH * S_LEN * DM];
__device__ __nv_bfloat16 g_xl[BATCH * S_LEN * DM];
__device__ __nv_bfloat16 g_w1h[DM * QKV_W];   // [Wq | Wkv]  [K=DM][N=1536]
__device__ __nv_bfloat16 g_w1l[DM * QKV_W];
__device__ __nv_bfloat16 g_woh[DM * DM];
__device__ __nv_bfloat16 g_wol[DM * DM];
__device__ __nv_bfloat16 g_aoh[BATCH * S_LEN * DM];
__device__ __nv_bfloat16 g_aol[BATCH * S_LEN * DM];

// bf16 split Q/K/V for attention  [b,h,s,d] / [b,kvh,s,d]
__device__ __nv_bfloat16 g_qhi[BATCH * NH * S_LEN * HD];
__device__ __nv_bfloat16 g_qlo[BATCH * NH * S_LEN * HD];
__device__ __nv_bfloat16 g_khi[BATCH * NKV * S_LEN * HD];
__device__ __nv_bfloat16 g_klo[BATCH * NKV * S_LEN * HD];
__device__ __nv_bfloat16 g_vhi[BATCH * NKV * S_LEN * HD];
__device__ __nv_bfloat16 g_vlo[BATCH * NKV * S_LEN * HD];

// ---------------- helpers ------------------------------------------------------
__device__ __forceinline__ uint32_t smem_u32(const void* p) {
    return (uint32_t)__cvta_generic_to_shared(p);
}
__device__ __forceinline__ void cpa16(uint32_t s, const void* g) {
    asm volatile("cp.async.cg.shared.global [%0], [%1], 16;" :: "r"(s), "l"(g));
}
#define CP_COMMIT asm volatile("cp.async.commit_group;")
#define CP_WAIT0  asm volatile("cp.async.wait_group 0;")
#define CP_WAIT1  asm volatile("cp.async.wait_group 1;")

__device__ __forceinline__ void ldsm_x4(uint32_t& r0, uint32_t& r1,
                                        uint32_t& r2, uint32_t& r3, uint32_t a) {
    asm volatile("ldmatrix.sync.aligned.m8n8.x4.shared.b16 {%0,%1,%2,%3},[%4];"
                 : "=r"(r0), "=r"(r1), "=r"(r2), "=r"(r3) : "r"(a));
}
__device__ __forceinline__ void ldsm_x4_t(uint32_t& r0, uint32_t& r1,
                                          uint32_t& r2, uint32_t& r3, uint32_t a) {
    asm volatile("ldmatrix.sync.aligned.m8n8.x4.trans.shared.b16 {%0,%1,%2,%3},[%4];"
                 : "=r"(r0), "=r"(r1), "=r"(r2), "=r"(r3) : "r"(a));
}
__device__ __forceinline__ void mma_bf16(float* c, const uint32_t* a,
                                         const uint32_t* b) {
    asm volatile(
        "mma.sync.aligned.m16n8k16.row.col.f32.bf16.bf16.f32 "
        "{%0,%1,%2,%3},{%4,%5,%6,%7},{%8,%9},{%0,%1,%2,%3};"
        : "+f"(c[0]), "+f"(c[1]), "+f"(c[2]), "+f"(c[3])
        : "r"(a[0]), "r"(a[1]), "r"(a[2]), "r"(a[3]), "r"(b[0]), "r"(b[1]));
}

// ---------------- fp32 -> (hi, lo) bf16 split --------------------------------
__global__ void cvt_split(const float* __restrict__ in,
                          __nv_bfloat16* __restrict__ hi,
                          __nv_bfloat16* __restrict__ lo, int n4) {
    int i = blockIdx.x * blockDim.x + threadIdx.x;
    if (i >= n4) return;
    float4 v = *(const float4*)(in + (size_t)i * 4);
    __nv_bfloat16 h0 = __float2bfloat16(v.x);
    __nv_bfloat16 h1 = __float2bfloat16(v.y);
    __nv_bfloat16 h2 = __float2bfloat16(v.z);
    __nv_bfloat16 h3 = __float2bfloat16(v.w);
    __nv_bfloat162* hp = (__nv_bfloat162*)(hi + (size_t)i * 4);
    __nv_bfloat162* lp = (__nv_bfloat162*)(lo + (size_t)i * 4);
    hp[0] = __nv_bfloat162(h0, h1); hp[1] = __nv_bfloat162(h2, h3);
    lp[0] = __nv_bfloat162(__float2bfloat16(v.x - __bfloat162float(h0)),
                           __float2bfloat16(v.y - __bfloat162float(h1)));
    lp[1] = __nv_bfloat162(__float2bfloat16(v.z - __bfloat162float(h2)),
                           __float2bfloat16(v.w - __bfloat162float(h3)));
}

// fp32 W[K][Nin] -> split written into wide [K][ld] buffer at column col0
__global__ void cvt_split_pad(const float* __restrict__ in,
                              __nv_bfloat16* __restrict__ hi,
                              __nv_bfloat16* __restrict__ lo,
                              int Nin, int ld, int col0, int n4) {
    int i = blockIdx.x * blockDim.x + threadIdx.x;
    if (i >= n4) return;
    int r = (i * 4) / Nin;
    int c = (i * 4) % Nin;
    float4 v = *(const float4*)(in + (size_t)r * Nin + c);
    size_t o = (size_t)r * ld + col0 + c;
    __nv_bfloat16 h0 = __float2bfloat16(v.x);
    __nv_bfloat16 h1 = __float2bfloat16(v.y);
    __nv_bfloat16 h2 = __float2bfloat16(v.z);
    __nv_bfloat16 h3 = __float2bfloat16(v.w);
    *(__nv_bfloat162*)(hi + o) = __nv_bfloat162(h0, h1);
    *(__nv_bfloat162*)(hi + o + 2) = __nv_bfloat162(h2, h3);
    *(__nv_bfloat162*)(lo + o) = __nv_bfloat162(
        __float2bfloat16(v.x - __bfloat162float(h0)),
        __float2bfloat16(v.y - __bfloat162float(h1)));
    *(__nv_bfloat162*)(lo + o + 2) = __nv_bfloat162(
        __float2bfloat16(v.z - __bfloat162float(h2)),
        __float2bfloat16(v.w - __bfloat162float(h3)));
}

// ---------------- 3x bf16-split tensor-core GEMM (cp.async pipelined) ---------
#define GBM 128
#define GBN 128
#define GBK 32

__global__ __launch_bounds__(256) void gemm_bf16_3x(
    const __nv_bfloat16* __restrict__ Ah, const __nv_bfloat16* __restrict__ Al,
    const __nv_bfloat16* __restrict__ Bh, const __nv_bfloat16* __restrict__ Bl,
    float* __restrict__ C, int M, int N, int K) {
    __shared__ __align__(16) __nv_bfloat16 As[2][GBM][GBK + 8];
    __shared__ __align__(16) __nv_bfloat16 Bs[2][GBK][GBN + 8];

    int tid = threadIdx.x;
    int wid = tid >> 5, lane = tid & 31;
    int bm = blockIdx.y * GBM, bn = blockIdx.x * GBN;
    int wm = (wid & 1) * 64;
    int wn = (wid >> 1) * 32;

    int ar0 = tid >> 2, ac0 = (tid & 3) * 8;
    int ar1 = (tid + 256) >> 2, ac1 = ((tid + 256) & 3) * 8;
    int br0 = tid >> 4, bc0 = (tid & 15) * 8;
    int br1 = (tid + 256) >> 4, bc1 = ((tid + 256) & 15) * 8;

    int T = 3 * K / GBK;

    auto prefetch = [&](int t, int buf) {
        int kk = t * GBK;
        int seg = kk / K;
        int kl = kk - seg * K;
        const __nv_bfloat16* Aseg = (seg < 2) ? Ah : Al;
        const __nv_bfloat16* Bseg = (seg == 1) ? Bl : Bh;
        cpa16(smem_u32(&As[buf][ar0][ac0]), Aseg + (size_t)(bm + ar0) * K + kl + ac0);
        cpa16(smem_u32(&As[buf][ar1][ac1]), Aseg + (size_t)(bm + ar1) * K + kl + ac1);
        cpa16(smem_u32(&Bs[buf][br0][bc0]), Bseg + (size_t)(kl + br0) * N + bn + bc0);
        cpa16(smem_u32(&Bs[buf][br1][bc1]), Bseg + (size_t)(kl + br1) * N + bn + bc1);
    };

    float acc[4][4][4];
#pragma unroll
    for (int i = 0; i < 4; i++)
#pragma unroll
        for (int j = 0; j < 4; j++)
#pragma unroll
            for (int e = 0; e < 4; e++) acc[i][j][e] = 0.0f;

    prefetch(0, 0);
    CP_COMMIT;

    for (int t = 0; t < T; t++) {
        int buf = t & 1;
        CP_WAIT0;
        __syncthreads();
        if (t + 1 < T) {
            prefetch(t + 1, buf ^ 1);
            CP_COMMIT;
        }

#pragma unroll
        for (int k0 = 0; k0 < GBK; k0 += 16) {
            uint32_t a[4][4];
#pragma unroll
            for (int mt = 0; mt < 4; mt++) {
                int row = wm + mt * 16 + (lane & 15);
                int col = k0 + (lane >> 4) * 8;
                ldsm_x4(a[mt][0], a[mt][1], a[mt][2], a[mt][3],
                        smem_u32(&As[buf][row][col]));
            }
            uint32_t b[4][2];
#pragma unroll
            for (int np = 0; np < 2; np++) {
                int r = k0 + (lane & 15);
                int col = wn + np * 16 + (lane >> 4) * 8;
                uint32_t t0, t1, t2, t3;
                ldsm_x4_t(t0, t1, t2, t3, smem_u32(&Bs[buf][r][col]));
                b[np * 2 + 0][0] = t0; b[np * 2 + 0][1] = t1;
                b[np * 2 + 1][0] = t2; b[np * 2 + 1][1] = t3;
            }
#pragma unroll
            for (int mt = 0; mt < 4; mt++)
#pragma unroll
                for (int nt = 0; nt < 4; nt++)
                    mma_bf16(acc[mt][nt], a[mt], b[nt]);
        }
    }

    int g = lane >> 2, tg = lane & 3;
#pragma unroll
    for (int mt = 0; mt < 4; mt++) {
#pragma unroll
        for (int nt = 0; nt < 4; nt++) {
            int row = bm + wm + mt * 16 + g;
            int col = bn + wn + nt * 8 + tg * 2;
            *(float2*)&C[(size_t)row * N + col] =
                make_float2(acc[mt][nt][0], acc[mt][nt][1]);
            *(float2*)&C[(size_t)(row + 8) * N + col] =
                make_float2(acc[mt][nt][2], acc[mt][nt][3]);
        }
    }
}

// ---------------- RMSNorm + RoPE -> bf16 hi/lo split --------------------------
__device__ const double c_inv8[8] = {
    1.0, 0.74989420933245582, 0.56234132519034912, 0.42169650342858224,
    0.31622776601683794, 0.23713737056616552, 0.17782794100389229,
    0.13335214321633241};
__device__ const double c_p10[4] = {1.0, 0.1, 0.01, 0.001};

__global__ void normrope_kernel(const float* __restrict__ in,
                                __nv_bfloat16* __restrict__ ohi,
                                __nv_bfloat16* __restrict__ olo,
                                const float* __restrict__ scale,
                                int nheads, int in_ld, int col0, float post) {
    int gw = (blockIdx.x * blockDim.x + threadIdx.x) >> 5;
    int lane = threadIdx.x & 31;
    int total = BATCH * S_LEN * nheads;
    if (gw >= total) return;
    int h = gw % nheads;
    int s = (gw / nheads) % S_LEN;
    int b = gw / (nheads * S_LEN);

    const float* ip = in + ((size_t)(b * S_LEN + s)) * in_ld + col0 + h * HD;
    float x1 = ip[lane];
    float x2 = ip[lane + 32];
    float ss = x1 * x1 + x2 * x2;
#pragma unroll
    for (int o = 16; o; o >>= 1) ss += __shfl_xor_sync(0xffffffffu, ss, o);
    float inv = rsqrtf(ss * (1.0f / 64.0f) + 1e-5f);
    x1 *= inv * scale[lane];
    x2 *= inv * scale[lane + 32];

    float invf = (float)(c_inv8[lane & 7] * c_p10[lane >> 3]);
    float f = (float)s * invf;
    float c, sn;
    sincosf(f, &sn, &c);   // sincosf(x, SIN*, COS*)

    float y1 = (x1 * c - x2 * sn) * post;
    float y2 = (x1 * sn + x2 * c) * post;

    size_t base = (((size_t)(b * nheads + h)) * S_LEN + s) * HD;
    __nv_bfloat16 h1 = __float2bfloat16(y1);
    __nv_bfloat16 h2 = __float2bfloat16(y2);
    ohi[base + lane] = h1;
    ohi[base + lane + 32] = h2;
    olo[base + lane] = __float2bfloat16(y1 - __bfloat162float(h1));
    olo[base + lane + 32] = __float2bfloat16(y2 - __bfloat162float(h2));
}

// ---------------- V rearrange + bf16 split ------------------------------------
__global__ void vcopy_kernel() {
    int idx = blockIdx.x * blockDim.x + threadIdx.x;   // float4 index
    int total = BATCH * NKV * S_LEN * (HD / 4);
    if (idx >= total) return;
    int c4 = idx & 15;
    int tmp = idx >> 4;
    int s = tmp % S_LEN;
    int bk = tmp / S_LEN;
    int kvh = bk % NKV;
    int b = bk / NKV;
    float4 v = *(const float4*)(g_qkv_raw + ((size_t)(b * S_LEN + s)) * QKV_W +
                                (DM + NKV * HD) + kvh * HD + c4 * 4);
    size_t o = ((size_t)bk * S_LEN + s) * HD + c4 * 4;
    __nv_bfloat16 h0 = __float2bfloat16(v.x);
    __nv_bfloat16 h1 = __float2bfloat16(v.y);
    __nv_bfloat16 h2 = __float2bfloat16(v.z);
    __nv_bfloat16 h3 = __float2bfloat16(v.w);
    *(__nv_bfloat162*)(g_vhi + o) = __nv_bfloat162(h0, h1);
    *(__nv_bfloat162*)(g_vhi + o + 2) = __nv_bfloat162(h2, h3);
    *(__nv_bfloat162*)(g_vlo + o) = __nv_bfloat162(
        __float2bfloat16(v.x - __bfloat162float(h0)),
        __float2bfloat16(v.y - __bfloat162float(h1)));
    *(__nv_bfloat162*)(g_vlo + o + 2) = __nv_bfloat162(
        __float2bfloat16(v.z - __bfloat162float(h2)),
        __float2bfloat16(v.w - __bfloat162float(h3)));
}

// ---------------- mma.sync causal GQA flash attention (2-stage K/V pipe) -------
#define SPAD 72   // 64 + 8
#define ATT_SMEM (2 * 4 * 64 * SPAD * 2)   // 73728 bytes

__global__ __launch_bounds__(256) void attn_mma_kernel() {
    extern __shared__ __align__(16) __nv_bfloat16 dsm[];
    // layout: stage s (0/1), array a (0=Khi 1=Klo 2=Vhi 3=Vlo): dsm + ((s*4+a)*64*SPAD)

    int b = blockIdx.z, h = blockIdx.y;
    int mb = (int)(gridDim.x - 1) - (int)blockIdx.x;  // heavy CTAs first
    int kvh = h >> 2;
    int tid = threadIdx.x;
    int wid = tid >> 5, lane = tid & 31;
    int g = lane >> 2, tg = lane & 3;

    const __nv_bfloat16* qhi = g_qhi + (((size_t)(b * NH + h)) * S_LEN + mb * 128) * HD;
    const __nv_bfloat16* qlo = g_qlo + (((size_t)(b * NH + h)) * S_LEN + mb * 128) * HD;
    const __nv_bfloat16* khi = g_khi + ((size_t)(b * NKV + kvh)) * S_LEN * HD;
    const __nv_bfloat16* klo = g_klo + ((size_t)(b * NKV + kvh)) * S_LEN * HD;
    const __nv_bfloat16* vhi = g_vhi + ((size_t)(b * NKV + kvh)) * S_LEN * HD;
    const __nv_bfloat16* vlo = g_vlo + ((size_t)(b * NKV + kvh)) * S_LEN * HD;

    // ---- phase 0: stage Q tile [128][64] hi+lo through smem, grab a-frags ----
    __nv_bfloat16* qs = dsm;   // [256][SPAD]
#pragma unroll
    for (int i = 0; i < 4; i++) {
        int idx = tid + i * 256;
        int r = idx >> 3;
        int c8 = (idx & 7) * 8;
        cpa16(smem_u32(qs + (size_t)r * SPAD + c8), qhi + (size_t)r * HD + c8);
        cpa16(smem_u32(qs + (size_t)(r + 128) * SPAD + c8), qlo + (size_t)r * HD + c8);
    }
    CP_COMMIT; CP_WAIT0;
    __syncthreads();

    uint32_t qha[4][4], qla[4][4];
    {
        int row = wid * 16 + (lane & 15);
#pragma unroll
        for (int kt = 0; kt < 4; kt++) {
            int col = kt * 16 + (lane >> 4) * 8;
            ldsm_x4(qha[kt][0], qha[kt][1], qha[kt][2], qha[kt][3],
                    smem_u32(qs + (size_t)row * SPAD + col));
            ldsm_x4(qla[kt][0], qla[kt][1], qla[kt][2], qla[kt][3],
                    smem_u32(qs + (size_t)(row + 128) * SPAD + col));
        }
    }
    __syncthreads();

    float oacc[8][4];
#pragma unroll
    for (int nt = 0; nt < 8; nt++)
#pragma unroll
        for (int e = 0; e < 4; e++) oacc[nt][e] = 0.0f;
    float m_i[2] = {-1e30f, -1e30f};
    float l_i[2] = {0.0f, 0.0f};

    int grow = mb * 128 + wid * 16;
    int row0 = grow + g, row1 = grow + g + 8;

    const __nv_bfloat16* srcs[4] = {khi, klo, vhi, vlo};
    auto load_kv = [&](int t, int stage) {
        int n0 = t * 64;
        __nv_bfloat16* base = dsm + (size_t)stage * 4 * 64 * SPAD;
#pragma unroll
        for (int a = 0; a < 4; a++) {
#pragma unroll
            for (int i = 0; i < 2; i++) {
                int idx = tid + i * 256;
                int r = idx >> 3;
                int c8 = (idx & 7) * 8;
                cpa16(smem_u32(base + (size_t)(a * 64 + r) * SPAD + c8),
                      srcs[a] + (size_t)(n0 + r) * HD + c8);
            }
        }
    };

    int ntiles = mb * 2 + 2;
    load_kv(0, 0);
    CP_COMMIT;

    for (int t = 0; t < ntiles; t++) {
        int stage = t & 1;
        if (t + 1 < ntiles) {
            load_kv(t + 1, stage ^ 1);
            CP_COMMIT;
            CP_WAIT1;
        } else {
            CP_WAIT0;
        }
        __syncthreads();

        __nv_bfloat16* sb = dsm + (size_t)stage * 4 * 64 * SPAD;
        __nv_bfloat16* sKh = sb;
        __nv_bfloat16* sKl = sb + 64 * SPAD;
        __nv_bfloat16* sVh = sb + 2 * 64 * SPAD;
        __nv_bfloat16* sVl = sb + 3 * 64 * SPAD;
        int n0 = t * 64;

        // ---- S = Q K^T (3-term split) ----
        float sacc[8][4];
#pragma unroll
        for (int nt = 0; nt < 8; nt++)
#pragma unroll
            for (int e = 0; e < 4; e++) sacc[nt][e] = 0.0f;

#pragma unroll
        for (int kt = 0; kt < 4; kt++) {
            uint32_t kb[8][2];
            {
                int rr = (lane & 7) + ((lane >> 4) << 3);
                int cc = kt * 16 + (((lane >> 3) & 1) << 3);
#pragma unroll
                for (int nb = 0; nb < 4; nb++) {
                    uint32_t t0, t1, t2, t3;
                    ldsm_x4(t0, t1, t2, t3,
                            smem_u32(sKh + (size_t)(nb * 16 + rr) * SPAD + cc));
                    kb[nb * 2 + 0][0] = t0; kb[nb * 2 + 0][1] = t1;
                    kb[nb * 2 + 1][0] = t2; kb[nb * 2 + 1][1] = t3;
                }
            }
#pragma unroll
            for (int nt = 0; nt < 8; nt++) {
                mma_bf16(sacc[nt], qha[kt], kb[nt]);
                mma_bf16(sacc[nt], qla[kt], kb[nt]);
            }
            {
                int rr = (lane & 7) + ((lane >> 4) << 3);
                int cc = kt * 16 + (((lane >> 3) & 1) << 3);
#pragma unroll
                for (int nb = 0; nb < 4; nb++) {
                    uint32_t t0, t1, t2, t3;
                    ldsm_x4(t0, t1, t2, t3,
                            smem_u32(sKl + (size_t)(nb * 16 + rr) * SPAD + cc));
                    kb[nb * 2 + 0][0] = t0; kb[nb * 2 + 0][1] = t1;
                    kb[nb * 2 + 1][0] = t2; kb[nb * 2 + 1][1] = t3;
                }
            }
#pragma unroll
            for (int nt = 0; nt < 8; nt++)
                mma_bf16(sacc[nt], qha[kt], kb[nt]);
        }

        // ---- causal mask + online softmax ----
        float rm[2] = {-1e30f, -1e30f};
#pragma unroll
        for (int nt = 0; nt < 8; nt++) {
            int col = n0 + nt * 8 + tg * 2;
            if (col > row0) sacc[nt][0] = -1e30f;
            if (col + 1 > row0) sacc[nt][1] = -1e30f;
            if (col > row1) sacc[nt][2] = -1e30f;
            if (col + 1 > row1) sacc[nt][3] = -1e30f;
            rm[0] = fmaxf(rm[0], fmaxf(sacc[nt][0], sacc[nt][1]));
            rm[1] = fmaxf(rm[1], fmaxf(sacc[nt][2], sacc[nt][3]));
        }
#pragma unroll
        for (int o = 1; o <= 2; o <<= 1) {
            rm[0] = fmaxf(rm[0], __shfl_xor_sync(0xffffffffu, rm[0], o));
            rm[1] = fmaxf(rm[1], __shfl_xor_sync(0xffffffffu, rm[1], o));
        }
        float m_new0 = fmaxf(m_i[0], rm[0]);
        float m_new1 = fmaxf(m_i[1], rm[1]);
        float corr0 = __expf(m_i[0] - m_new0);
        float corr1 = __expf(m_i[1] - m_new1);
        float ls0 = 0.0f, ls1 = 0.0f;
#pragma unroll
        for (int nt = 0; nt < 8; nt++) {
            sacc[nt][0] = __expf(sacc[nt][0] - m_new0);
            sacc[nt][1] = __expf(sacc[nt][1] - m_new0);
            sacc[nt][2] = __expf(sacc[nt][2] - m_new1);
            sacc[nt][3] = __expf(sacc[nt][3] - m_new1);
            ls0 += sacc[nt][0] + sacc[nt][1];
            ls1 += sacc[nt][2] + sacc[nt][3];
        }
#pragma unroll
        for (int o = 1; o <= 2; o <<= 1) {
            ls0 += __shfl_xor_sync(0xffffffffu, ls0, o);
            ls1 += __shfl_xor_sync(0xffffffffu, ls1, o);
        }
        l_i[0] = l_i[0] * corr0 + ls0;
        l_i[1] = l_i[1] * corr1 + ls1;
        m_i[0] = m_new0; m_i[1] = m_new1;
#pragma unroll
        for (int nt = 0; nt < 8; nt++) {
            oacc[nt][0] *= corr0; oacc[nt][1] *= corr0;
            oacc[nt][2] *= corr1; oacc[nt][3] *= corr1;
        }

        // ---- O += P V (3-term split) ----
#pragma unroll
        for (int kt = 0; kt < 4; kt++) {
            uint32_t pha[4], pla[4];
#pragma unroll
            for (int half = 0; half < 2; half++) {
                const float* pp = sacc[kt * 2 + half];
                __nv_bfloat16 h0 = __float2bfloat16(pp[0]);
                __nv_bfloat16 h1 = __float2bfloat16(pp[1]);
                __nv_bfloat16 h2 = __float2bfloat16(pp[2]);
                __nv_bfloat16 h3 = __float2bfloat16(pp[3]);
                __nv_bfloat162 a01(h0, h1), a23(h2, h3);
                pha[half * 2 + 0] = *(uint32_t*)&a01;
                pha[half * 2 + 1] = *(uint32_t*)&a23;
                __nv_bfloat162 l01(__float2bfloat16(pp[0] - __bfloat162float(h0)),
                                   __float2bfloat16(pp[1] - __bfloat162float(h1)));
                __nv_bfloat162 l23(__float2bfloat16(pp[2] - __bfloat162float(h2)),
                                   __float2bfloat16(pp[3] - __bfloat162float(h3)));
                pla[half * 2 + 0] = *(uint32_t*)&l01;
                pla[half * 2 + 1] = *(uint32_t*)&l23;
            }
            uint32_t vb[8][2];
            {
                int rr = kt * 16 + (lane & 15);
                int c0 = (lane >> 4) * 8;
#pragma unroll
                for (int nb = 0; nb < 4; nb++) {
                    uint32_t t0, t1, t2, t3;
                    ldsm_x4_t(t0, t1, t2, t3,
                              smem_u32(sVh + (size_t)rr * SPAD + nb * 16 + c0));
                    vb[nb * 2 + 0][0] = t0; vb[nb * 2 + 0][1] = t1;
                    vb[nb * 2 + 1][0] = t2; vb[nb * 2 + 1][1] = t3;
                }
            }
#pragma unroll
            for (int nt = 0; nt < 8; nt++) {
                mma_bf16(oacc[nt], pha, vb[nt]);
                mma_bf16(oacc[nt], pla, vb[nt]);
            }
            {
                int rr = kt * 16 + (lane & 15);
                int c0 = (lane >> 4) * 8;
#pragma unroll
                for (int nb = 0; nb < 4; nb++) {
                    uint32_t t0, t1, t2, t3;
                    ldsm_x4_t(t0, t1, t2, t3,
                              smem_u32(sVl + (size_t)rr * SPAD + nb * 16 + c0));
                    vb[nb * 2 + 0][0] = t0; vb[nb * 2 + 0][1] = t1;
                    vb[nb * 2 + 1][0] = t2; vb[nb * 2 + 1][1] = t3;
                }
            }
#pragma unroll
            for (int nt = 0; nt < 8; nt++)
                mma_bf16(oacc[nt], pha, vb[nt]);
        }
        __syncthreads();
    }

    // ---- epilogue: write bf16 hi/lo splits directly ----
    float inv0 = 1.0f / l_i[0];
    float inv1 = 1.0f / l_i[1];
#pragma unroll
    for (int nt = 0; nt < 8; nt++) {
        int col = h * HD + nt * 8 + tg * 2;
        size_t o0 = ((size_t)(b * S_LEN + row0)) * DM + col;
        size_t o1 = ((size_t)(b * S_LEN + row1)) * DM + col;
        float y00 = oacc[nt][0] * inv0, y01 = oacc[nt][1] * inv0;
        float y10 = oacc[nt][2] * inv1, y11 = oacc[nt][3] * inv1;
        __nv_bfloat16 h00 = __float2bfloat16(y00), h01 = __float2bfloat16(y01);
        __nv_bfloat16 h10 = __float2bfloat16(y10), h11 = __float2bfloat16(y11);
        *(__nv_bfloat162*)&g_aoh[o0] = __nv_bfloat162(h00, h01);
        *(__nv_bfloat162*)&g_aoh[o1] = __nv_bfloat162(h10, h11);
        *(__nv_bfloat162*)&g_aol[o0] = __nv_bfloat162(
            __float2bfloat16(y00 - __bfloat162float(h00)),
            __float2bfloat16(y01 - __bfloat162float(h01)));
        *(__nv_bfloat162*)&g_aol[o1] = __nv_bfloat162(
            __float2bfloat16(y10 - __bfloat162float(h10)),
            __float2bfloat16(y11 - __bfloat162float(h11)));
    }
}

// ---------------- launcher ----------------------------------------------------
extern "C" void kernel_launch(void* const* d_in, const int* in_sizes, int n_in,
                              void* d_out, int out_size) {
    const float* x   = (const float*)d_in[0];
    const float* Wq  = (const float*)d_in[1];
    const float* Wkv = (const float*)d_in[2];
    const float* Wo  = (const float*)d_in[3];
    const float* qs  = (const float*)d_in[4];
    const float* ks  = (const float*)d_in[5];
    float* out = (float*)d_out;

    float* pqkv;
    cudaGetSymbolAddress((void**)&pqkv, g_qkv_raw);

    __nv_bfloat16 *pxh, *pxl, *pw1h, *pw1l, *pwoh, *pwol, *paoh, *paol;
    cudaGetSymbolAddress((void**)&pxh, g_xh);
    cudaGetSymbolAddress((void**)&pxl, g_xl);
    cudaGetSymbolAddress((void**)&pw1h, g_w1h);
    cudaGetSymbolAddress((void**)&pw1l, g_w1l);
    cudaGetSymbolAddress((void**)&pwoh, g_woh);
    cudaGetSymbolAddress((void**)&pwol, g_wol);
    cudaGetSymbolAddress((void**)&paoh, g_aoh);
    cudaGetSymbolAddress((void**)&paol, g_aol);

    __nv_bfloat16 *pqhi, *pqlo, *pkhi, *pklo;
    cudaGetSymbolAddress((void**)&pqhi, g_qhi);
    cudaGetSymbolAddress((void**)&pqlo, g_qlo);
    cudaGetSymbolAddress((void**)&pkhi, g_khi);
    cudaGetSymbolAddress((void**)&pklo, g_klo);

    cudaFuncSetAttribute(attn_mma_kernel,
                         cudaFuncAttributeMaxDynamicSharedMemorySize, ATT_SMEM);

    int M = BATCH * S_LEN;  // 4096

    // 0) split-convert: X, [Wq|Wkv] merged wide, Wo
    cvt_split<<<(M * DM / 4 + 255) / 256, 256>>>(x, pxh, pxl, M * DM / 4);
    cvt_split_pad<<<(DM * DM / 4 + 255) / 256, 256>>>(Wq, pw1h, pw1l, DM, QKV_W, 0, DM * DM / 4);
    cvt_split_pad<<<(DM * KV_W / 4 + 255) / 256, 256>>>(Wkv, pw1h, pw1l, KV_W, QKV_W, DM, DM * KV_W / 4);
    cvt_split<<<(DM * DM / 4 + 255) / 256, 256>>>(Wo, pwoh, pwol, DM * DM / 4);

    // 1) merged QKV projection (one GEMM, N=1536)
    gemm_bf16_3x<<<dim3(QKV_W / GBN, M / GBM), 256>>>(
        pxh, pxl, pw1h, pw1l, pqkv, M, QKV_W, DM);

    // 2) rmsnorm + rope -> bf16 split (q pre-scaled by 1/8)
    normrope_kernel<<<(M * NH * 32 + 255) / 256, 256>>>(pqkv, pqhi, pqlo, qs, NH, QKV_W, 0, 0.125f);
    normrope_kernel<<<(M * NKV * 32 + 255) / 256, 256>>>(pqkv, pkhi, pklo, ks, NKV, QKV_W, DM, 1.0f);

    // 3) v rearrange + split
    vcopy_kernel<<<(BATCH * NKV * S_LEN * (HD / 4) + 255) / 256, 256>>>();

    // 4) mma.sync causal GQA attention (2-stage pipelined K/V)
    attn_mma_kernel<<<dim3(S_LEN / 128, NH, BATCH), 256, ATT_SMEM>>>();

    // 5) output projection
    gemm_bf16_3x<<<dim3(DM / GBN, M / GBM), 256>>>(paoh, paol, pwoh, pwol, out, M, DM, DM);
}

// round 8
// speedup vs baseline: 4.2438x; 1.0470x over previous
#include <cuda_runtime.h>
#include <cuda_bf16.h>
#include <math.h>
#include <stdint.h>

#define BATCH 2
#define S_LEN 2048
#define DM 1024
#define NH 16
#define NKV 4
#define HD 64
#define KV_W 512     // 2 * NKV * HD
#define QKV_W 1536   // DM + KV_W

// ---------------- scratch (device globals; no allocs allowed) ----------------
__device__ float g_qkv_raw[BATCH * S_LEN * QKV_W];  // X @ [Wq | Wkv]

// bf16 split buffers
__device__ __nv_bfloat16 g_xh[BATCH * S_LEN * DM];
__device__ __nv_bfloat16 g_xl[BATCH * S_LEN * DM];
__device__ __nv_bfloat16 g_w1h[DM * QKV_W];   // [Wq | Wkv]  [K=DM][N=1536]
__device__ __nv_bfloat16 g_w1l[DM * QKV_W];
__device__ __nv_bfloat16 g_woh[DM * DM];
__device__ __nv_bfloat16 g_wol[DM * DM];
__device__ __nv_bfloat16 g_aoh[BATCH * S_LEN * DM];
__device__ __nv_bfloat16 g_aol[BATCH * S_LEN * DM];

// bf16 split Q/K/V for attention  [b,h,s,d] / [b,kvh,s,d]
__device__ __nv_bfloat16 g_qhi[BATCH * NH * S_LEN * HD];
__device__ __nv_bfloat16 g_qlo[BATCH * NH * S_LEN * HD];
__device__ __nv_bfloat16 g_khi[BATCH * NKV * S_LEN * HD];
__device__ __nv_bfloat16 g_klo[BATCH * NKV * S_LEN * HD];
__device__ __nv_bfloat16 g_vhi[BATCH * NKV * S_LEN * HD];
__device__ __nv_bfloat16 g_vlo[BATCH * NKV * S_LEN * HD];

// ---------------- helpers ------------------------------------------------------
__device__ __forceinline__ uint32_t smem_u32(const void* p) {
    return (uint32_t)__cvta_generic_to_shared(p);
}
__device__ __forceinline__ void cpa16(uint32_t s, const void* g) {
    asm volatile("cp.async.cg.shared.global [%0], [%1], 16;" :: "r"(s), "l"(g));
}
#define CP_COMMIT asm volatile("cp.async.commit_group;")
#define CP_WAIT0  asm volatile("cp.async.wait_group 0;")
#define CP_WAIT1  asm volatile("cp.async.wait_group 1;")

__device__ __forceinline__ void ldsm_x4(uint32_t& r0, uint32_t& r1,
                                        uint32_t& r2, uint32_t& r3, uint32_t a) {
    asm volatile("ldmatrix.sync.aligned.m8n8.x4.shared.b16 {%0,%1,%2,%3},[%4];"
                 : "=r"(r0), "=r"(r1), "=r"(r2), "=r"(r3) : "r"(a));
}
__device__ __forceinline__ void ldsm_x4_t(uint32_t& r0, uint32_t& r1,
                                          uint32_t& r2, uint32_t& r3, uint32_t a) {
    asm volatile("ldmatrix.sync.aligned.m8n8.x4.trans.shared.b16 {%0,%1,%2,%3},[%4];"
                 : "=r"(r0), "=r"(r1), "=r"(r2), "=r"(r3) : "r"(a));
}
__device__ __forceinline__ void mma_bf16(float* c, const uint32_t* a,
                                         const uint32_t* b) {
    asm volatile(
        "mma.sync.aligned.m16n8k16.row.col.f32.bf16.bf16.f32 "
        "{%0,%1,%2,%3},{%4,%5,%6,%7},{%8,%9},{%0,%1,%2,%3};"
        : "+f"(c[0]), "+f"(c[1]), "+f"(c[2]), "+f"(c[3])
        : "r"(a[0]), "r"(a[1]), "r"(a[2]), "r"(a[3]), "r"(b[0]), "r"(b[1]));
}

// ---------------- fused fp32 -> (hi,lo) bf16 split for all 4 tensors ----------
__device__ __forceinline__ void split_write(float4 v, __nv_bfloat16* hi,
                                            __nv_bfloat16* lo, size_t o) {
    __nv_bfloat16 h0 = __float2bfloat16(v.x);
    __nv_bfloat16 h1 = __float2bfloat16(v.y);
    __nv_bfloat16 h2 = __float2bfloat16(v.z);
    __nv_bfloat16 h3 = __float2bfloat16(v.w);
    *(__nv_bfloat162*)(hi + o) = __nv_bfloat162(h0, h1);
    *(__nv_bfloat162*)(hi + o + 2) = __nv_bfloat162(h2, h3);
    *(__nv_bfloat162*)(lo + o) = __nv_bfloat162(
        __float2bfloat16(v.x - __bfloat162float(h0)),
        __float2bfloat16(v.y - __bfloat162float(h1)));
    *(__nv_bfloat162*)(lo + o + 2) = __nv_bfloat162(
        __float2bfloat16(v.z - __bfloat162float(h2)),
        __float2bfloat16(v.w - __bfloat162float(h3)));
}

// regions: [0,4096) X ; [4096,5120) Wq->w1 col0=0 ; [5120,5632) Wkv->w1 col0=DM ;
//          [5632,6656) Wo
__global__ void cvt_all(const float* __restrict__ x, const float* __restrict__ Wq,
                        const float* __restrict__ Wkv, const float* __restrict__ Wo) {
    int bx = blockIdx.x;
    int tid = threadIdx.x;
    if (bx < 4096) {
        int i = bx * 256 + tid;                 // float4 idx over X
        float4 v = *(const float4*)(x + (size_t)i * 4);
        split_write(v, g_xh, g_xl, (size_t)i * 4);
    } else if (bx < 5120) {
        int i = (bx - 4096) * 256 + tid;        // over Wq [DM][DM]
        int r = (i * 4) / DM, c = (i * 4) % DM;
        float4 v = *(const float4*)(Wq + (size_t)r * DM + c);
        split_write(v, g_w1h, g_w1l, (size_t)r * QKV_W + c);
    } else if (bx < 5632) {
        int i = (bx - 5120) * 256 + tid;        // over Wkv [DM][KV_W]
        int r = (i * 4) / KV_W, c = (i * 4) % KV_W;
        float4 v = *(const float4*)(Wkv + (size_t)r * KV_W + c);
        split_write(v, g_w1h, g_w1l, (size_t)r * QKV_W + DM + c);
    } else {
        int i = (bx - 5632) * 256 + tid;        // over Wo [DM][DM]
        float4 v = *(const float4*)(Wo + (size_t)i * 4);
        split_write(v, g_woh, g_wol, (size_t)i * 4);
    }
}

// ---------------- 3x bf16-split mma GEMM, 64x64 warp tiles, 2 CTAs/SM ---------
#define GBM 128
#define GBN 128
#define GBK 32

__global__ __launch_bounds__(128, 2) void gemm_bf16_3x(
    const __nv_bfloat16* __restrict__ Ah, const __nv_bfloat16* __restrict__ Al,
    const __nv_bfloat16* __restrict__ Bh, const __nv_bfloat16* __restrict__ Bl,
    float* __restrict__ C, int M, int N, int K) {
    __shared__ __align__(16) __nv_bfloat16 As[2][GBM][GBK + 8];   // 20.0 KB
    __shared__ __align__(16) __nv_bfloat16 Bs[2][GBK][GBN + 8];   // 17.0 KB

    int tid = threadIdx.x;
    int wid = tid >> 5, lane = tid & 31;
    int bm = blockIdx.y * GBM, bn = blockIdx.x * GBN;
    int wm = (wid & 1) * 64;
    int wn = (wid >> 1) * 64;

    int T = 3 * K / GBK;

    auto prefetch = [&](int t, int buf) {
        int kk = t * GBK;
        int seg = kk / K;
        int kl = kk - seg * K;
        const __nv_bfloat16* Aseg = (seg < 2) ? Ah : Al;
        const __nv_bfloat16* Bseg = (seg == 1) ? Bl : Bh;
#pragma unroll
        for (int i = 0; i < 4; i++) {
            int idx = tid + i * 128;                 // 0..511
            int ar = idx >> 2, ac = (idx & 3) * 8;   // A: 128 x 32
            cpa16(smem_u32(&As[buf][ar][ac]), Aseg + (size_t)(bm + ar) * K + kl + ac);
            int br = idx >> 4, bc = (idx & 15) * 8;  // B: 32 x 128
            cpa16(smem_u32(&Bs[buf][br][bc]), Bseg + (size_t)(kl + br) * N + bn + bc);
        }
    };

    float acc[4][8][4];
#pragma unroll
    for (int i = 0; i < 4; i++)
#pragma unroll
        for (int j = 0; j < 8; j++)
#pragma unroll
            for (int e = 0; e < 4; e++) acc[i][j][e] = 0.0f;

    prefetch(0, 0);
    CP_COMMIT;

    for (int t = 0; t < T; t++) {
        int buf = t & 1;
        CP_WAIT0;
        __syncthreads();
        if (t + 1 < T) {
            prefetch(t + 1, buf ^ 1);
            CP_COMMIT;
        }

#pragma unroll
        for (int k0 = 0; k0 < GBK; k0 += 16) {
            uint32_t a[4][4];
#pragma unroll
            for (int mt = 0; mt < 4; mt++) {
                int row = wm + mt * 16 + (lane & 15);
                int col = k0 + (lane >> 4) * 8;
                ldsm_x4(a[mt][0], a[mt][1], a[mt][2], a[mt][3],
                        smem_u32(&As[buf][row][col]));
            }
            uint32_t b[8][2];
#pragma unroll
            for (int np = 0; np < 4; np++) {
                int r = k0 + (lane & 15);
                int col = wn + np * 16 + (lane >> 4) * 8;
                uint32_t t0, t1, t2, t3;
                ldsm_x4_t(t0, t1, t2, t3, smem_u32(&Bs[buf][r][col]));
                b[np * 2 + 0][0] = t0; b[np * 2 + 0][1] = t1;
                b[np * 2 + 1][0] = t2; b[np * 2 + 1][1] = t3;
            }
#pragma unroll
            for (int mt = 0; mt < 4; mt++)
#pragma unroll
                for (int nt = 0; nt < 8; nt++)
                    mma_bf16(acc[mt][nt], a[mt], b[nt]);
        }
    }

    int g = lane >> 2, tg = lane & 3;
#pragma unroll
    for (int mt = 0; mt < 4; mt++) {
#pragma unroll
        for (int nt = 0; nt < 8; nt++) {
            int row = bm + wm + mt * 16 + g;
            int col = bn + wn + nt * 8 + tg * 2;
            *(float2*)&C[(size_t)row * N + col] =
                make_float2(acc[mt][nt][0], acc[mt][nt][1]);
            *(float2*)&C[(size_t)(row + 8) * N + col] =
                make_float2(acc[mt][nt][2], acc[mt][nt][3]);
        }
    }
}

// ---------------- fused RMSNorm+RoPE (Q,K) + V rearrange -----------------------
__device__ const double c_inv8[8] = {
    1.0, 0.74989420933245582, 0.56234132519034912, 0.42169650342858224,
    0.31622776601683794, 0.23713737056616552, 0.17782794100389229,
    0.13335214321633241};
__device__ const double c_p10[4] = {1.0, 0.1, 0.01, 0.001};

__device__ __forceinline__ void normrope_row(
    int gw, int lane, __nv_bfloat16* __restrict__ ohi,
    __nv_bfloat16* __restrict__ olo, const float* __restrict__ scale,
    int nheads, int col0, float post) {
    int h = gw % nheads;
    int s = (gw / nheads) % S_LEN;
    int b = gw / (nheads * S_LEN);

    const float* ip = g_qkv_raw + ((size_t)(b * S_LEN + s)) * QKV_W + col0 + h * HD;
    float x1 = ip[lane];
    float x2 = ip[lane + 32];
    float ss = x1 * x1 + x2 * x2;
#pragma unroll
    for (int o = 16; o; o >>= 1) ss += __shfl_xor_sync(0xffffffffu, ss, o);
    float inv = rsqrtf(ss * (1.0f / 64.0f) + 1e-5f);
    x1 *= inv * scale[lane];
    x2 *= inv * scale[lane + 32];

    float invf = (float)(c_inv8[lane & 7] * c_p10[lane >> 3]);
    float f = (float)s * invf;
    float c, sn;
    sincosf(f, &sn, &c);   // sincosf(x, SIN*, COS*)

    float y1 = (x1 * c - x2 * sn) * post;
    float y2 = (x1 * sn + x2 * c) * post;

    size_t base = (((size_t)(b * nheads + h)) * S_LEN + s) * HD;
    __nv_bfloat16 h1 = __float2bfloat16(y1);
    __nv_bfloat16 h2 = __float2bfloat16(y2);
    ohi[base + lane] = h1;
    ohi[base + lane + 32] = h2;
    olo[base + lane] = __float2bfloat16(y1 - __bfloat162float(h1));
    olo[base + lane + 32] = __float2bfloat16(y2 - __bfloat162float(h2));
}

// blocks: [0,8192) Q ; [8192,10240) K ; [10240,11264) V copy
__global__ void postproc_kernel(const float* __restrict__ qs,
                                const float* __restrict__ ks) {
    int bx = blockIdx.x;
    int tid = threadIdx.x;
    int wid = tid >> 5, lane = tid & 31;
    if (bx < 8192) {
        normrope_row(bx * 8 + wid, lane, g_qhi, g_qlo, qs, NH, 0, 0.125f);
    } else if (bx < 10240) {
        normrope_row((bx - 8192) * 8 + wid, lane, g_khi, g_klo, ks, NKV, DM, 1.0f);
    } else {
        int idx = (bx - 10240) * 256 + tid;   // float4 index
        int c4 = idx & 15;
        int tmp = idx >> 4;
        int s = tmp % S_LEN;
        int bk = tmp / S_LEN;
        int kvh = bk % NKV;
        int b = bk / NKV;
        float4 v = *(const float4*)(g_qkv_raw + ((size_t)(b * S_LEN + s)) * QKV_W +
                                    (DM + NKV * HD) + kvh * HD + c4 * 4);
        split_write(v, g_vhi, g_vlo, ((size_t)bk * S_LEN + s) * HD + c4 * 4);
    }
}

// ---------------- mma.sync causal GQA flash attention (2-stage K/V pipe) -------
#define SPAD 72   // 64 + 8
#define ATT_SMEM (2 * 4 * 64 * SPAD * 2)   // 73728 bytes

__global__ __launch_bounds__(256) void attn_mma_kernel() {
    extern __shared__ __align__(16) __nv_bfloat16 dsm[];

    int b = blockIdx.z, h = blockIdx.y;
    int mb = (int)(gridDim.x - 1) - (int)blockIdx.x;  // heavy CTAs first
    int kvh = h >> 2;
    int tid = threadIdx.x;
    int wid = tid >> 5, lane = tid & 31;
    int g = lane >> 2, tg = lane & 3;

    const __nv_bfloat16* qhi = g_qhi + (((size_t)(b * NH + h)) * S_LEN + mb * 128) * HD;
    const __nv_bfloat16* qlo = g_qlo + (((size_t)(b * NH + h)) * S_LEN + mb * 128) * HD;
    const __nv_bfloat16* khi = g_khi + ((size_t)(b * NKV + kvh)) * S_LEN * HD;
    const __nv_bfloat16* klo = g_klo + ((size_t)(b * NKV + kvh)) * S_LEN * HD;
    const __nv_bfloat16* vhi = g_vhi + ((size_t)(b * NKV + kvh)) * S_LEN * HD;
    const __nv_bfloat16* vlo = g_vlo + ((size_t)(b * NKV + kvh)) * S_LEN * HD;

    __nv_bfloat16* qs = dsm;   // [256][SPAD]
#pragma unroll
    for (int i = 0; i < 4; i++) {
        int idx = tid + i * 256;
        int r = idx >> 3;
        int c8 = (idx & 7) * 8;
        cpa16(smem_u32(qs + (size_t)r * SPAD + c8), qhi + (size_t)r * HD + c8);
        cpa16(smem_u32(qs + (size_t)(r + 128) * SPAD + c8), qlo + (size_t)r * HD + c8);
    }
    CP_COMMIT; CP_WAIT0;
    __syncthreads();

    uint32_t qha[4][4], qla[4][4];
    {
        int row = wid * 16 + (lane & 15);
#pragma unroll
        for (int kt = 0; kt < 4; kt++) {
            int col = kt * 16 + (lane >> 4) * 8;
            ldsm_x4(qha[kt][0], qha[kt][1], qha[kt][2], qha[kt][3],
                    smem_u32(qs + (size_t)row * SPAD + col));
            ldsm_x4(qla[kt][0], qla[kt][1], qla[kt][2], qla[kt][3],
                    smem_u32(qs + (size_t)(row + 128) * SPAD + col));
        }
    }
    __syncthreads();

    float oacc[8][4];
#pragma unroll
    for (int nt = 0; nt < 8; nt++)
#pragma unroll
        for (int e = 0; e < 4; e++) oacc[nt][e] = 0.0f;
    float m_i[2] = {-1e30f, -1e30f};
    float l_i[2] = {0.0f, 0.0f};

    int grow = mb * 128 + wid * 16;
    int row0 = grow + g, row1 = grow + g + 8;

    const __nv_bfloat16* srcs[4] = {khi, klo, vhi, vlo};
    auto load_kv = [&](int t, int stage) {
        int n0 = t * 64;
        __nv_bfloat16* base = dsm + (size_t)stage * 4 * 64 * SPAD;
#pragma unroll
        for (int a = 0; a < 4; a++) {
#pragma unroll
            for (int i = 0; i < 2; i++) {
                int idx = tid + i * 256;
                int r = idx >> 3;
                int c8 = (idx & 7) * 8;
                cpa16(smem_u32(base + (size_t)(a * 64 + r) * SPAD + c8),
                      srcs[a] + (size_t)(n0 + r) * HD + c8);
            }
        }
    };

    int ntiles = mb * 2 + 2;
    load_kv(0, 0);
    CP_COMMIT;

    for (int t = 0; t < ntiles; t++) {
        int stage = t & 1;
        if (t + 1 < ntiles) {
            load_kv(t + 1, stage ^ 1);
            CP_COMMIT;
            CP_WAIT1;
        } else {
            CP_WAIT0;
        }
        __syncthreads();

        __nv_bfloat16* sb = dsm + (size_t)stage * 4 * 64 * SPAD;
        __nv_bfloat16* sKh = sb;
        __nv_bfloat16* sKl = sb + 64 * SPAD;
        __nv_bfloat16* sVh = sb + 2 * 64 * SPAD;
        __nv_bfloat16* sVl = sb + 3 * 64 * SPAD;
        int n0 = t * 64;

        float sacc[8][4];
#pragma unroll
        for (int nt = 0; nt < 8; nt++)
#pragma unroll
            for (int e = 0; e < 4; e++) sacc[nt][e] = 0.0f;

#pragma unroll
        for (int kt = 0; kt < 4; kt++) {
            uint32_t kb[8][2];
            {
                int rr = (lane & 7) + ((lane >> 4) << 3);
                int cc = kt * 16 + (((lane >> 3) & 1) << 3);
#pragma unroll
                for (int nb = 0; nb < 4; nb++) {
                    uint32_t t0, t1, t2, t3;
                    ldsm_x4(t0, t1, t2, t3,
                            smem_u32(sKh + (size_t)(nb * 16 + rr) * SPAD + cc));
                    kb[nb * 2 + 0][0] = t0; kb[nb * 2 + 0][1] = t1;
                    kb[nb * 2 + 1][0] = t2; kb[nb * 2 + 1][1] = t3;
                }
            }
#pragma unroll
            for (int nt = 0; nt < 8; nt++) {
                mma_bf16(sacc[nt], qha[kt], kb[nt]);
                mma_bf16(sacc[nt], qla[kt], kb[nt]);
            }
            {
                int rr = (lane & 7) + ((lane >> 4) << 3);
                int cc = kt * 16 + (((lane >> 3) & 1) << 3);
#pragma unroll
                for (int nb = 0; nb < 4; nb++) {
                    uint32_t t0, t1, t2, t3;
                    ldsm_x4(t0, t1, t2, t3,
                            smem_u32(sKl + (size_t)(nb * 16 + rr) * SPAD + cc));
                    kb[nb * 2 + 0][0] = t0; kb[nb * 2 + 0][1] = t1;
                    kb[nb * 2 + 1][0] = t2; kb[nb * 2 + 1][1] = t3;
                }
            }
#pragma unroll
            for (int nt = 0; nt < 8; nt++)
                mma_bf16(sacc[nt], qha[kt], kb[nt]);
        }

        float rm[2] = {-1e30f, -1e30f};
#pragma unroll
        for (int nt = 0; nt < 8; nt++) {
            int col = n0 + nt * 8 + tg * 2;
            if (col > row0) sacc[nt][0] = -1e30f;
            if (col + 1 > row0) sacc[nt][1] = -1e30f;
            if (col > row1) sacc[nt][2] = -1e30f;
            if (col + 1 > row1) sacc[nt][3] = -1e30f;
            rm[0] = fmaxf(rm[0], fmaxf(sacc[nt][0], sacc[nt][1]));
            rm[1] = fmaxf(rm[1], fmaxf(sacc[nt][2], sacc[nt][3]));
        }
#pragma unroll
        for (int o = 1; o <= 2; o <<= 1) {
            rm[0] = fmaxf(rm[0], __shfl_xor_sync(0xffffffffu, rm[0], o));
            rm[1] = fmaxf(rm[1], __shfl_xor_sync(0xffffffffu, rm[1], o));
        }
        float m_new0 = fmaxf(m_i[0], rm[0]);
        float m_new1 = fmaxf(m_i[1], rm[1]);
        float corr0 = __expf(m_i[0] - m_new0);
        float corr1 = __expf(m_i[1] - m_new1);
        float ls0 = 0.0f, ls1 = 0.0f;
#pragma unroll
        for (int nt = 0; nt < 8; nt++) {
            sacc[nt][0] = __expf(sacc[nt][0] - m_new0);
            sacc[nt][1] = __expf(sacc[nt][1] - m_new0);
            sacc[nt][2] = __expf(sacc[nt][2] - m_new1);
            sacc[nt][3] = __expf(sacc[nt][3] - m_new1);
            ls0 += sacc[nt][0] + sacc[nt][1];
            ls1 += sacc[nt][2] + sacc[nt][3];
        }
#pragma unroll
        for (int o = 1; o <= 2; o <<= 1) {
            ls0 += __shfl_xor_sync(0xffffffffu, ls0, o);
            ls1 += __shfl_xor_sync(0xffffffffu, ls1, o);
        }
        l_i[0] = l_i[0] * corr0 + ls0;
        l_i[1] = l_i[1] * corr1 + ls1;
        m_i[0] = m_new0; m_i[1] = m_new1;
#pragma unroll
        for (int nt = 0; nt < 8; nt++) {
            oacc[nt][0] *= corr0; oacc[nt][1] *= corr0;
            oacc[nt][2] *= corr1; oacc[nt][3] *= corr1;
        }

#pragma unroll
        for (int kt = 0; kt < 4; kt++) {
            uint32_t pha[4], pla[4];
#pragma unroll
            for (int half = 0; half < 2; half++) {
                const float* pp = sacc[kt * 2 + half];
                __nv_bfloat16 h0 = __float2bfloat16(pp[0]);
                __nv_bfloat16 h1 = __float2bfloat16(pp[1]);
                __nv_bfloat16 h2 = __float2bfloat16(pp[2]);
                __nv_bfloat16 h3 = __float2bfloat16(pp[3]);
                __nv_bfloat162 a01(h0, h1), a23(h2, h3);
                pha[half * 2 + 0] = *(uint32_t*)&a01;
                pha[half * 2 + 1] = *(uint32_t*)&a23;
                __nv_bfloat162 l01(__float2bfloat16(pp[0] - __bfloat162float(h0)),
                                   __float2bfloat16(pp[1] - __bfloat162float(h1)));
                __nv_bfloat162 l23(__float2bfloat16(pp[2] - __bfloat162float(h2)),
                                   __float2bfloat16(pp[3] - __bfloat162float(h3)));
                pla[half * 2 + 0] = *(uint32_t*)&l01;
                pla[half * 2 + 1] = *(uint32_t*)&l23;
            }
            uint32_t vb[8][2];
            {
                int rr = kt * 16 + (lane & 15);
                int c0 = (lane >> 4) * 8;
#pragma unroll
                for (int nb = 0; nb < 4; nb++) {
                    uint32_t t0, t1, t2, t3;
                    ldsm_x4_t(t0, t1, t2, t3,
                              smem_u32(sVh + (size_t)rr * SPAD + nb * 16 + c0));
                    vb[nb * 2 + 0][0] = t0; vb[nb * 2 + 0][1] = t1;
                    vb[nb * 2 + 1][0] = t2; vb[nb * 2 + 1][1] = t3;
                }
            }
#pragma unroll
            for (int nt = 0; nt < 8; nt++) {
                mma_bf16(oacc[nt], pha, vb[nt]);
                mma_bf16(oacc[nt], pla, vb[nt]);
            }
            {
                int rr = kt * 16 + (lane & 15);
                int c0 = (lane >> 4) * 8;
#pragma unroll
                for (int nb = 0; nb < 4; nb++) {
                    uint32_t t0, t1, t2, t3;
                    ldsm_x4_t(t0, t1, t2, t3,
                              smem_u32(sVl + (size_t)rr * SPAD + nb * 16 + c0));
                    vb[nb * 2 + 0][0] = t0; vb[nb * 2 + 0][1] = t1;
                    vb[nb * 2 + 1][0] = t2; vb[nb * 2 + 1][1] = t3;
                }
            }
#pragma unroll
            for (int nt = 0; nt < 8; nt++)
                mma_bf16(oacc[nt], pha, vb[nt]);
        }
        __syncthreads();
    }

    float inv0 = 1.0f / l_i[0];
    float inv1 = 1.0f / l_i[1];
#pragma unroll
    for (int nt = 0; nt < 8; nt++) {
        int col = h * HD + nt * 8 + tg * 2;
        size_t o0 = ((size_t)(b * S_LEN + row0)) * DM + col;
        size_t o1 = ((size_t)(b * S_LEN + row1)) * DM + col;
        float y00 = oacc[nt][0] * inv0, y01 = oacc[nt][1] * inv0;
        float y10 = oacc[nt][2] * inv1, y11 = oacc[nt][3] * inv1;
        __nv_bfloat16 h00 = __float2bfloat16(y00), h01 = __float2bfloat16(y01);
        __nv_bfloat16 h10 = __float2bfloat16(y10), h11 = __float2bfloat16(y11);
        *(__nv_bfloat162*)&g_aoh[o0] = __nv_bfloat162(h00, h01);
        *(__nv_bfloat162*)&g_aoh[o1] = __nv_bfloat162(h10, h11);
        *(__nv_bfloat162*)&g_aol[o0] = __nv_bfloat162(
            __float2bfloat16(y00 - __bfloat162float(h00)),
            __float2bfloat16(y01 - __bfloat162float(h01)));
        *(__nv_bfloat162*)&g_aol[o1] = __nv_bfloat162(
            __float2bfloat16(y10 - __bfloat162float(h10)),
            __float2bfloat16(y11 - __bfloat162float(h11)));
    }
}

// ---------------- launcher ----------------------------------------------------
extern "C" void kernel_launch(void* const* d_in, const int* in_sizes, int n_in,
                              void* d_out, int out_size) {
    const float* x   = (const float*)d_in[0];
    const float* Wq  = (const float*)d_in[1];
    const float* Wkv = (const float*)d_in[2];
    const float* Wo  = (const float*)d_in[3];
    const float* qs  = (const float*)d_in[4];
    const float* ks  = (const float*)d_in[5];
    float* out = (float*)d_out;

    float* pqkv;
    cudaGetSymbolAddress((void**)&pqkv, g_qkv_raw);

    __nv_bfloat16 *pxh, *pxl, *pw1h, *pw1l, *pwoh, *pwol, *paoh, *paol;
    cudaGetSymbolAddress((void**)&pxh, g_xh);
    cudaGetSymbolAddress((void**)&pxl, g_xl);
    cudaGetSymbolAddress((void**)&pw1h, g_w1h);
    cudaGetSymbolAddress((void**)&pw1l, g_w1l);
    cudaGetSymbolAddress((void**)&pwoh, g_woh);
    cudaGetSymbolAddress((void**)&pwol, g_wol);
    cudaGetSymbolAddress((void**)&paoh, g_aoh);
    cudaGetSymbolAddress((void**)&paol, g_aol);

    cudaFuncSetAttribute(attn_mma_kernel,
                         cudaFuncAttributeMaxDynamicSharedMemorySize, ATT_SMEM);

    int M = BATCH * S_LEN;  // 4096

    // 0) fused split-convert of X, [Wq|Wkv], Wo
    cvt_all<<<6656, 256>>>(x, Wq, Wkv, Wo);

    // 1) merged QKV projection (one GEMM, N=1536)
    gemm_bf16_3x<<<dim3(QKV_W / GBN, M / GBM), 128>>>(
        pxh, pxl, pw1h, pw1l, pqkv, M, QKV_W, DM);

    // 2) fused rmsnorm+rope (Q,K) + V rearrange
    postproc_kernel<<<11264, 256>>>(qs, ks);

    // 3) mma.sync causal GQA attention (2-stage pipelined K/V)
    attn_mma_kernel<<<dim3(S_LEN / 128, NH, BATCH), 256, ATT_SMEM>>>();

    // 4) output projection
    gemm_bf16_3x<<<dim3(DM / GBN, M / GBM), 128>>>(paoh, paol, pwoh, pwol, out, M, DM, DM);
}

// round 9
// speedup vs baseline: 4.2597x; 1.0037x over previous
#include <cuda_runtime.h>
#include <cuda_bf16.h>
#include <math.h>
#include <stdint.h>

#define BATCH 2
#define S_LEN 2048
#define DM 1024
#define NH 16
#define NKV 4
#define HD 64
#define KV_W 512     // 2 * NKV * HD
#define QKV_W 1536   // DM + KV_W

// ---------------- scratch (device globals; no allocs allowed) ----------------
__device__ float g_qkv_raw[BATCH * S_LEN * QKV_W];  // X @ [Wq | Wkv]

// bf16 split buffers
__device__ __nv_bfloat16 g_xh[BATCH * S_LEN * DM];
__device__ __nv_bfloat16 g_xl[BATCH * S_LEN * DM];
__device__ __nv_bfloat16 g_w1h[DM * QKV_W];   // [Wq | Wkv]  [K=DM][N=1536]
__device__ __nv_bfloat16 g_w1l[DM * QKV_W];
__device__ __nv_bfloat16 g_woh[DM * DM];
__device__ __nv_bfloat16 g_wol[DM * DM];
__device__ __nv_bfloat16 g_aoh[BATCH * S_LEN * DM];
__device__ __nv_bfloat16 g_aol[BATCH * S_LEN * DM];

// bf16 split Q/K/V for attention  [b,h,s,d] / [b,kvh,s,d]
__device__ __nv_bfloat16 g_qhi[BATCH * NH * S_LEN * HD];
__device__ __nv_bfloat16 g_qlo[BATCH * NH * S_LEN * HD];
__device__ __nv_bfloat16 g_khi[BATCH * NKV * S_LEN * HD];
__device__ __nv_bfloat16 g_klo[BATCH * NKV * S_LEN * HD];
__device__ __nv_bfloat16 g_vhi[BATCH * NKV * S_LEN * HD];
__device__ __nv_bfloat16 g_vlo[BATCH * NKV * S_LEN * HD];

// ---------------- helpers ------------------------------------------------------
__device__ __forceinline__ uint32_t smem_u32(const void* p) {
    return (uint32_t)__cvta_generic_to_shared(p);
}
__device__ __forceinline__ void cpa16(uint32_t s, const void* g) {
    asm volatile("cp.async.cg.shared.global [%0], [%1], 16;" :: "r"(s), "l"(g));
}
#define CP_COMMIT asm volatile("cp.async.commit_group;")
#define CP_WAIT0  asm volatile("cp.async.wait_group 0;")
#define CP_WAIT1  asm volatile("cp.async.wait_group 1;")

__device__ __forceinline__ void ldsm_x4(uint32_t& r0, uint32_t& r1,
                                        uint32_t& r2, uint32_t& r3, uint32_t a) {
    asm volatile("ldmatrix.sync.aligned.m8n8.x4.shared.b16 {%0,%1,%2,%3},[%4];"
                 : "=r"(r0), "=r"(r1), "=r"(r2), "=r"(r3) : "r"(a));
}
__device__ __forceinline__ void ldsm_x4_t(uint32_t& r0, uint32_t& r1,
                                          uint32_t& r2, uint32_t& r3, uint32_t a) {
    asm volatile("ldmatrix.sync.aligned.m8n8.x4.trans.shared.b16 {%0,%1,%2,%3},[%4];"
                 : "=r"(r0), "=r"(r1), "=r"(r2), "=r"(r3) : "r"(a));
}
__device__ __forceinline__ void mma_bf16(float* c, const uint32_t* a,
                                         const uint32_t* b) {
    asm volatile(
        "mma.sync.aligned.m16n8k16.row.col.f32.bf16.bf16.f32 "
        "{%0,%1,%2,%3},{%4,%5,%6,%7},{%8,%9},{%0,%1,%2,%3};"
        : "+f"(c[0]), "+f"(c[1]), "+f"(c[2]), "+f"(c[3])
        : "r"(a[0]), "r"(a[1]), "r"(a[2]), "r"(a[3]), "r"(b[0]), "r"(b[1]));
}

// ---------------- fused fp32 -> (hi,lo) bf16 split for all 4 tensors ----------
__device__ __forceinline__ void split_write(float4 v, __nv_bfloat16* hi,
                                            __nv_bfloat16* lo, size_t o) {
    __nv_bfloat16 h0 = __float2bfloat16(v.x);
    __nv_bfloat16 h1 = __float2bfloat16(v.y);
    __nv_bfloat16 h2 = __float2bfloat16(v.z);
    __nv_bfloat16 h3 = __float2bfloat16(v.w);
    *(__nv_bfloat162*)(hi + o) = __nv_bfloat162(h0, h1);
    *(__nv_bfloat162*)(hi + o + 2) = __nv_bfloat162(h2, h3);
    *(__nv_bfloat162*)(lo + o) = __nv_bfloat162(
        __float2bfloat16(v.x - __bfloat162float(h0)),
        __float2bfloat16(v.y - __bfloat162float(h1)));
    *(__nv_bfloat162*)(lo + o + 2) = __nv_bfloat162(
        __float2bfloat16(v.z - __bfloat162float(h2)),
        __float2bfloat16(v.w - __bfloat162float(h3)));
}

// regions: [0,4096) X ; [4096,5120) Wq->w1 col0=0 ; [5120,5632) Wkv->w1 col0=DM ;
//          [5632,6656) Wo
__global__ void cvt_all(const float* __restrict__ x, const float* __restrict__ Wq,
                        const float* __restrict__ Wkv, const float* __restrict__ Wo) {
    int bx = blockIdx.x;
    int tid = threadIdx.x;
    if (bx < 4096) {
        int i = bx * 256 + tid;                 // float4 idx over X
        float4 v = *(const float4*)(x + (size_t)i * 4);
        split_write(v, g_xh, g_xl, (size_t)i * 4);
    } else if (bx < 5120) {
        int i = (bx - 4096) * 256 + tid;        // over Wq [DM][DM]
        int r = (i * 4) / DM, c = (i * 4) % DM;
        float4 v = *(const float4*)(Wq + (size_t)r * DM + c);
        split_write(v, g_w1h, g_w1l, (size_t)r * QKV_W + c);
    } else if (bx < 5632) {
        int i = (bx - 5120) * 256 + tid;        // over Wkv [DM][KV_W]
        int r = (i * 4) / KV_W, c = (i * 4) % KV_W;
        float4 v = *(const float4*)(Wkv + (size_t)r * KV_W + c);
        split_write(v, g_w1h, g_w1l, (size_t)r * QKV_W + DM + c);
    } else {
        int i = (bx - 5632) * 256 + tid;        // over Wo [DM][DM]
        float4 v = *(const float4*)(Wo + (size_t)i * 4);
        split_write(v, g_woh, g_wol, (size_t)i * 4);
    }
}

// ---------------- 3x bf16-split mma GEMM, 64x64 warp tiles, 2 CTAs/SM ---------
#define GBM 128
#define GBN 128
#define GBK 32

__global__ __launch_bounds__(128, 2) void gemm_bf16_3x(
    const __nv_bfloat16* __restrict__ Ah, const __nv_bfloat16* __restrict__ Al,
    const __nv_bfloat16* __restrict__ Bh, const __nv_bfloat16* __restrict__ Bl,
    float* __restrict__ C, int M, int N, int K) {
    __shared__ __align__(16) __nv_bfloat16 As[2][GBM][GBK + 8];   // 20.0 KB
    __shared__ __align__(16) __nv_bfloat16 Bs[2][GBK][GBN + 8];   // 17.0 KB

    int tid = threadIdx.x;
    int wid = tid >> 5, lane = tid & 31;
    int bm = blockIdx.y * GBM, bn = blockIdx.x * GBN;
    int wm = (wid & 1) * 64;
    int wn = (wid >> 1) * 64;

    int T = 3 * K / GBK;

    auto prefetch = [&](int t, int buf) {
        int kk = t * GBK;
        int seg = kk / K;
        int kl = kk - seg * K;
        const __nv_bfloat16* Aseg = (seg < 2) ? Ah : Al;
        const __nv_bfloat16* Bseg = (seg == 1) ? Bl : Bh;
#pragma unroll
        for (int i = 0; i < 4; i++) {
            int idx = tid + i * 128;                 // 0..511
            int ar = idx >> 2, ac = (idx & 3) * 8;   // A: 128 x 32
            cpa16(smem_u32(&As[buf][ar][ac]), Aseg + (size_t)(bm + ar) * K + kl + ac);
            int br = idx >> 4, bc = (idx & 15) * 8;  // B: 32 x 128
            cpa16(smem_u32(&Bs[buf][br][bc]), Bseg + (size_t)(kl + br) * N + bn + bc);
        }
    };

    float acc[4][8][4];
#pragma unroll
    for (int i = 0; i < 4; i++)
#pragma unroll
        for (int j = 0; j < 8; j++)
#pragma unroll
            for (int e = 0; e < 4; e++) acc[i][j][e] = 0.0f;

    prefetch(0, 0);
    CP_COMMIT;

    for (int t = 0; t < T; t++) {
        int buf = t & 1;
        CP_WAIT0;
        __syncthreads();
        if (t + 1 < T) {
            prefetch(t + 1, buf ^ 1);
            CP_COMMIT;
        }

#pragma unroll
        for (int k0 = 0; k0 < GBK; k0 += 16) {
            uint32_t a[4][4];
#pragma unroll
            for (int mt = 0; mt < 4; mt++) {
                int row = wm + mt * 16 + (lane & 15);
                int col = k0 + (lane >> 4) * 8;
                ldsm_x4(a[mt][0], a[mt][1], a[mt][2], a[mt][3],
                        smem_u32(&As[buf][row][col]));
            }
            uint32_t b[8][2];
#pragma unroll
            for (int np = 0; np < 4; np++) {
                int r = k0 + (lane & 15);
                int col = wn + np * 16 + (lane >> 4) * 8;
                uint32_t t0, t1, t2, t3;
                ldsm_x4_t(t0, t1, t2, t3, smem_u32(&Bs[buf][r][col]));
                b[np * 2 + 0][0] = t0; b[np * 2 + 0][1] = t1;
                b[np * 2 + 1][0] = t2; b[np * 2 + 1][1] = t3;
            }
#pragma unroll
            for (int mt = 0; mt < 4; mt++)
#pragma unroll
                for (int nt = 0; nt < 8; nt++)
                    mma_bf16(acc[mt][nt], a[mt], b[nt]);
        }
    }

    int g = lane >> 2, tg = lane & 3;
#pragma unroll
    for (int mt = 0; mt < 4; mt++) {
#pragma unroll
        for (int nt = 0; nt < 8; nt++) {
            int row = bm + wm + mt * 16 + g;
            int col = bn + wn + nt * 8 + tg * 2;
            *(float2*)&C[(size_t)row * N + col] =
                make_float2(acc[mt][nt][0], acc[mt][nt][1]);
            *(float2*)&C[(size_t)(row + 8) * N + col] =
                make_float2(acc[mt][nt][2], acc[mt][nt][3]);
        }
    }
}

// ---------------- fused RMSNorm+RoPE (Q,K) + V rearrange -----------------------
__device__ const double c_inv8[8] = {
    1.0, 0.74989420933245582, 0.56234132519034912, 0.42169650342858224,
    0.31622776601683794, 0.23713737056616552, 0.17782794100389229,
    0.13335214321633241};
__device__ const double c_p10[4] = {1.0, 0.1, 0.01, 0.001};

__device__ __forceinline__ void normrope_row(
    int gw, int lane, __nv_bfloat16* __restrict__ ohi,
    __nv_bfloat16* __restrict__ olo, const float* __restrict__ scale,
    int nheads, int col0, float post) {
    int h = gw % nheads;
    int s = (gw / nheads) % S_LEN;
    int b = gw / (nheads * S_LEN);

    const float* ip = g_qkv_raw + ((size_t)(b * S_LEN + s)) * QKV_W + col0 + h * HD;
    float x1 = ip[lane];
    float x2 = ip[lane + 32];
    float ss = x1 * x1 + x2 * x2;
#pragma unroll
    for (int o = 16; o; o >>= 1) ss += __shfl_xor_sync(0xffffffffu, ss, o);
    float inv = rsqrtf(ss * (1.0f / 64.0f) + 1e-5f);
    x1 *= inv * scale[lane];
    x2 *= inv * scale[lane + 32];

    float invf = (float)(c_inv8[lane & 7] * c_p10[lane >> 3]);
    float f = (float)s * invf;
    float c, sn;
    sincosf(f, &sn, &c);   // sincosf(x, SIN*, COS*)

    float y1 = (x1 * c - x2 * sn) * post;
    float y2 = (x1 * sn + x2 * c) * post;

    size_t base = (((size_t)(b * nheads + h)) * S_LEN + s) * HD;
    __nv_bfloat16 h1 = __float2bfloat16(y1);
    __nv_bfloat16 h2 = __float2bfloat16(y2);
    ohi[base + lane] = h1;
    ohi[base + lane + 32] = h2;
    olo[base + lane] = __float2bfloat16(y1 - __bfloat162float(h1));
    olo[base + lane + 32] = __float2bfloat16(y2 - __bfloat162float(h2));
}

// blocks: [0,8192) Q ; [8192,10240) K ; [10240,11264) V copy
__global__ void postproc_kernel(const float* __restrict__ qs,
                                const float* __restrict__ ks) {
    int bx = blockIdx.x;
    int tid = threadIdx.x;
    int wid = tid >> 5, lane = tid & 31;
    if (bx < 8192) {
        normrope_row(bx * 8 + wid, lane, g_qhi, g_qlo, qs, NH, 0, 0.125f);
    } else if (bx < 10240) {
        normrope_row((bx - 8192) * 8 + wid, lane, g_khi, g_klo, ks, NKV, DM, 1.0f);
    } else {
        int idx = (bx - 10240) * 256 + tid;   // float4 index
        int c4 = idx & 15;
        int tmp = idx >> 4;
        int s = tmp % S_LEN;
        int bk = tmp / S_LEN;
        int kvh = bk % NKV;
        int b = bk / NKV;
        float4 v = *(const float4*)(g_qkv_raw + ((size_t)(b * S_LEN + s)) * QKV_W +
                                    (DM + NKV * HD) + kvh * HD + c4 * 4);
        split_write(v, g_vhi, g_vlo, ((size_t)bk * S_LEN + s) * HD + c4 * 4);
    }
}

// ---------------- mma.sync causal GQA flash attention (2-stage K/V pipe) -------
// __launch_bounds__(256, 2): cap regs at 128 so 2 CTAs/SM fit (R8 profile:
// regs=138 -> occ 12.5%, issue 29.5%, tensor 38.7% -- occupancy-bound).
#define SPAD 72   // 64 + 8
#define ATT_SMEM (2 * 4 * 64 * SPAD * 2)   // 73728 bytes

__global__ __launch_bounds__(256, 2) void attn_mma_kernel() {
    extern __shared__ __align__(16) __nv_bfloat16 dsm[];

    int b = blockIdx.z, h = blockIdx.y;
    int mb = (int)(gridDim.x - 1) - (int)blockIdx.x;  // heavy CTAs first
    int kvh = h >> 2;
    int tid = threadIdx.x;
    int wid = tid >> 5, lane = tid & 31;
    int g = lane >> 2, tg = lane & 3;

    const __nv_bfloat16* qhi = g_qhi + (((size_t)(b * NH + h)) * S_LEN + mb * 128) * HD;
    const __nv_bfloat16* qlo = g_qlo + (((size_t)(b * NH + h)) * S_LEN + mb * 128) * HD;
    const __nv_bfloat16* khi = g_khi + ((size_t)(b * NKV + kvh)) * S_LEN * HD;
    const __nv_bfloat16* klo = g_klo + ((size_t)(b * NKV + kvh)) * S_LEN * HD;
    const __nv_bfloat16* vhi = g_vhi + ((size_t)(b * NKV + kvh)) * S_LEN * HD;
    const __nv_bfloat16* vlo = g_vlo + ((size_t)(b * NKV + kvh)) * S_LEN * HD;

    __nv_bfloat16* qs = dsm;   // [256][SPAD]
#pragma unroll
    for (int i = 0; i < 4; i++) {
        int idx = tid + i * 256;
        int r = idx >> 3;
        int c8 = (idx & 7) * 8;
        cpa16(smem_u32(qs + (size_t)r * SPAD + c8), qhi + (size_t)r * HD + c8);
        cpa16(smem_u32(qs + (size_t)(r + 128) * SPAD + c8), qlo + (size_t)r * HD + c8);
    }
    CP_COMMIT; CP_WAIT0;
    __syncthreads();

    uint32_t qha[4][4], qla[4][4];
    {
        int row = wid * 16 + (lane & 15);
#pragma unroll
        for (int kt = 0; kt < 4; kt++) {
            int col = kt * 16 + (lane >> 4) * 8;
            ldsm_x4(qha[kt][0], qha[kt][1], qha[kt][2], qha[kt][3],
                    smem_u32(qs + (size_t)row * SPAD + col));
            ldsm_x4(qla[kt][0], qla[kt][1], qla[kt][2], qla[kt][3],
                    smem_u32(qs + (size_t)(row + 128) * SPAD + col));
        }
    }
    __syncthreads();

    float oacc[8][4];
#pragma unroll
    for (int nt = 0; nt < 8; nt++)
#pragma unroll
        for (int e = 0; e < 4; e++) oacc[nt][e] = 0.0f;
    float m_i[2] = {-1e30f, -1e30f};
    float l_i[2] = {0.0f, 0.0f};

    int grow = mb * 128 + wid * 16;
    int row0 = grow + g, row1 = grow + g + 8;

    const __nv_bfloat16* srcs[4] = {khi, klo, vhi, vlo};
    auto load_kv = [&](int t, int stage) {
        int n0 = t * 64;
        __nv_bfloat16* base = dsm + (size_t)stage * 4 * 64 * SPAD;
#pragma unroll
        for (int a = 0; a < 4; a++) {
#pragma unroll
            for (int i = 0; i < 2; i++) {
                int idx = tid + i * 256;
                int r = idx >> 3;
                int c8 = (idx & 7) * 8;
                cpa16(smem_u32(base + (size_t)(a * 64 + r) * SPAD + c8),
                      srcs[a] + (size_t)(n0 + r) * HD + c8);
            }
        }
    };

    int ntiles = mb * 2 + 2;
    load_kv(0, 0);
    CP_COMMIT;

    for (int t = 0; t < ntiles; t++) {
        int stage = t & 1;
        if (t + 1 < ntiles) {
            load_kv(t + 1, stage ^ 1);
            CP_COMMIT;
            CP_WAIT1;
        } else {
            CP_WAIT0;
        }
        __syncthreads();

        __nv_bfloat16* sb = dsm + (size_t)stage * 4 * 64 * SPAD;
        __nv_bfloat16* sKh = sb;
        __nv_bfloat16* sKl = sb + 64 * SPAD;
        __nv_bfloat16* sVh = sb + 2 * 64 * SPAD;
        __nv_bfloat16* sVl = sb + 3 * 64 * SPAD;
        int n0 = t * 64;

        float sacc[8][4];
#pragma unroll
        for (int nt = 0; nt < 8; nt++)
#pragma unroll
            for (int e = 0; e < 4; e++) sacc[nt][e] = 0.0f;

#pragma unroll
        for (int kt = 0; kt < 4; kt++) {
            uint32_t kb[8][2];
            {
                int rr = (lane & 7) + ((lane >> 4) << 3);
                int cc = kt * 16 + (((lane >> 3) & 1) << 3);
#pragma unroll
                for (int nb = 0; nb < 4; nb++) {
                    uint32_t t0, t1, t2, t3;
                    ldsm_x4(t0, t1, t2, t3,
                            smem_u32(sKh + (size_t)(nb * 16 + rr) * SPAD + cc));
                    kb[nb * 2 + 0][0] = t0; kb[nb * 2 + 0][1] = t1;
                    kb[nb * 2 + 1][0] = t2; kb[nb * 2 + 1][1] = t3;
                }
            }
#pragma unroll
            for (int nt = 0; nt < 8; nt++) {
                mma_bf16(sacc[nt], qha[kt], kb[nt]);
                mma_bf16(sacc[nt], qla[kt], kb[nt]);
            }
            {
                int rr = (lane & 7) + ((lane >> 4) << 3);
                int cc = kt * 16 + (((lane >> 3) & 1) << 3);
#pragma unroll
                for (int nb = 0; nb < 4; nb++) {
                    uint32_t t0, t1, t2, t3;
                    ldsm_x4(t0, t1, t2, t3,
                            smem_u32(sKl + (size_t)(nb * 16 + rr) * SPAD + cc));
                    kb[nb * 2 + 0][0] = t0; kb[nb * 2 + 0][1] = t1;
                    kb[nb * 2 + 1][0] = t2; kb[nb * 2 + 1][1] = t3;
                }
            }
#pragma unroll
            for (int nt = 0; nt < 8; nt++)
                mma_bf16(sacc[nt], qha[kt], kb[nt]);
        }

        float rm[2] = {-1e30f, -1e30f};
#pragma unroll
        for (int nt = 0; nt < 8; nt++) {
            int col = n0 + nt * 8 + tg * 2;
            if (col > row0) sacc[nt][0] = -1e30f;
            if (col + 1 > row0) sacc[nt][1] = -1e30f;
            if (col > row1) sacc[nt][2] = -1e30f;
            if (col + 1 > row1) sacc[nt][3] = -1e30f;
            rm[0] = fmaxf(rm[0], fmaxf(sacc[nt][0], sacc[nt][1]));
            rm[1] = fmaxf(rm[1], fmaxf(sacc[nt][2], sacc[nt][3]));
        }
#pragma unroll
        for (int o = 1; o <= 2; o <<= 1) {
            rm[0] = fmaxf(rm[0], __shfl_xor_sync(0xffffffffu, rm[0], o));
            rm[1] = fmaxf(rm[1], __shfl_xor_sync(0xffffffffu, rm[1], o));
        }
        float m_new0 = fmaxf(m_i[0], rm[0]);
        float m_new1 = fmaxf(m_i[1], rm[1]);
        float corr0 = __expf(m_i[0] - m_new0);
        float corr1 = __expf(m_i[1] - m_new1);
        float ls0 = 0.0f, ls1 = 0.0f;
#pragma unroll
        for (int nt = 0; nt < 8; nt++) {
            sacc[nt][0] = __expf(sacc[nt][0] - m_new0);
            sacc[nt][1] = __expf(sacc[nt][1] - m_new0);
            sacc[nt][2] = __expf(sacc[nt][2] - m_new1);
            sacc[nt][3] = __expf(sacc[nt][3] - m_new1);
            ls0 += sacc[nt][0] + sacc[nt][1];
            ls1 += sacc[nt][2] + sacc[nt][3];
        }
#pragma unroll
        for (int o = 1; o <= 2; o <<= 1) {
            ls0 += __shfl_xor_sync(0xffffffffu, ls0, o);
            ls1 += __shfl_xor_sync(0xffffffffu, ls1, o);
        }
        l_i[0] = l_i[0] * corr0 + ls0;
        l_i[1] = l_i[1] * corr1 + ls1;
        m_i[0] = m_new0; m_i[1] = m_new1;
#pragma unroll
        for (int nt = 0; nt < 8; nt++) {
            oacc[nt][0] *= corr0; oacc[nt][1] *= corr0;
            oacc[nt][2] *= corr1; oacc[nt][3] *= corr1;
        }

#pragma unroll
        for (int kt = 0; kt < 4; kt++) {
            uint32_t pha[4], pla[4];
#pragma unroll
            for (int half = 0; half < 2; half++) {
                const float* pp = sacc[kt * 2 + half];
                __nv_bfloat16 h0 = __float2bfloat16(pp[0]);
                __nv_bfloat16 h1 = __float2bfloat16(pp[1]);
                __nv_bfloat16 h2 = __float2bfloat16(pp[2]);
                __nv_bfloat16 h3 = __float2bfloat16(pp[3]);
                __nv_bfloat162 a01(h0, h1), a23(h2, h3);
                pha[half * 2 + 0] = *(uint32_t*)&a01;
                pha[half * 2 + 1] = *(uint32_t*)&a23;
                __nv_bfloat162 l01(__float2bfloat16(pp[0] - __bfloat162float(h0)),
                                   __float2bfloat16(pp[1] - __bfloat162float(h1)));
                __nv_bfloat162 l23(__float2bfloat16(pp[2] - __bfloat162float(h2)),
                                   __float2bfloat16(pp[3] - __bfloat162float(h3)));
                pla[half * 2 + 0] = *(uint32_t*)&l01;
                pla[half * 2 + 1] = *(uint32_t*)&l23;
            }
            uint32_t vb[8][2];
            {
                int rr = kt * 16 + (lane & 15);
                int c0 = (lane >> 4) * 8;
#pragma unroll
                for (int nb = 0; nb < 4; nb++) {
                    uint32_t t0, t1, t2, t3;
                    ldsm_x4_t(t0, t1, t2, t3,
                              smem_u32(sVh + (size_t)rr * SPAD + nb * 16 + c0));
                    vb[nb * 2 + 0][0] = t0; vb[nb * 2 + 0][1] = t1;
                    vb[nb * 2 + 1][0] = t2; vb[nb * 2 + 1][1] = t3;
                }
            }
#pragma unroll
            for (int nt = 0; nt < 8; nt++) {
                mma_bf16(oacc[nt], pha, vb[nt]);
                mma_bf16(oacc[nt], pla, vb[nt]);
            }
            {
                int rr = kt * 16 + (lane & 15);
                int c0 = (lane >> 4) * 8;
#pragma unroll
                for (int nb = 0; nb < 4; nb++) {
                    uint32_t t0, t1, t2, t3;
                    ldsm_x4_t(t0, t1, t2, t3,
                              smem_u32(sVl + (size_t)rr * SPAD + nb * 16 + c0));
                    vb[nb * 2 + 0][0] = t0; vb[nb * 2 + 0][1] = t1;
                    vb[nb * 2 + 1][0] = t2; vb[nb * 2 + 1][1] = t3;
                }
            }
#pragma unroll
            for (int nt = 0; nt < 8; nt++)
                mma_bf16(oacc[nt], pha, vb[nt]);
        }
        __syncthreads();
    }

    float inv0 = 1.0f / l_i[0];
    float inv1 = 1.0f / l_i[1];
#pragma unroll
    for (int nt = 0; nt < 8; nt++) {
        int col = h * HD + nt * 8 + tg * 2;
        size_t o0 = ((size_t)(b * S_LEN + row0)) * DM + col;
        size_t o1 = ((size_t)(b * S_LEN + row1)) * DM + col;
        float y00 = oacc[nt][0] * inv0, y01 = oacc[nt][1] * inv0;
        float y10 = oacc[nt][2] * inv1, y11 = oacc[nt][3] * inv1;
        __nv_bfloat16 h00 = __float2bfloat16(y00), h01 = __float2bfloat16(y01);
        __nv_bfloat16 h10 = __float2bfloat16(y10), h11 = __float2bfloat16(y11);
        *(__nv_bfloat162*)&g_aoh[o0] = __nv_bfloat162(h00, h01);
        *(__nv_bfloat162*)&g_aoh[o1] = __nv_bfloat162(h10, h11);
        *(__nv_bfloat162*)&g_aol[o0] = __nv_bfloat162(
            __float2bfloat16(y00 - __bfloat162float(h00)),
            __float2bfloat16(y01 - __bfloat162float(h01)));
        *(__nv_bfloat162*)&g_aol[o1] = __nv_bfloat162(
            __float2bfloat16(y10 - __bfloat162float(h10)),
            __float2bfloat16(y11 - __bfloat162float(h11)));
    }
}

// ---------------- launcher ----------------------------------------------------
extern "C" void kernel_launch(void* const* d_in, const int* in_sizes, int n_in,
                              void* d_out, int out_size) {
    const float* x   = (const float*)d_in[0];
    const float* Wq  = (const float*)d_in[1];
    const float* Wkv = (const float*)d_in[2];
    const float* Wo  = (const float*)d_in[3];
    const float* qs  = (const float*)d_in[4];
    const float* ks  = (const float*)d_in[5];
    float* out = (float*)d_out;

    float* pqkv;
    cudaGetSymbolAddress((void**)&pqkv, g_qkv_raw);

    __nv_bfloat16 *pxh, *pxl, *pw1h, *pw1l, *pwoh, *pwol, *paoh, *paol;
    cudaGetSymbolAddress((void**)&pxh, g_xh);
    cudaGetSymbolAddress((void**)&pxl, g_xl);
    cudaGetSymbolAddress((void**)&pw1h, g_w1h);
    cudaGetSymbolAddress((void**)&pw1l, g_w1l);
    cudaGetSymbolAddress((void**)&pwoh, g_woh);
    cudaGetSymbolAddress((void**)&pwol, g_wol);
    cudaGetSymbolAddress((void**)&paoh, g_aoh);
    cudaGetSymbolAddress((void**)&paol, g_aol);

    cudaFuncSetAttribute(attn_mma_kernel,
                         cudaFuncAttributeMaxDynamicSharedMemorySize, ATT_SMEM);

    int M = BATCH * S_LEN;  // 4096

    // 0) fused split-convert of X, [Wq|Wkv], Wo
    cvt_all<<<6656, 256>>>(x, Wq, Wkv, Wo);

    // 1) merged QKV projection (one GEMM, N=1536)
    gemm_bf16_3x<<<dim3(QKV_W / GBN, M / GBM), 128>>>(
        pxh, pxl, pw1h, pw1l, pqkv, M, QKV_W, DM);

    // 2) fused rmsnorm+rope (Q,K) + V rearrange
    postproc_kernel<<<11264, 256>>>(qs, ks);

    // 3) mma.sync causal GQA attention (2-stage pipelined K/V, 2 CTAs/SM)
    attn_mma_kernel<<<dim3(S_LEN / 128, NH, BATCH), 256, ATT_SMEM>>>();

    // 4) output projection
    gemm_bf16_3x<<<dim3(DM / GBN, M / GBM), 128>>>(paoh, paol, pwoh, pwol, out, M, DM, DM);
}

// round 10
// speedup vs baseline: 4.8687x; 1.1430x over previous
#include <cuda_runtime.h>
#include <cuda_bf16.h>
#include <cuda_fp16.h>
#include <math.h>
#include <stdint.h>

#define BATCH 2
#define S_LEN 2048
#define DM 1024
#define NH 16
#define NKV 4
#define HD 64
#define KV_W 512     // 2 * NKV * HD
#define QKV_W 1536   // DM + KV_W

// ---------------- scratch (device globals; no allocs allowed) ----------------
__device__ float g_qkv_raw[BATCH * S_LEN * QKV_W];  // X @ [Wq | Wkv]

// bf16 split buffers (projection GEMMs)
__device__ __nv_bfloat16 g_xh[BATCH * S_LEN * DM];
__device__ __nv_bfloat16 g_xl[BATCH * S_LEN * DM];
__device__ __nv_bfloat16 g_w1h[DM * QKV_W];   // [Wq | Wkv]  [K=DM][N=1536]
__device__ __nv_bfloat16 g_w1l[DM * QKV_W];
__device__ __nv_bfloat16 g_woh[DM * DM];
__device__ __nv_bfloat16 g_wol[DM * DM];
__device__ __nv_bfloat16 g_aoh[BATCH * S_LEN * DM];
__device__ __nv_bfloat16 g_aol[BATCH * S_LEN * DM];

// fp16 attention operands: Q split hi/lo; K, V single fp16
__device__ __half g_qh16[BATCH * NH * S_LEN * HD];
__device__ __half g_ql16[BATCH * NH * S_LEN * HD];
__device__ __half g_k16[BATCH * NKV * S_LEN * HD];
__device__ __half g_v16[BATCH * NKV * S_LEN * HD];

// ---------------- helpers ------------------------------------------------------
__device__ __forceinline__ uint32_t smem_u32(const void* p) {
    return (uint32_t)__cvta_generic_to_shared(p);
}
__device__ __forceinline__ void cpa16(uint32_t s, const void* g) {
    asm volatile("cp.async.cg.shared.global [%0], [%1], 16;" :: "r"(s), "l"(g));
}
#define CP_COMMIT asm volatile("cp.async.commit_group;")
#define CP_WAIT0  asm volatile("cp.async.wait_group 0;")
#define CP_WAIT1  asm volatile("cp.async.wait_group 1;")

__device__ __forceinline__ void ldsm_x4(uint32_t& r0, uint32_t& r1,
                                        uint32_t& r2, uint32_t& r3, uint32_t a) {
    asm volatile("ldmatrix.sync.aligned.m8n8.x4.shared.b16 {%0,%1,%2,%3},[%4];"
                 : "=r"(r0), "=r"(r1), "=r"(r2), "=r"(r3) : "r"(a));
}
__device__ __forceinline__ void ldsm_x4_t(uint32_t& r0, uint32_t& r1,
                                          uint32_t& r2, uint32_t& r3, uint32_t a) {
    asm volatile("ldmatrix.sync.aligned.m8n8.x4.trans.shared.b16 {%0,%1,%2,%3},[%4];"
                 : "=r"(r0), "=r"(r1), "=r"(r2), "=r"(r3) : "r"(a));
}
__device__ __forceinline__ void mma_bf16(float* c, const uint32_t* a,
                                         const uint32_t* b) {
    asm volatile(
        "mma.sync.aligned.m16n8k16.row.col.f32.bf16.bf16.f32 "
        "{%0,%1,%2,%3},{%4,%5,%6,%7},{%8,%9},{%0,%1,%2,%3};"
        : "+f"(c[0]), "+f"(c[1]), "+f"(c[2]), "+f"(c[3])
        : "r"(a[0]), "r"(a[1]), "r"(a[2]), "r"(a[3]), "r"(b[0]), "r"(b[1]));
}
__device__ __forceinline__ void mma_f16(float* c, const uint32_t* a,
                                        const uint32_t* b) {
    asm volatile(
        "mma.sync.aligned.m16n8k16.row.col.f32.f16.f16.f32 "
        "{%0,%1,%2,%3},{%4,%5,%6,%7},{%8,%9},{%0,%1,%2,%3};"
        : "+f"(c[0]), "+f"(c[1]), "+f"(c[2]), "+f"(c[3])
        : "r"(a[0]), "r"(a[1]), "r"(a[2]), "r"(a[3]), "r"(b[0]), "r"(b[1]));
}

// ---------------- fused fp32 -> (hi,lo) bf16 split for all 4 tensors ----------
__device__ __forceinline__ void split_write(float4 v, __nv_bfloat16* hi,
                                            __nv_bfloat16* lo, size_t o) {
    __nv_bfloat16 h0 = __float2bfloat16(v.x);
    __nv_bfloat16 h1 = __float2bfloat16(v.y);
    __nv_bfloat16 h2 = __float2bfloat16(v.z);
    __nv_bfloat16 h3 = __float2bfloat16(v.w);
    *(__nv_bfloat162*)(hi + o) = __nv_bfloat162(h0, h1);
    *(__nv_bfloat162*)(hi + o + 2) = __nv_bfloat162(h2, h3);
    *(__nv_bfloat162*)(lo + o) = __nv_bfloat162(
        __float2bfloat16(v.x - __bfloat162float(h0)),
        __float2bfloat16(v.y - __bfloat162float(h1)));
    *(__nv_bfloat162*)(lo + o + 2) = __nv_bfloat162(
        __float2bfloat16(v.z - __bfloat162float(h2)),
        __float2bfloat16(v.w - __bfloat162float(h3)));
}

// regions: [0,4096) X ; [4096,5120) Wq->w1 col0=0 ; [5120,5632) Wkv->w1 col0=DM ;
//          [5632,6656) Wo
__global__ void cvt_all(const float* __restrict__ x, const float* __restrict__ Wq,
                        const float* __restrict__ Wkv, const float* __restrict__ Wo) {
    int bx = blockIdx.x;
    int tid = threadIdx.x;
    if (bx < 4096) {
        int i = bx * 256 + tid;
        float4 v = *(const float4*)(x + (size_t)i * 4);
        split_write(v, g_xh, g_xl, (size_t)i * 4);
    } else if (bx < 5120) {
        int i = (bx - 4096) * 256 + tid;
        int r = (i * 4) / DM, c = (i * 4) % DM;
        float4 v = *(const float4*)(Wq + (size_t)r * DM + c);
        split_write(v, g_w1h, g_w1l, (size_t)r * QKV_W + c);
    } else if (bx < 5632) {
        int i = (bx - 5120) * 256 + tid;
        int r = (i * 4) / KV_W, c = (i * 4) % KV_W;
        float4 v = *(const float4*)(Wkv + (size_t)r * KV_W + c);
        split_write(v, g_w1h, g_w1l, (size_t)r * QKV_W + DM + c);
    } else {
        int i = (bx - 5632) * 256 + tid;
        float4 v = *(const float4*)(Wo + (size_t)i * 4);
        split_write(v, g_woh, g_wol, (size_t)i * 4);
    }
}

// ---------------- 3x bf16-split mma GEMM, 64x64 warp tiles, 2 CTAs/SM ---------
#define GBM 128
#define GBN 128
#define GBK 32

__global__ __launch_bounds__(128, 2) void gemm_bf16_3x(
    const __nv_bfloat16* __restrict__ Ah, const __nv_bfloat16* __restrict__ Al,
    const __nv_bfloat16* __restrict__ Bh, const __nv_bfloat16* __restrict__ Bl,
    float* __restrict__ C, int M, int N, int K) {
    __shared__ __align__(16) __nv_bfloat16 As[2][GBM][GBK + 8];
    __shared__ __align__(16) __nv_bfloat16 Bs[2][GBK][GBN + 8];

    int tid = threadIdx.x;
    int wid = tid >> 5, lane = tid & 31;
    int bm = blockIdx.y * GBM, bn = blockIdx.x * GBN;
    int wm = (wid & 1) * 64;
    int wn = (wid >> 1) * 64;

    int T = 3 * K / GBK;

    auto prefetch = [&](int t, int buf) {
        int kk = t * GBK;
        int seg = kk / K;
        int kl = kk - seg * K;
        const __nv_bfloat16* Aseg = (seg < 2) ? Ah : Al;
        const __nv_bfloat16* Bseg = (seg == 1) ? Bl : Bh;
#pragma unroll
        for (int i = 0; i < 4; i++) {
            int idx = tid + i * 128;
            int ar = idx >> 2, ac = (idx & 3) * 8;
            cpa16(smem_u32(&As[buf][ar][ac]), Aseg + (size_t)(bm + ar) * K + kl + ac);
            int br = idx >> 4, bc = (idx & 15) * 8;
            cpa16(smem_u32(&Bs[buf][br][bc]), Bseg + (size_t)(kl + br) * N + bn + bc);
        }
    };

    float acc[4][8][4];
#pragma unroll
    for (int i = 0; i < 4; i++)
#pragma unroll
        for (int j = 0; j < 8; j++)
#pragma unroll
            for (int e = 0; e < 4; e++) acc[i][j][e] = 0.0f;

    prefetch(0, 0);
    CP_COMMIT;

    for (int t = 0; t < T; t++) {
        int buf = t & 1;
        CP_WAIT0;
        __syncthreads();
        if (t + 1 < T) {
            prefetch(t + 1, buf ^ 1);
            CP_COMMIT;
        }

#pragma unroll
        for (int k0 = 0; k0 < GBK; k0 += 16) {
            uint32_t a[4][4];
#pragma unroll
            for (int mt = 0; mt < 4; mt++) {
                int row = wm + mt * 16 + (lane & 15);
                int col = k0 + (lane >> 4) * 8;
                ldsm_x4(a[mt][0], a[mt][1], a[mt][2], a[mt][3],
                        smem_u32(&As[buf][row][col]));
            }
            uint32_t b[8][2];
#pragma unroll
            for (int np = 0; np < 4; np++) {
                int r = k0 + (lane & 15);
                int col = wn + np * 16 + (lane >> 4) * 8;
                uint32_t t0, t1, t2, t3;
                ldsm_x4_t(t0, t1, t2, t3, smem_u32(&Bs[buf][r][col]));
                b[np * 2 + 0][0] = t0; b[np * 2 + 0][1] = t1;
                b[np * 2 + 1][0] = t2; b[np * 2 + 1][1] = t3;
            }
#pragma unroll
            for (int mt = 0; mt < 4; mt++)
#pragma unroll
                for (int nt = 0; nt < 8; nt++)
                    mma_bf16(acc[mt][nt], a[mt], b[nt]);
        }
    }

    int g = lane >> 2, tg = lane & 3;
#pragma unroll
    for (int mt = 0; mt < 4; mt++) {
#pragma unroll
        for (int nt = 0; nt < 8; nt++) {
            int row = bm + wm + mt * 16 + g;
            int col = bn + wn + nt * 8 + tg * 2;
            *(float2*)&C[(size_t)row * N + col] =
                make_float2(acc[mt][nt][0], acc[mt][nt][1]);
            *(float2*)&C[(size_t)(row + 8) * N + col] =
                make_float2(acc[mt][nt][2], acc[mt][nt][3]);
        }
    }
}

// ---------------- fused RMSNorm+RoPE (Q,K) + V rearrange -----------------------
__device__ const double c_inv8[8] = {
    1.0, 0.74989420933245582, 0.56234132519034912, 0.42169650342858224,
    0.31622776601683794, 0.23713737056616552, 0.17782794100389229,
    0.13335214321633241};
__device__ const double c_p10[4] = {1.0, 0.1, 0.01, 0.001};

// Q: writes fp16 hi + lo split.  K: writes single fp16 (olo == nullptr).
__device__ __forceinline__ void normrope_row(
    int gw, int lane, __half* __restrict__ ohi, __half* __restrict__ olo,
    const float* __restrict__ scale, int nheads, int col0, float post) {
    int h = gw % nheads;
    int s = (gw / nheads) % S_LEN;
    int b = gw / (nheads * S_LEN);

    const float* ip = g_qkv_raw + ((size_t)(b * S_LEN + s)) * QKV_W + col0 + h * HD;
    float x1 = ip[lane];
    float x2 = ip[lane + 32];
    float ss = x1 * x1 + x2 * x2;
#pragma unroll
    for (int o = 16; o; o >>= 1) ss += __shfl_xor_sync(0xffffffffu, ss, o);
    float inv = rsqrtf(ss * (1.0f / 64.0f) + 1e-5f);
    x1 *= inv * scale[lane];
    x2 *= inv * scale[lane + 32];

    float invf = (float)(c_inv8[lane & 7] * c_p10[lane >> 3]);
    float f = (float)s * invf;
    float c, sn;
    sincosf(f, &sn, &c);   // sincosf(x, SIN*, COS*)

    float y1 = (x1 * c - x2 * sn) * post;
    float y2 = (x1 * sn + x2 * c) * post;

    size_t base = (((size_t)(b * nheads + h)) * S_LEN + s) * HD;
    __half h1 = __float2half_rn(y1);
    __half h2 = __float2half_rn(y2);
    ohi[base + lane] = h1;
    ohi[base + lane + 32] = h2;
    if (olo) {
        olo[base + lane] = __float2half_rn(y1 - __half2float(h1));
        olo[base + lane + 32] = __float2half_rn(y2 - __half2float(h2));
    }
}

// blocks: [0,8192) Q ; [8192,10240) K ; [10240,11264) V copy
__global__ void postproc_kernel(const float* __restrict__ qs,
                                const float* __restrict__ ks) {
    int bx = blockIdx.x;
    int tid = threadIdx.x;
    int wid = tid >> 5, lane = tid & 31;
    if (bx < 8192) {
        normrope_row(bx * 8 + wid, lane, g_qh16, g_ql16, qs, NH, 0, 0.125f);
    } else if (bx < 10240) {
        normrope_row((bx - 8192) * 8 + wid, lane, g_k16, nullptr, ks, NKV, DM, 1.0f);
    } else {
        int idx = (bx - 10240) * 256 + tid;   // float4 index
        int c4 = idx & 15;
        int tmp = idx >> 4;
        int s = tmp % S_LEN;
        int bk = tmp / S_LEN;
        int kvh = bk % NKV;
        int b = bk / NKV;
        float4 v = *(const float4*)(g_qkv_raw + ((size_t)(b * S_LEN + s)) * QKV_W +
                                    (DM + NKV * HD) + kvh * HD + c4 * 4);
        size_t o = ((size_t)bk * S_LEN + s) * HD + c4 * 4;
        *(__half2*)(g_v16 + o) = __halves2half2(__float2half_rn(v.x), __float2half_rn(v.y));
        *(__half2*)(g_v16 + o + 2) = __halves2half2(__float2half_rn(v.z), __float2half_rn(v.w));
    }
}

// ---------------- fp16 mma.sync causal GQA flash attention ---------------------
// S = (Qh + Ql) @ K^T  (Q exact via 2-term fp16 split; K single fp16)
// O += (Ph + Pl) @ V   (P exact via split; V single fp16)
#define SPAD 72   // 64 + 8
#define ATT_SMEM (2 * 2 * 64 * SPAD * 2)   // 36864 bytes (== Q staging size)

__global__ __launch_bounds__(256, 2) void attn_mma_kernel() {
    extern __shared__ __align__(16) __half dsm[];

    int b = blockIdx.z, h = blockIdx.y;
    int mb = (int)(gridDim.x - 1) - (int)blockIdx.x;  // heavy CTAs first
    int kvh = h >> 2;
    int tid = threadIdx.x;
    int wid = tid >> 5, lane = tid & 31;
    int g = lane >> 2, tg = lane & 3;

    const __half* qhi = g_qh16 + (((size_t)(b * NH + h)) * S_LEN + mb * 128) * HD;
    const __half* qlo = g_ql16 + (((size_t)(b * NH + h)) * S_LEN + mb * 128) * HD;
    const __half* kp = g_k16 + ((size_t)(b * NKV + kvh)) * S_LEN * HD;
    const __half* vp = g_v16 + ((size_t)(b * NKV + kvh)) * S_LEN * HD;

    // ---- stage Q tile [128][64] hi+lo through smem, grab a-frags ----
    __half* qs = dsm;   // [256][SPAD]
#pragma unroll
    for (int i = 0; i < 4; i++) {
        int idx = tid + i * 256;
        int r = idx >> 3;
        int c8 = (idx & 7) * 8;
        cpa16(smem_u32(qs + (size_t)r * SPAD + c8), qhi + (size_t)r * HD + c8);
        cpa16(smem_u32(qs + (size_t)(r + 128) * SPAD + c8), qlo + (size_t)r * HD + c8);
    }
    CP_COMMIT; CP_WAIT0;
    __syncthreads();

    uint32_t qha[4][4], qla[4][4];
    {
        int row = wid * 16 + (lane & 15);
#pragma unroll
        for (int kt = 0; kt < 4; kt++) {
            int col = kt * 16 + (lane >> 4) * 8;
            ldsm_x4(qha[kt][0], qha[kt][1], qha[kt][2], qha[kt][3],
                    smem_u32(qs + (size_t)row * SPAD + col));
            ldsm_x4(qla[kt][0], qla[kt][1], qla[kt][2], qla[kt][3],
                    smem_u32(qs + (size_t)(row + 128) * SPAD + col));
        }
    }
    __syncthreads();

    float oacc[8][4];
#pragma unroll
    for (int nt = 0; nt < 8; nt++)
#pragma unroll
        for (int e = 0; e < 4; e++) oacc[nt][e] = 0.0f;
    float m_i[2] = {-1e30f, -1e30f};
    float l_i[2] = {0.0f, 0.0f};

    int grow = mb * 128 + wid * 16;
    int row0 = grow + g, row1 = grow + g + 8;

    auto load_kv = [&](int t, int stage) {
        int n0 = t * 64;
        __half* base = dsm + (size_t)stage * 2 * 64 * SPAD;
#pragma unroll
        for (int i = 0; i < 2; i++) {
            int idx = tid + i * 256;      // 0..511
            int r = idx >> 3;             // 0..63
            int c8 = (idx & 7) * 8;
            cpa16(smem_u32(base + (size_t)r * SPAD + c8),
                  kp + (size_t)(n0 + r) * HD + c8);
            cpa16(smem_u32(base + (size_t)(64 + r) * SPAD + c8),
                  vp + (size_t)(n0 + r) * HD + c8);
        }
    };

    int ntiles = mb * 2 + 2;
    load_kv(0, 0);
    CP_COMMIT;

    for (int t = 0; t < ntiles; t++) {
        int stage = t & 1;
        if (t + 1 < ntiles) {
            load_kv(t + 1, stage ^ 1);
            CP_COMMIT;
            CP_WAIT1;
        } else {
            CP_WAIT0;
        }
        __syncthreads();

        __half* sK = dsm + (size_t)stage * 2 * 64 * SPAD;
        __half* sV = sK + 64 * SPAD;
        int n0 = t * 64;

        // ---- S = Q K^T (Q split, K single) ----
        float sacc[8][4];
#pragma unroll
        for (int nt = 0; nt < 8; nt++)
#pragma unroll
            for (int e = 0; e < 4; e++) sacc[nt][e] = 0.0f;

#pragma unroll
        for (int kt = 0; kt < 4; kt++) {
            uint32_t kb[8][2];
            {
                int rr = (lane & 7) + ((lane >> 4) << 3);
                int cc = kt * 16 + (((lane >> 3) & 1) << 3);
#pragma unroll
                for (int nb = 0; nb < 4; nb++) {
                    uint32_t t0, t1, t2, t3;
                    ldsm_x4(t0, t1, t2, t3,
                            smem_u32(sK + (size_t)(nb * 16 + rr) * SPAD + cc));
                    kb[nb * 2 + 0][0] = t0; kb[nb * 2 + 0][1] = t1;
                    kb[nb * 2 + 1][0] = t2; kb[nb * 2 + 1][1] = t3;
                }
            }
#pragma unroll
            for (int nt = 0; nt < 8; nt++) {
                mma_f16(sacc[nt], qha[kt], kb[nt]);
                mma_f16(sacc[nt], qla[kt], kb[nt]);
            }
        }

        // ---- causal mask + online softmax ----
        float rm[2] = {-1e30f, -1e30f};
#pragma unroll
        for (int nt = 0; nt < 8; nt++) {
            int col = n0 + nt * 8 + tg * 2;
            if (col > row0) sacc[nt][0] = -1e30f;
            if (col + 1 > row0) sacc[nt][1] = -1e30f;
            if (col > row1) sacc[nt][2] = -1e30f;
            if (col + 1 > row1) sacc[nt][3] = -1e30f;
            rm[0] = fmaxf(rm[0], fmaxf(sacc[nt][0], sacc[nt][1]));
            rm[1] = fmaxf(rm[1], fmaxf(sacc[nt][2], sacc[nt][3]));
        }
#pragma unroll
        for (int o = 1; o <= 2; o <<= 1) {
            rm[0] = fmaxf(rm[0], __shfl_xor_sync(0xffffffffu, rm[0], o));
            rm[1] = fmaxf(rm[1], __shfl_xor_sync(0xffffffffu, rm[1], o));
        }
        float m_new0 = fmaxf(m_i[0], rm[0]);
        float m_new1 = fmaxf(m_i[1], rm[1]);
        float corr0 = __expf(m_i[0] - m_new0);
        float corr1 = __expf(m_i[1] - m_new1);
        float ls0 = 0.0f, ls1 = 0.0f;
#pragma unroll
        for (int nt = 0; nt < 8; nt++) {
            sacc[nt][0] = __expf(sacc[nt][0] - m_new0);
            sacc[nt][1] = __expf(sacc[nt][1] - m_new0);
            sacc[nt][2] = __expf(sacc[nt][2] - m_new1);
            sacc[nt][3] = __expf(sacc[nt][3] - m_new1);
            ls0 += sacc[nt][0] + sacc[nt][1];
            ls1 += sacc[nt][2] + sacc[nt][3];
        }
#pragma unroll
        for (int o = 1; o <= 2; o <<= 1) {
            ls0 += __shfl_xor_sync(0xffffffffu, ls0, o);
            ls1 += __shfl_xor_sync(0xffffffffu, ls1, o);
        }
        l_i[0] = l_i[0] * corr0 + ls0;
        l_i[1] = l_i[1] * corr1 + ls1;
        m_i[0] = m_new0; m_i[1] = m_new1;
#pragma unroll
        for (int nt = 0; nt < 8; nt++) {
            oacc[nt][0] *= corr0; oacc[nt][1] *= corr0;
            oacc[nt][2] *= corr1; oacc[nt][3] *= corr1;
        }

        // ---- O += P V (P split, V single) ----
#pragma unroll
        for (int kt = 0; kt < 4; kt++) {
            uint32_t pha[4], pla[4];
#pragma unroll
            for (int half = 0; half < 2; half++) {
                const float* pp = sacc[kt * 2 + half];
                __half h0 = __float2half_rn(pp[0]);
                __half h1 = __float2half_rn(pp[1]);
                __half h2 = __float2half_rn(pp[2]);
                __half h3 = __float2half_rn(pp[3]);
                __half2 a01 = __halves2half2(h0, h1);
                __half2 a23 = __halves2half2(h2, h3);
                pha[half * 2 + 0] = *(uint32_t*)&a01;
                pha[half * 2 + 1] = *(uint32_t*)&a23;
                __half2 l01 = __halves2half2(
                    __float2half_rn(pp[0] - __half2float(h0)),
                    __float2half_rn(pp[1] - __half2float(h1)));
                __half2 l23 = __halves2half2(
                    __float2half_rn(pp[2] - __half2float(h2)),
                    __float2half_rn(pp[3] - __half2float(h3)));
                pla[half * 2 + 0] = *(uint32_t*)&l01;
                pla[half * 2 + 1] = *(uint32_t*)&l23;
            }
            uint32_t vb[8][2];
            {
                int rr = kt * 16 + (lane & 15);
                int c0 = (lane >> 4) * 8;
#pragma unroll
                for (int nb = 0; nb < 4; nb++) {
                    uint32_t t0, t1, t2, t3;
                    ldsm_x4_t(t0, t1, t2, t3,
                              smem_u32(sV + (size_t)rr * SPAD + nb * 16 + c0));
                    vb[nb * 2 + 0][0] = t0; vb[nb * 2 + 0][1] = t1;
                    vb[nb * 2 + 1][0] = t2; vb[nb * 2 + 1][1] = t3;
                }
            }
#pragma unroll
            for (int nt = 0; nt < 8; nt++) {
                mma_f16(oacc[nt], pha, vb[nt]);
                mma_f16(oacc[nt], pla, vb[nt]);
            }
        }
        __syncthreads();
    }

    // ---- epilogue: write bf16 hi/lo splits for the Wo GEMM ----
    float inv0 = 1.0f / l_i[0];
    float inv1 = 1.0f / l_i[1];
#pragma unroll
    for (int nt = 0; nt < 8; nt++) {
        int col = h * HD + nt * 8 + tg * 2;
        size_t o0 = ((size_t)(b * S_LEN + row0)) * DM + col;
        size_t o1 = ((size_t)(b * S_LEN + row1)) * DM + col;
        float y00 = oacc[nt][0] * inv0, y01 = oacc[nt][1] * inv0;
        float y10 = oacc[nt][2] * inv1, y11 = oacc[nt][3] * inv1;
        __nv_bfloat16 h00 = __float2bfloat16(y00), h01 = __float2bfloat16(y01);
        __nv_bfloat16 h10 = __float2bfloat16(y10), h11 = __float2bfloat16(y11);
        *(__nv_bfloat162*)&g_aoh[o0] = __nv_bfloat162(h00, h01);
        *(__nv_bfloat162*)&g_aoh[o1] = __nv_bfloat162(h10, h11);
        *(__nv_bfloat162*)&g_aol[o0] = __nv_bfloat162(
            __float2bfloat16(y00 - __bfloat162float(h00)),
            __float2bfloat16(y01 - __bfloat162float(h01)));
        *(__nv_bfloat162*)&g_aol[o1] = __nv_bfloat162(
            __float2bfloat16(y10 - __bfloat162float(h10)),
            __float2bfloat16(y11 - __bfloat162float(h11)));
    }
}

// ---------------- launcher ----------------------------------------------------
extern "C" void kernel_launch(void* const* d_in, const int* in_sizes, int n_in,
                              void* d_out, int out_size) {
    const float* x   = (const float*)d_in[0];
    const float* Wq  = (const float*)d_in[1];
    const float* Wkv = (const float*)d_in[2];
    const float* Wo  = (const float*)d_in[3];
    const float* qs  = (const float*)d_in[4];
    const float* ks  = (const float*)d_in[5];
    float* out = (float*)d_out;

    float* pqkv;
    cudaGetSymbolAddress((void**)&pqkv, g_qkv_raw);

    __nv_bfloat16 *pxh, *pxl, *pw1h, *pw1l, *pwoh, *pwol, *paoh, *paol;
    cudaGetSymbolAddress((void**)&pxh, g_xh);
    cudaGetSymbolAddress((void**)&pxl, g_xl);
    cudaGetSymbolAddress((void**)&pw1h, g_w1h);
    cudaGetSymbolAddress((void**)&pw1l, g_w1l);
    cudaGetSymbolAddress((void**)&pwoh, g_woh);
    cudaGetSymbolAddress((void**)&pwol, g_wol);
    cudaGetSymbolAddress((void**)&paoh, g_aoh);
    cudaGetSymbolAddress((void**)&paol, g_aol);

    cudaFuncSetAttribute(attn_mma_kernel,
                         cudaFuncAttributeMaxDynamicSharedMemorySize, ATT_SMEM);

    int M = BATCH * S_LEN;  // 4096

    // 0) fused split-convert of X, [Wq|Wkv], Wo
    cvt_all<<<6656, 256>>>(x, Wq, Wkv, Wo);

    // 1) merged QKV projection (one GEMM, N=1536, bf16 3-term)
    gemm_bf16_3x<<<dim3(QKV_W / GBN, M / GBM), 128>>>(
        pxh, pxl, pw1h, pw1l, pqkv, M, QKV_W, DM);

    // 2) fused rmsnorm+rope (Q split fp16, K single fp16) + V fp16 rearrange
    postproc_kernel<<<11264, 256>>>(qs, ks);

    // 3) fp16 mma causal GQA attention (2-stage pipelined K/V, 2 CTAs/SM)
    attn_mma_kernel<<<dim3(S_LEN / 128, NH, BATCH), 256, ATT_SMEM>>>();

    // 4) output projection (bf16 3-term)
    gemm_bf16_3x<<<dim3(DM / GBN, M / GBM), 128>>>(paoh, paol, pwoh, pwol, out, M, DM, DM);
}

// round 11
// speedup vs baseline: 6.3120x; 1.2965x over previous
#include <cuda_runtime.h>
#include <cuda_bf16.h>
#include <cuda_fp16.h>
#include <math.h>
#include <stdint.h>

#define BATCH 2
#define S_LEN 2048
#define DM 1024
#define NH 16
#define NKV 4
#define HD 64
#define KV_W 512     // 2 * NKV * HD
#define QKV_W 1536   // DM + KV_W

// ---------------- scratch (device globals; no allocs allowed) ----------------
__device__ float g_qkv_raw[BATCH * S_LEN * QKV_W];  // X @ [Wq | Wkv]

// fp16 buffers: A-side split hi/lo (exact), weights single fp16
__device__ __half g_xh16[BATCH * S_LEN * DM];
__device__ __half g_xl16[BATCH * S_LEN * DM];
__device__ __half g_w116[DM * QKV_W];   // [Wq | Wkv] single fp16
__device__ __half g_wo16[DM * DM];      // Wo single fp16
__device__ __half g_aoh16[BATCH * S_LEN * DM];
__device__ __half g_aol16[BATCH * S_LEN * DM];

// fp16 attention operands: Q split hi/lo; K, V single fp16
__device__ __half g_qh16[BATCH * NH * S_LEN * HD];
__device__ __half g_ql16[BATCH * NH * S_LEN * HD];
__device__ __half g_k16[BATCH * NKV * S_LEN * HD];
__device__ __half g_v16[BATCH * NKV * S_LEN * HD];

// ---------------- helpers ------------------------------------------------------
__device__ __forceinline__ uint32_t smem_u32(const void* p) {
    return (uint32_t)__cvta_generic_to_shared(p);
}
__device__ __forceinline__ void cpa16(uint32_t s, const void* g) {
    asm volatile("cp.async.cg.shared.global [%0], [%1], 16;" :: "r"(s), "l"(g));
}
#define CP_COMMIT asm volatile("cp.async.commit_group;")
#define CP_WAIT0  asm volatile("cp.async.wait_group 0;")
#define CP_WAIT1  asm volatile("cp.async.wait_group 1;")

__device__ __forceinline__ void ldsm_x4(uint32_t& r0, uint32_t& r1,
                                        uint32_t& r2, uint32_t& r3, uint32_t a) {
    asm volatile("ldmatrix.sync.aligned.m8n8.x4.shared.b16 {%0,%1,%2,%3},[%4];"
                 : "=r"(r0), "=r"(r1), "=r"(r2), "=r"(r3) : "r"(a));
}
__device__ __forceinline__ void ldsm_x4_t(uint32_t& r0, uint32_t& r1,
                                          uint32_t& r2, uint32_t& r3, uint32_t a) {
    asm volatile("ldmatrix.sync.aligned.m8n8.x4.trans.shared.b16 {%0,%1,%2,%3},[%4];"
                 : "=r"(r0), "=r"(r1), "=r"(r2), "=r"(r3) : "r"(a));
}
__device__ __forceinline__ void mma_f16(float* c, const uint32_t* a,
                                        const uint32_t* b) {
    asm volatile(
        "mma.sync.aligned.m16n8k16.row.col.f32.f16.f16.f32 "
        "{%0,%1,%2,%3},{%4,%5,%6,%7},{%8,%9},{%0,%1,%2,%3};"
        : "+f"(c[0]), "+f"(c[1]), "+f"(c[2]), "+f"(c[3])
        : "r"(a[0]), "r"(a[1]), "r"(a[2]), "r"(a[3]), "r"(b[0]), "r"(b[1]));
}

// ---------------- fused converts -----------------------------------------------
__device__ __forceinline__ void split_write_h(float4 v, __half* hi, __half* lo,
                                              size_t o) {
    __half h0 = __float2half_rn(v.x);
    __half h1 = __float2half_rn(v.y);
    __half h2 = __float2half_rn(v.z);
    __half h3 = __float2half_rn(v.w);
    *(__half2*)(hi + o) = __halves2half2(h0, h1);
    *(__half2*)(hi + o + 2) = __halves2half2(h2, h3);
    *(__half2*)(lo + o) = __halves2half2(
        __float2half_rn(v.x - __half2float(h0)),
        __float2half_rn(v.y - __half2float(h1)));
    *(__half2*)(lo + o + 2) = __halves2half2(
        __float2half_rn(v.z - __half2float(h2)),
        __float2half_rn(v.w - __half2float(h3)));
}
__device__ __forceinline__ void cvt_write_h(float4 v, __half* dst, size_t o) {
    *(__half2*)(dst + o) = __halves2half2(__float2half_rn(v.x), __float2half_rn(v.y));
    *(__half2*)(dst + o + 2) = __halves2half2(__float2half_rn(v.z), __float2half_rn(v.w));
}

// regions: [0,4096) X split ; [4096,5120) Wq->w1 ; [5120,5632) Wkv->w1 ; [5632,6656) Wo
__global__ void cvt_all(const float* __restrict__ x, const float* __restrict__ Wq,
                        const float* __restrict__ Wkv, const float* __restrict__ Wo) {
    int bx = blockIdx.x;
    int tid = threadIdx.x;
    if (bx < 4096) {
        int i = bx * 256 + tid;
        float4 v = *(const float4*)(x + (size_t)i * 4);
        split_write_h(v, g_xh16, g_xl16, (size_t)i * 4);
    } else if (bx < 5120) {
        int i = (bx - 4096) * 256 + tid;
        int r = (i * 4) / DM, c = (i * 4) % DM;
        float4 v = *(const float4*)(Wq + (size_t)r * DM + c);
        cvt_write_h(v, g_w116, (size_t)r * QKV_W + c);
    } else if (bx < 5632) {
        int i = (bx - 5120) * 256 + tid;
        int r = (i * 4) / KV_W, c = (i * 4) % KV_W;
        float4 v = *(const float4*)(Wkv + (size_t)r * KV_W + c);
        cvt_write_h(v, g_w116, (size_t)r * QKV_W + DM + c);
    } else {
        int i = (bx - 5632) * 256 + tid;
        float4 v = *(const float4*)(Wo + (size_t)i * 4);
        cvt_write_h(v, g_wo16, (size_t)i * 4);
    }
}

// ---------------- 2x fp16-split mma GEMM (A split, B single), 64x64 warp tiles --
#define GBM 128
#define GBN 128
#define GBK 32

__global__ __launch_bounds__(128, 2) void gemm_f16_2x(
    const __half* __restrict__ Ah, const __half* __restrict__ Al,
    const __half* __restrict__ B, float* __restrict__ C, int M, int N, int K) {
    __shared__ __align__(16) __half As[2][GBM][GBK + 8];
    __shared__ __align__(16) __half Bs[2][GBK][GBN + 8];

    int tid = threadIdx.x;
    int wid = tid >> 5, lane = tid & 31;
    int bm = blockIdx.y * GBM, bn = blockIdx.x * GBN;
    int wm = (wid & 1) * 64;
    int wn = (wid >> 1) * 64;

    int T = 2 * K / GBK;

    auto prefetch = [&](int t, int buf) {
        int kk = t * GBK;
        int seg = kk / K;
        int kl = kk - seg * K;
        const __half* Aseg = seg ? Al : Ah;
#pragma unroll
        for (int i = 0; i < 4; i++) {
            int idx = tid + i * 128;
            int ar = idx >> 2, ac = (idx & 3) * 8;
            cpa16(smem_u32(&As[buf][ar][ac]), Aseg + (size_t)(bm + ar) * K + kl + ac);
            int br = idx >> 4, bc = (idx & 15) * 8;
            cpa16(smem_u32(&Bs[buf][br][bc]), B + (size_t)(kl + br) * N + bn + bc);
        }
    };

    float acc[4][8][4];
#pragma unroll
    for (int i = 0; i < 4; i++)
#pragma unroll
        for (int j = 0; j < 8; j++)
#pragma unroll
            for (int e = 0; e < 4; e++) acc[i][j][e] = 0.0f;

    prefetch(0, 0);
    CP_COMMIT;

    for (int t = 0; t < T; t++) {
        int buf = t & 1;
        CP_WAIT0;
        __syncthreads();
        if (t + 1 < T) {
            prefetch(t + 1, buf ^ 1);
            CP_COMMIT;
        }

#pragma unroll
        for (int k0 = 0; k0 < GBK; k0 += 16) {
            uint32_t a[4][4];
#pragma unroll
            for (int mt = 0; mt < 4; mt++) {
                int row = wm + mt * 16 + (lane & 15);
                int col = k0 + (lane >> 4) * 8;
                ldsm_x4(a[mt][0], a[mt][1], a[mt][2], a[mt][3],
                        smem_u32(&As[buf][row][col]));
            }
            uint32_t b[8][2];
#pragma unroll
            for (int np = 0; np < 4; np++) {
                int r = k0 + (lane & 15);
                int col = wn + np * 16 + (lane >> 4) * 8;
                uint32_t t0, t1, t2, t3;
                ldsm_x4_t(t0, t1, t2, t3, smem_u32(&Bs[buf][r][col]));
                b[np * 2 + 0][0] = t0; b[np * 2 + 0][1] = t1;
                b[np * 2 + 1][0] = t2; b[np * 2 + 1][1] = t3;
            }
#pragma unroll
            for (int mt = 0; mt < 4; mt++)
#pragma unroll
                for (int nt = 0; nt < 8; nt++)
                    mma_f16(acc[mt][nt], a[mt], b[nt]);
        }
    }

    int g = lane >> 2, tg = lane & 3;
#pragma unroll
    for (int mt = 0; mt < 4; mt++) {
#pragma unroll
        for (int nt = 0; nt < 8; nt++) {
            int row = bm + wm + mt * 16 + g;
            int col = bn + wn + nt * 8 + tg * 2;
            *(float2*)&C[(size_t)row * N + col] =
                make_float2(acc[mt][nt][0], acc[mt][nt][1]);
            *(float2*)&C[(size_t)(row + 8) * N + col] =
                make_float2(acc[mt][nt][2], acc[mt][nt][3]);
        }
    }
}

// ---------------- fused RMSNorm+RoPE (Q,K) + V rearrange -----------------------
__device__ const double c_inv8[8] = {
    1.0, 0.74989420933245582, 0.56234132519034912, 0.42169650342858224,
    0.31622776601683794, 0.23713737056616552, 0.17782794100389229,
    0.13335214321633241};
__device__ const double c_p10[4] = {1.0, 0.1, 0.01, 0.001};

// Q: writes fp16 hi + lo split.  K: writes single fp16 (olo == nullptr).
__device__ __forceinline__ void normrope_row(
    int gw, int lane, __half* __restrict__ ohi, __half* __restrict__ olo,
    const float* __restrict__ scale, int nheads, int col0, float post) {
    int h = gw % nheads;
    int s = (gw / nheads) % S_LEN;
    int b = gw / (nheads * S_LEN);

    const float* ip = g_qkv_raw + ((size_t)(b * S_LEN + s)) * QKV_W + col0 + h * HD;
    float x1 = ip[lane];
    float x2 = ip[lane + 32];
    float ss = x1 * x1 + x2 * x2;
#pragma unroll
    for (int o = 16; o; o >>= 1) ss += __shfl_xor_sync(0xffffffffu, ss, o);
    float inv = rsqrtf(ss * (1.0f / 64.0f) + 1e-5f);
    x1 *= inv * scale[lane];
    x2 *= inv * scale[lane + 32];

    float invf = (float)(c_inv8[lane & 7] * c_p10[lane >> 3]);
    float f = (float)s * invf;
    float c, sn;
    sincosf(f, &sn, &c);   // sincosf(x, SIN*, COS*)

    float y1 = (x1 * c - x2 * sn) * post;
    float y2 = (x1 * sn + x2 * c) * post;

    size_t base = (((size_t)(b * nheads + h)) * S_LEN + s) * HD;
    __half h1 = __float2half_rn(y1);
    __half h2 = __float2half_rn(y2);
    ohi[base + lane] = h1;
    ohi[base + lane + 32] = h2;
    if (olo) {
        olo[base + lane] = __float2half_rn(y1 - __half2float(h1));
        olo[base + lane + 32] = __float2half_rn(y2 - __half2float(h2));
    }
}

// blocks: [0,8192) Q ; [8192,10240) K ; [10240,11264) V copy
__global__ void postproc_kernel(const float* __restrict__ qs,
                                const float* __restrict__ ks) {
    int bx = blockIdx.x;
    int tid = threadIdx.x;
    int wid = tid >> 5, lane = tid & 31;
    if (bx < 8192) {
        normrope_row(bx * 8 + wid, lane, g_qh16, g_ql16, qs, NH, 0, 0.125f);
    } else if (bx < 10240) {
        normrope_row((bx - 8192) * 8 + wid, lane, g_k16, nullptr, ks, NKV, DM, 1.0f);
    } else {
        int idx = (bx - 10240) * 256 + tid;   // float4 index
        int c4 = idx & 15;
        int tmp = idx >> 4;
        int s = tmp % S_LEN;
        int bk = tmp / S_LEN;
        int kvh = bk % NKV;
        int b = bk / NKV;
        float4 v = *(const float4*)(g_qkv_raw + ((size_t)(b * S_LEN + s)) * QKV_W +
                                    (DM + NKV * HD) + kvh * HD + c4 * 4);
        cvt_write_h(v, g_v16, ((size_t)bk * S_LEN + s) * HD + c4 * 4);
    }
}

// ---------------- fp16 mma.sync causal GQA flash attention ---------------------
// S = (Qh + Ql) @ K^T  (Q exact split -- logit errors are exp-amplified)
// O += P @ V           (P, V single fp16 -- value-stage errors, benign)
#define SPAD 72   // 64 + 8
#define ATT_SMEM (2 * 2 * 64 * SPAD * 2)   // 36864 bytes (== Q staging size)

__global__ __launch_bounds__(256, 2) void attn_mma_kernel() {
    extern __shared__ __align__(16) __half dsm[];

    int b = blockIdx.z, h = blockIdx.y;
    int mb = (int)(gridDim.x - 1) - (int)blockIdx.x;  // heavy CTAs first
    int kvh = h >> 2;
    int tid = threadIdx.x;
    int wid = tid >> 5, lane = tid & 31;
    int g = lane >> 2, tg = lane & 3;

    const __half* qhi = g_qh16 + (((size_t)(b * NH + h)) * S_LEN + mb * 128) * HD;
    const __half* qlo = g_ql16 + (((size_t)(b * NH + h)) * S_LEN + mb * 128) * HD;
    const __half* kp = g_k16 + ((size_t)(b * NKV + kvh)) * S_LEN * HD;
    const __half* vp = g_v16 + ((size_t)(b * NKV + kvh)) * S_LEN * HD;

    // ---- stage Q tile [128][64] hi+lo through smem, grab a-frags ----
    __half* qs = dsm;   // [256][SPAD]
#pragma unroll
    for (int i = 0; i < 4; i++) {
        int idx = tid + i * 256;
        int r = idx >> 3;
        int c8 = (idx & 7) * 8;
        cpa16(smem_u32(qs + (size_t)r * SPAD + c8), qhi + (size_t)r * HD + c8);
        cpa16(smem_u32(qs + (size_t)(r + 128) * SPAD + c8), qlo + (size_t)r * HD + c8);
    }
    CP_COMMIT; CP_WAIT0;
    __syncthreads();

    uint32_t qha[4][4], qla[4][4];
    {
        int row = wid * 16 + (lane & 15);
#pragma unroll
        for (int kt = 0; kt < 4; kt++) {
            int col = kt * 16 + (lane >> 4) * 8;
            ldsm_x4(qha[kt][0], qha[kt][1], qha[kt][2], qha[kt][3],
                    smem_u32(qs + (size_t)row * SPAD + col));
            ldsm_x4(qla[kt][0], qla[kt][1], qla[kt][2], qla[kt][3],
                    smem_u32(qs + (size_t)(row + 128) * SPAD + col));
        }
    }
    __syncthreads();

    float oacc[8][4];
#pragma unroll
    for (int nt = 0; nt < 8; nt++)
#pragma unroll
        for (int e = 0; e < 4; e++) oacc[nt][e] = 0.0f;
    float m_i[2] = {-1e30f, -1e30f};
    float l_i[2] = {0.0f, 0.0f};

    int grow = mb * 128 + wid * 16;
    int row0 = grow + g, row1 = grow + g + 8;

    auto load_kv = [&](int t, int stage) {
        int n0 = t * 64;
        __half* base = dsm + (size_t)stage * 2 * 64 * SPAD;
#pragma unroll
        for (int i = 0; i < 2; i++) {
            int idx = tid + i * 256;
            int r = idx >> 3;
            int c8 = (idx & 7) * 8;
            cpa16(smem_u32(base + (size_t)r * SPAD + c8),
                  kp + (size_t)(n0 + r) * HD + c8);
            cpa16(smem_u32(base + (size_t)(64 + r) * SPAD + c8),
                  vp + (size_t)(n0 + r) * HD + c8);
        }
    };

    int ntiles = mb * 2 + 2;
    load_kv(0, 0);
    CP_COMMIT;

    for (int t = 0; t < ntiles; t++) {
        int stage = t & 1;
        if (t + 1 < ntiles) {
            load_kv(t + 1, stage ^ 1);
            CP_COMMIT;
            CP_WAIT1;
        } else {
            CP_WAIT0;
        }
        __syncthreads();

        __half* sK = dsm + (size_t)stage * 2 * 64 * SPAD;
        __half* sV = sK + 64 * SPAD;
        int n0 = t * 64;

        // ---- S = Q K^T (Q split, K single) ----
        float sacc[8][4];
#pragma unroll
        for (int nt = 0; nt < 8; nt++)
#pragma unroll
            for (int e = 0; e < 4; e++) sacc[nt][e] = 0.0f;

#pragma unroll
        for (int kt = 0; kt < 4; kt++) {
            uint32_t kb[8][2];
            {
                int rr = (lane & 7) + ((lane >> 4) << 3);
                int cc = kt * 16 + (((lane >> 3) & 1) << 3);
#pragma unroll
                for (int nb = 0; nb < 4; nb++) {
                    uint32_t t0, t1, t2, t3;
                    ldsm_x4(t0, t1, t2, t3,
                            smem_u32(sK + (size_t)(nb * 16 + rr) * SPAD + cc));
                    kb[nb * 2 + 0][0] = t0; kb[nb * 2 + 0][1] = t1;
                    kb[nb * 2 + 1][0] = t2; kb[nb * 2 + 1][1] = t3;
                }
            }
#pragma unroll
            for (int nt = 0; nt < 8; nt++) {
                mma_f16(sacc[nt], qha[kt], kb[nt]);
                mma_f16(sacc[nt], qla[kt], kb[nt]);
            }
        }

        // ---- causal mask + online softmax ----
        float rm[2] = {-1e30f, -1e30f};
#pragma unroll
        for (int nt = 0; nt < 8; nt++) {
            int col = n0 + nt * 8 + tg * 2;
            if (col > row0) sacc[nt][0] = -1e30f;
            if (col + 1 > row0) sacc[nt][1] = -1e30f;
            if (col > row1) sacc[nt][2] = -1e30f;
            if (col + 1 > row1) sacc[nt][3] = -1e30f;
            rm[0] = fmaxf(rm[0], fmaxf(sacc[nt][0], sacc[nt][1]));
            rm[1] = fmaxf(rm[1], fmaxf(sacc[nt][2], sacc[nt][3]));
        }
#pragma unroll
        for (int o = 1; o <= 2; o <<= 1) {
            rm[0] = fmaxf(rm[0], __shfl_xor_sync(0xffffffffu, rm[0], o));
            rm[1] = fmaxf(rm[1], __shfl_xor_sync(0xffffffffu, rm[1], o));
        }
        float m_new0 = fmaxf(m_i[0], rm[0]);
        float m_new1 = fmaxf(m_i[1], rm[1]);
        float corr0 = __expf(m_i[0] - m_new0);
        float corr1 = __expf(m_i[1] - m_new1);
        float ls0 = 0.0f, ls1 = 0.0f;
#pragma unroll
        for (int nt = 0; nt < 8; nt++) {
            sacc[nt][0] = __expf(sacc[nt][0] - m_new0);
            sacc[nt][1] = __expf(sacc[nt][1] - m_new0);
            sacc[nt][2] = __expf(sacc[nt][2] - m_new1);
            sacc[nt][3] = __expf(sacc[nt][3] - m_new1);
            ls0 += sacc[nt][0] + sacc[nt][1];
            ls1 += sacc[nt][2] + sacc[nt][3];
        }
#pragma unroll
        for (int o = 1; o <= 2; o <<= 1) {
            ls0 += __shfl_xor_sync(0xffffffffu, ls0, o);
            ls1 += __shfl_xor_sync(0xffffffffu, ls1, o);
        }
        l_i[0] = l_i[0] * corr0 + ls0;
        l_i[1] = l_i[1] * corr1 + ls1;
        m_i[0] = m_new0; m_i[1] = m_new1;
#pragma unroll
        for (int nt = 0; nt < 8; nt++) {
            oacc[nt][0] *= corr0; oacc[nt][1] *= corr0;
            oacc[nt][2] *= corr1; oacc[nt][3] *= corr1;
        }

        // ---- O += P V (P single, V single) ----
#pragma unroll
        for (int kt = 0; kt < 4; kt++) {
            uint32_t pha[4];
#pragma unroll
            for (int half = 0; half < 2; half++) {
                const float* pp = sacc[kt * 2 + half];
                __half2 a01 = __halves2half2(__float2half_rn(pp[0]),
                                             __float2half_rn(pp[1]));
                __half2 a23 = __halves2half2(__float2half_rn(pp[2]),
                                             __float2half_rn(pp[3]));
                pha[half * 2 + 0] = *(uint32_t*)&a01;
                pha[half * 2 + 1] = *(uint32_t*)&a23;
            }
            uint32_t vb[8][2];
            {
                int rr = kt * 16 + (lane & 15);
                int c0 = (lane >> 4) * 8;
#pragma unroll
                for (int nb = 0; nb < 4; nb++) {
                    uint32_t t0, t1, t2, t3;
                    ldsm_x4_t(t0, t1, t2, t3,
                              smem_u32(sV + (size_t)rr * SPAD + nb * 16 + c0));
                    vb[nb * 2 + 0][0] = t0; vb[nb * 2 + 0][1] = t1;
                    vb[nb * 2 + 1][0] = t2; vb[nb * 2 + 1][1] = t3;
                }
            }
#pragma unroll
            for (int nt = 0; nt < 8; nt++)
                mma_f16(oacc[nt], pha, vb[nt]);
        }
        __syncthreads();
    }

    // ---- epilogue: write fp16 hi/lo splits for the Wo GEMM ----
    float inv0 = 1.0f / l_i[0];
    float inv1 = 1.0f / l_i[1];
#pragma unroll
    for (int nt = 0; nt < 8; nt++) {
        int col = h * HD + nt * 8 + tg * 2;
        size_t o0 = ((size_t)(b * S_LEN + row0)) * DM + col;
        size_t o1 = ((size_t)(b * S_LEN + row1)) * DM + col;
        float y00 = oacc[nt][0] * inv0, y01 = oacc[nt][1] * inv0;
        float y10 = oacc[nt][2] * inv1, y11 = oacc[nt][3] * inv1;
        __half h00 = __float2half_rn(y00), h01 = __float2half_rn(y01);
        __half h10 = __float2half_rn(y10), h11 = __float2half_rn(y11);
        *(__half2*)&g_aoh16[o0] = __halves2half2(h00, h01);
        *(__half2*)&g_aoh16[o1] = __halves2half2(h10, h11);
        *(__half2*)&g_aol16[o0] = __halves2half2(
            __float2half_rn(y00 - __half2float(h00)),
            __float2half_rn(y01 - __half2float(h01)));
        *(__half2*)&g_aol16[o1] = __halves2half2(
            __float2half_rn(y10 - __half2float(h10)),
            __float2half_rn(y11 - __half2float(h11)));
    }
}

// ---------------- launcher ----------------------------------------------------
extern "C" void kernel_launch(void* const* d_in, const int* in_sizes, int n_in,
                              void* d_out, int out_size) {
    const float* x   = (const float*)d_in[0];
    const float* Wq  = (const float*)d_in[1];
    const float* Wkv = (const float*)d_in[2];
    const float* Wo  = (const float*)d_in[3];
    const float* qs  = (const float*)d_in[4];
    const float* ks  = (const float*)d_in[5];
    float* out = (float*)d_out;

    float* pqkv;
    cudaGetSymbolAddress((void**)&pqkv, g_qkv_raw);

    __half *pxh, *pxl, *pw1, *pwo, *paoh, *paol;
    cudaGetSymbolAddress((void**)&pxh, g_xh16);
    cudaGetSymbolAddress((void**)&pxl, g_xl16);
    cudaGetSymbolAddress((void**)&pw1, g_w116);
    cudaGetSymbolAddress((void**)&pwo, g_wo16);
    cudaGetSymbolAddress((void**)&paoh, g_aoh16);
    cudaGetSymbolAddress((void**)&paol, g_aol16);

    cudaFuncSetAttribute(attn_mma_kernel,
                         cudaFuncAttributeMaxDynamicSharedMemorySize, ATT_SMEM);

    int M = BATCH * S_LEN;  // 4096

    // 0) fused convert: X -> fp16 split, weights -> single fp16
    cvt_all<<<6656, 256>>>(x, Wq, Wkv, Wo);

    // 1) merged QKV projection (fp16 2-term)
    gemm_f16_2x<<<dim3(QKV_W / GBN, M / GBM), 128>>>(
        pxh, pxl, pw1, pqkv, M, QKV_W, DM);

    // 2) fused rmsnorm+rope (Q split fp16, K single fp16) + V fp16 rearrange
    postproc_kernel<<<11264, 256>>>(qs, ks);

    // 3) fp16 mma causal GQA attention (2-stage pipelined K/V, 2 CTAs/SM)
    attn_mma_kernel<<<dim3(S_LEN / 128, NH, BATCH), 256, ATT_SMEM>>>();

    // 4) output projection (fp16 2-term)
    gemm_f16_2x<<<dim3(DM / GBN, M / GBM), 128>>>(paoh, paol, pwo, out, M, DM, DM);
}

// round 13
// speedup vs baseline: 7.4174x; 1.1751x over previous
#include <cuda_runtime.h>
#include <cuda_fp16.h>
#include <math.h>
#include <stdint.h>

#define BATCH 2
#define S_LEN 2048
#define DM 1024
#define NH 16
#define NKV 4
#define HD 64
#define KV_W 512     // 2 * NKV * HD
#define QKV_W 1536   // DM + KV_W

// ---------------- scratch (device globals; no allocs allowed) ----------------
__device__ float g_qkv_raw[BATCH * S_LEN * QKV_W];  // X @ [Wq | Wkv]

// fp16 buffers: X split hi/lo (exact), weights single fp16
__device__ __half g_xh16[BATCH * S_LEN * DM];
__device__ __half g_xl16[BATCH * S_LEN * DM];
__device__ __half g_w116[DM * QKV_W];   // [Wq | Wkv] single fp16
__device__ __half g_wo16[DM * DM];      // Wo single fp16
__device__ __half g_aoh16[BATCH * S_LEN * DM];
__device__ __half g_aol16[BATCH * S_LEN * DM];

// fp16 attention operands: Q, K, V single fp16 (Q logit error covered by margin)
__device__ __half g_q16[BATCH * NH * S_LEN * HD];
__device__ __half g_k16[BATCH * NKV * S_LEN * HD];
__device__ __half g_v16[BATCH * NKV * S_LEN * HD];

// ---------------- helpers ------------------------------------------------------
__device__ __forceinline__ uint32_t smem_u32(const void* p) {
    return (uint32_t)__cvta_generic_to_shared(p);
}
__device__ __forceinline__ void cpa16(uint32_t s, const void* g) {
    asm volatile("cp.async.cg.shared.global [%0], [%1], 16;" :: "r"(s), "l"(g));
}
#define CP_COMMIT asm volatile("cp.async.commit_group;")
#define CP_WAIT0  asm volatile("cp.async.wait_group 0;")
#define CP_WAIT1  asm volatile("cp.async.wait_group 1;")

__device__ __forceinline__ void ldsm_x4(uint32_t& r0, uint32_t& r1,
                                        uint32_t& r2, uint32_t& r3, uint32_t a) {
    asm volatile("ldmatrix.sync.aligned.m8n8.x4.shared.b16 {%0,%1,%2,%3},[%4];"
                 : "=r"(r0), "=r"(r1), "=r"(r2), "=r"(r3) : "r"(a));
}
__device__ __forceinline__ void ldsm_x4_t(uint32_t& r0, uint32_t& r1,
                                          uint32_t& r2, uint32_t& r3, uint32_t a) {
    asm volatile("ldmatrix.sync.aligned.m8n8.x4.trans.shared.b16 {%0,%1,%2,%3},[%4];"
                 : "=r"(r0), "=r"(r1), "=r"(r2), "=r"(r3) : "r"(a));
}
__device__ __forceinline__ void mma_f16(float* c, const uint32_t* a,
                                        const uint32_t* b) {
    asm volatile(
        "mma.sync.aligned.m16n8k16.row.col.f32.f16.f16.f32 "
        "{%0,%1,%2,%3},{%4,%5,%6,%7},{%8,%9},{%0,%1,%2,%3};"
        : "+f"(c[0]), "+f"(c[1]), "+f"(c[2]), "+f"(c[3])
        : "r"(a[0]), "r"(a[1]), "r"(a[2]), "r"(a[3]), "r"(b[0]), "r"(b[1]));
}

// ---------------- fused converts -----------------------------------------------
__device__ __forceinline__ void split_write_h(float4 v, __half* hi, __half* lo,
                                              size_t o) {
    __half h0 = __float2half_rn(v.x);
    __half h1 = __float2half_rn(v.y);
    __half h2 = __float2half_rn(v.z);
    __half h3 = __float2half_rn(v.w);
    *(__half2*)(hi + o) = __halves2half2(h0, h1);
    *(__half2*)(hi + o + 2) = __halves2half2(h2, h3);
    *(__half2*)(lo + o) = __halves2half2(
        __float2half_rn(v.x - __half2float(h0)),
        __float2half_rn(v.y - __half2float(h1)));
    *(__half2*)(lo + o + 2) = __halves2half2(
        __float2half_rn(v.z - __half2float(h2)),
        __float2half_rn(v.w - __half2float(h3)));
}
__device__ __forceinline__ void cvt_write_h(float4 v, __half* dst, size_t o) {
    *(__half2*)(dst + o) = __halves2half2(__float2half_rn(v.x), __float2half_rn(v.y));
    *(__half2*)(dst + o + 2) = __halves2half2(__float2half_rn(v.z), __float2half_rn(v.w));
}

// regions: [0,4096) X split ; [4096,5120) Wq->w1 ; [5120,5632) Wkv->w1 ; [5632,6656) Wo
__global__ void cvt_all(const float* __restrict__ x, const float* __restrict__ Wq,
                        const float* __restrict__ Wkv, const float* __restrict__ Wo) {
    int bx = blockIdx.x;
    int tid = threadIdx.x;
    if (bx < 4096) {
        int i = bx * 256 + tid;
        float4 v = *(const float4*)(x + (size_t)i * 4);
        split_write_h(v, g_xh16, g_xl16, (size_t)i * 4);
    } else if (bx < 5120) {
        int i = (bx - 4096) * 256 + tid;
        int r = (i * 4) / DM, c = (i * 4) % DM;
        float4 v = *(const float4*)(Wq + (size_t)r * DM + c);
        cvt_write_h(v, g_w116, (size_t)r * QKV_W + c);
    } else if (bx < 5632) {
        int i = (bx - 5120) * 256 + tid;
        int r = (i * 4) / KV_W, c = (i * 4) % KV_W;
        float4 v = *(const float4*)(Wkv + (size_t)r * KV_W + c);
        cvt_write_h(v, g_w116, (size_t)r * QKV_W + DM + c);
    } else {
        int i = (bx - 5632) * 256 + tid;
        float4 v = *(const float4*)(Wo + (size_t)i * 4);
        cvt_write_h(v, g_wo16, (size_t)i * 4);
    }
}

// ---------------- fp16 2-term GEMM: B loaded ONCE per K-tile -------------------
// C = (Ah + Al) @ B. Per K-tile: stage Ah, Al, B; run both mma sets vs one B.
#define GBM 128
#define GBN 128
#define GBK 32
// dynamic smem layout (bytes):
//   As: [2 buf][2 seg][128][GBK+8]  = 2*2*128*40*2 = 40960
//   Bs: [2 buf][GBK][GBN+8]         = 2*32*136*2   = 17408
#define GA_STRIDE 40
#define GB_STRIDE 136
#define GEMM_SMEM (40960 + 17408)

__global__ __launch_bounds__(128, 2) void gemm_f16_2x(
    const __half* __restrict__ Ah, const __half* __restrict__ Al,
    const __half* __restrict__ B, float* __restrict__ C, int M, int N, int K) {
    extern __shared__ __align__(16) char gsm[];
    __half* As = (__half*)gsm;
    __half* Bs = (__half*)(gsm + 40960);
#define AS_AT(buf, seg, r, c) (As + ((((buf)*2 + (seg)) * GBM + (r)) * GA_STRIDE + (c)))
#define BS_AT(buf, r, c) (Bs + (((buf)*GBK + (r)) * GB_STRIDE + (c)))

    int tid = threadIdx.x;
    int wid = tid >> 5, lane = tid & 31;
    int bm = blockIdx.y * GBM, bn = blockIdx.x * GBN;
    int wm = (wid & 1) * 64;
    int wn = (wid >> 1) * 64;

    int T = K / GBK;

    auto prefetch = [&](int t, int buf) {
        int kl = t * GBK;
#pragma unroll
        for (int i = 0; i < 4; i++) {
            int idx = tid + i * 128;                 // 0..511
            int ar = idx >> 2, ac = (idx & 3) * 8;   // 128 x 32
            cpa16(smem_u32(AS_AT(buf, 0, ar, ac)), Ah + (size_t)(bm + ar) * K + kl + ac);
            cpa16(smem_u32(AS_AT(buf, 1, ar, ac)), Al + (size_t)(bm + ar) * K + kl + ac);
            int br = idx >> 4, bc = (idx & 15) * 8;  // 32 x 128
            cpa16(smem_u32(BS_AT(buf, br, bc)), B + (size_t)(kl + br) * N + bn + bc);
        }
    };

    float acc[4][8][4];
#pragma unroll
    for (int i = 0; i < 4; i++)
#pragma unroll
        for (int j = 0; j < 8; j++)
#pragma unroll
            for (int e = 0; e < 4; e++) acc[i][j][e] = 0.0f;

    prefetch(0, 0);
    CP_COMMIT;

    for (int t = 0; t < T; t++) {
        int buf = t & 1;
        CP_WAIT0;
        __syncthreads();
        if (t + 1 < T) {
            prefetch(t + 1, buf ^ 1);
            CP_COMMIT;
        }

#pragma unroll
        for (int k0 = 0; k0 < GBK; k0 += 16) {
            uint32_t b[8][2];
#pragma unroll
            for (int np = 0; np < 4; np++) {
                int r = k0 + (lane & 15);
                int col = wn + np * 16 + (lane >> 4) * 8;
                uint32_t t0, t1, t2, t3;
                ldsm_x4_t(t0, t1, t2, t3, smem_u32(BS_AT(buf, r, col)));
                b[np * 2 + 0][0] = t0; b[np * 2 + 0][1] = t1;
                b[np * 2 + 1][0] = t2; b[np * 2 + 1][1] = t3;
            }
            uint32_t ah[4][4], al[4][4];
#pragma unroll
            for (int mt = 0; mt < 4; mt++) {
                int row = wm + mt * 16 + (lane & 15);
                int col = k0 + (lane >> 4) * 8;
                ldsm_x4(ah[mt][0], ah[mt][1], ah[mt][2], ah[mt][3],
                        smem_u32(AS_AT(buf, 0, row, col)));
                ldsm_x4(al[mt][0], al[mt][1], al[mt][2], al[mt][3],
                        smem_u32(AS_AT(buf, 1, row, col)));
            }
#pragma unroll
            for (int mt = 0; mt < 4; mt++)
#pragma unroll
                for (int nt = 0; nt < 8; nt++) {
                    mma_f16(acc[mt][nt], ah[mt], b[nt]);
                    mma_f16(acc[mt][nt], al[mt], b[nt]);
                }
        }
    }

    int g = lane >> 2, tg = lane & 3;
#pragma unroll
    for (int mt = 0; mt < 4; mt++) {
#pragma unroll
        for (int nt = 0; nt < 8; nt++) {
            int row = bm + wm + mt * 16 + g;
            int col = bn + wn + nt * 8 + tg * 2;
            *(float2*)&C[(size_t)row * N + col] =
                make_float2(acc[mt][nt][0], acc[mt][nt][1]);
            *(float2*)&C[(size_t)(row + 8) * N + col] =
                make_float2(acc[mt][nt][2], acc[mt][nt][3]);
        }
    }
#undef AS_AT
#undef BS_AT
}

// ---------------- fused RMSNorm+RoPE (Q,K) + V rearrange -----------------------
__device__ const double c_inv8[8] = {
    1.0, 0.74989420933245582, 0.56234132519034912, 0.42169650342858224,
    0.31622776601683794, 0.23713737056616552, 0.17782794100389229,
    0.13335214321633241};
__device__ const double c_p10[4] = {1.0, 0.1, 0.01, 0.001};

__device__ __forceinline__ void normrope_row(
    int gw, int lane, __half* __restrict__ out,
    const float* __restrict__ scale, int nheads, int col0, float post) {
    int h = gw % nheads;
    int s = (gw / nheads) % S_LEN;
    int b = gw / (nheads * S_LEN);

    const float* ip = g_qkv_raw + ((size_t)(b * S_LEN + s)) * QKV_W + col0 + h * HD;
    float x1 = ip[lane];
    float x2 = ip[lane + 32];
    float ss = x1 * x1 + x2 * x2;
#pragma unroll
    for (int o = 16; o; o >>= 1) ss += __shfl_xor_sync(0xffffffffu, ss, o);
    float inv = rsqrtf(ss * (1.0f / 64.0f) + 1e-5f);
    x1 *= inv * scale[lane];
    x2 *= inv * scale[lane + 32];

    float invf = (float)(c_inv8[lane & 7] * c_p10[lane >> 3]);
    float f = (float)s * invf;
    float c, sn;
    sincosf(f, &sn, &c);   // sincosf(x, SIN*, COS*)

    size_t base = (((size_t)(b * nheads + h)) * S_LEN + s) * HD;
    out[base + lane] = __float2half_rn((x1 * c - x2 * sn) * post);
    out[base + lane + 32] = __float2half_rn((x1 * sn + x2 * c) * post);
}

// blocks: [0,8192) Q ; [8192,10240) K ; [10240,11264) V copy
__global__ void postproc_kernel(const float* __restrict__ qs,
                                const float* __restrict__ ks) {
    int bx = blockIdx.x;
    int tid = threadIdx.x;
    int wid = tid >> 5, lane = tid & 31;
    if (bx < 8192) {
        normrope_row(bx * 8 + wid, lane, g_q16, qs, NH, 0, 0.125f);
    } else if (bx < 10240) {
        normrope_row((bx - 8192) * 8 + wid, lane, g_k16, ks, NKV, DM, 1.0f);
    } else {
        int idx = (bx - 10240) * 256 + tid;   // float4 index
        int c4 = idx & 15;
        int tmp = idx >> 4;
        int s = tmp % S_LEN;
        int bk = tmp / S_LEN;
        int kvh = bk % NKV;
        int b = bk / NKV;
        float4 v = *(const float4*)(g_qkv_raw + ((size_t)(b * S_LEN + s)) * QKV_W +
                                    (DM + NKV * HD) + kvh * HD + c4 * 4);
        cvt_write_h(v, g_v16, ((size_t)bk * S_LEN + s) * HD + c4 * 4);
    }
}

// ---------------- fp16 mma.sync causal GQA flash attention ---------------------
// S = Q @ K^T ; O += P @ V   (all single fp16; error budget calibrated)
#define SPAD 72   // 64 + 8
#define ATT_SMEM (2 * 2 * 64 * SPAD * 2)   // 36864 bytes

__global__ __launch_bounds__(256, 2) void attn_mma_kernel() {
    extern __shared__ __align__(16) __half dsm[];

    int b = blockIdx.z, h = blockIdx.y;
    int mb = (int)(gridDim.x - 1) - (int)blockIdx.x;  // heavy CTAs first
    int kvh = h >> 2;
    int tid = threadIdx.x;
    int wid = tid >> 5, lane = tid & 31;
    int g = lane >> 2, tg = lane & 3;

    const __half* qp = g_q16 + (((size_t)(b * NH + h)) * S_LEN + mb * 128) * HD;
    const __half* kp = g_k16 + ((size_t)(b * NKV + kvh)) * S_LEN * HD;
    const __half* vp = g_v16 + ((size_t)(b * NKV + kvh)) * S_LEN * HD;

    // ---- stage Q tile [128][64] through smem, grab a-frags ----
    __half* qs = dsm;   // [128][SPAD]
#pragma unroll
    for (int i = 0; i < 4; i++) {
        int idx = tid + i * 256;          // 0..1023
        int r = idx >> 3;                 // 0..127
        int c8 = (idx & 7) * 8;
        cpa16(smem_u32(qs + (size_t)r * SPAD + c8), qp + (size_t)r * HD + c8);
    }
    CP_COMMIT; CP_WAIT0;
    __syncthreads();

    uint32_t qha[4][4];
    {
        int row = wid * 16 + (lane & 15);
#pragma unroll
        for (int kt = 0; kt < 4; kt++) {
            int col = kt * 16 + (lane >> 4) * 8;
            ldsm_x4(qha[kt][0], qha[kt][1], qha[kt][2], qha[kt][3],
                    smem_u32(qs + (size_t)row * SPAD + col));
        }
    }
    __syncthreads();

    float oacc[8][4];
#pragma unroll
    for (int nt = 0; nt < 8; nt++)
#pragma unroll
        for (int e = 0; e < 4; e++) oacc[nt][e] = 0.0f;
    float m_i[2] = {-1e30f, -1e30f};
    float l_i[2] = {0.0f, 0.0f};

    int grow = mb * 128 + wid * 16;
    int row0 = grow + g, row1 = grow + g + 8;

    auto load_kv = [&](int t, int stage) {
        int n0 = t * 64;
        __half* base = dsm + (size_t)stage * 2 * 64 * SPAD;
#pragma unroll
        for (int i = 0; i < 2; i++) {
            int idx = tid + i * 256;
            int r = idx >> 3;
            int c8 = (idx & 7) * 8;
            cpa16(smem_u32(base + (size_t)r * SPAD + c8),
                  kp + (size_t)(n0 + r) * HD + c8);
            cpa16(smem_u32(base + (size_t)(64 + r) * SPAD + c8),
                  vp + (size_t)(n0 + r) * HD + c8);
        }
    };

    int ntiles = mb * 2 + 2;
    load_kv(0, 0);
    CP_COMMIT;

    for (int t = 0; t < ntiles; t++) {
        int stage = t & 1;
        if (t + 1 < ntiles) {
            load_kv(t + 1, stage ^ 1);
            CP_COMMIT;
            CP_WAIT1;
        } else {
            CP_WAIT0;
        }
        __syncthreads();

        __half* sK = dsm + (size_t)stage * 2 * 64 * SPAD;
        __half* sV = sK + 64 * SPAD;
        int n0 = t * 64;

        // ---- S = Q K^T ----
        float sacc[8][4];
#pragma unroll
        for (int nt = 0; nt < 8; nt++)
#pragma unroll
            for (int e = 0; e < 4; e++) sacc[nt][e] = 0.0f;

#pragma unroll
        for (int kt = 0; kt < 4; kt++) {
            uint32_t kb[8][2];
            {
                int rr = (lane & 7) + ((lane >> 4) << 3);
                int cc = kt * 16 + (((lane >> 3) & 1) << 3);
#pragma unroll
                for (int nb = 0; nb < 4; nb++) {
                    uint32_t t0, t1, t2, t3;
                    ldsm_x4(t0, t1, t2, t3,
                            smem_u32(sK + (size_t)(nb * 16 + rr) * SPAD + cc));
                    kb[nb * 2 + 0][0] = t0; kb[nb * 2 + 0][1] = t1;
                    kb[nb * 2 + 1][0] = t2; kb[nb * 2 + 1][1] = t3;
                }
            }
#pragma unroll
            for (int nt = 0; nt < 8; nt++)
                mma_f16(sacc[nt], qha[kt], kb[nt]);
        }

        // ---- causal mask + online softmax ----
        float rm[2] = {-1e30f, -1e30f};
#pragma unroll
        for (int nt = 0; nt < 8; nt++) {
            int col = n0 + nt * 8 + tg * 2;
            if (col > row0) sacc[nt][0] = -1e30f;
            if (col + 1 > row0) sacc[nt][1] = -1e30f;
            if (col > row1) sacc[nt][2] = -1e30f;
            if (col + 1 > row1) sacc[nt][3] = -1e30f;
            rm[0] = fmaxf(rm[0], fmaxf(sacc[nt][0], sacc[nt][1]));
            rm[1] = fmaxf(rm[1], fmaxf(sacc[nt][2], sacc[nt][3]));
        }
#pragma unroll
        for (int o = 1; o <= 2; o <<= 1) {
            rm[0] = fmaxf(rm[0], __shfl_xor_sync(0xffffffffu, rm[0], o));
            rm[1] = fmaxf(rm[1], __shfl_xor_sync(0xffffffffu, rm[1], o));
        }
        float m_new0 = fmaxf(m_i[0], rm[0]);
        float m_new1 = fmaxf(m_i[1], rm[1]);
        float corr0 = __expf(m_i[0] - m_new0);
        float corr1 = __expf(m_i[1] - m_new1);
        float ls0 = 0.0f, ls1 = 0.0f;
#pragma unroll
        for (int nt = 0; nt < 8; nt++) {
            sacc[nt][0] = __expf(sacc[nt][0] - m_new0);
            sacc[nt][1] = __expf(sacc[nt][1] - m_new0);
            sacc[nt][2] = __expf(sacc[nt][2] - m_new1);
            sacc[nt][3] = __expf(sacc[nt][3] - m_new1);
            ls0 += sacc[nt][0] + sacc[nt][1];
            ls1 += sacc[nt][2] + sacc[nt][3];
        }
#pragma unroll
        for (int o = 1; o <= 2; o <<= 1) {
            ls0 += __shfl_xor_sync(0xffffffffu, ls0, o);
            ls1 += __shfl_xor_sync(0xffffffffu, ls1, o);
        }
        l_i[0] = l_i[0] * corr0 + ls0;
        l_i[1] = l_i[1] * corr1 + ls1;
        m_i[0] = m_new0; m_i[1] = m_new1;
#pragma unroll
        for (int nt = 0; nt < 8; nt++) {
            oacc[nt][0] *= corr0; oacc[nt][1] *= corr0;
            oacc[nt][2] *= corr1; oacc[nt][3] *= corr1;
        }

        // ---- O += P V ----
#pragma unroll
        for (int kt = 0; kt < 4; kt++) {
            uint32_t pha[4];
#pragma unroll
            for (int half = 0; half < 2; half++) {
                const float* pp = sacc[kt * 2 + half];
                __half2 a01 = __halves2half2(__float2half_rn(pp[0]),
                                             __float2half_rn(pp[1]));
                __half2 a23 = __halves2half2(__float2half_rn(pp[2]),
                                             __float2half_rn(pp[3]));
                pha[half * 2 + 0] = *(uint32_t*)&a01;
                pha[half * 2 + 1] = *(uint32_t*)&a23;
            }
            uint32_t vb[8][2];
            {
                int rr = kt * 16 + (lane & 15);
                int c0 = (lane >> 4) * 8;
#pragma unroll
                for (int nb = 0; nb < 4; nb++) {
                    uint32_t t0, t1, t2, t3;
                    ldsm_x4_t(t0, t1, t2, t3,
                              smem_u32(sV + (size_t)rr * SPAD + nb * 16 + c0));
                    vb[nb * 2 + 0][0] = t0; vb[nb * 2 + 0][1] = t1;
                    vb[nb * 2 + 1][0] = t2; vb[nb * 2 + 1][1] = t3;
                }
            }
#pragma unroll
            for (int nt = 0; nt < 8; nt++)
                mma_f16(oacc[nt], pha, vb[nt]);
        }
        __syncthreads();
    }

    // ---- epilogue: write fp16 hi/lo splits for the Wo GEMM ----
    float inv0 = 1.0f / l_i[0];
    float inv1 = 1.0f / l_i[1];
#pragma unroll
    for (int nt = 0; nt < 8; nt++) {
        int col = h * HD + nt * 8 + tg * 2;
        size_t o0 = ((size_t)(b * S_LEN + row0)) * DM + col;
        size_t o1 = ((size_t)(b * S_LEN + row1)) * DM + col;
        float y00 = oacc[nt][0] * inv0, y01 = oacc[nt][1] * inv0;
        float y10 = oacc[nt][2] * inv1, y11 = oacc[nt][3] * inv1;
        __half h00 = __float2half_rn(y00), h01 = __float2half_rn(y01);
        __half h10 = __float2half_rn(y10), h11 = __float2half_rn(y11);
        *(__half2*)&g_aoh16[o0] = __halves2half2(h00, h01);
        *(__half2*)&g_aoh16[o1] = __halves2half2(h10, h11);
        *(__half2*)&g_aol16[o0] = __halves2half2(
            __float2half_rn(y00 - __half2float(h00)),
            __float2half_rn(y01 - __half2float(h01)));
        *(__half2*)&g_aol16[o1] = __halves2half2(
            __float2half_rn(y10 - __half2float(h10)),
            __float2half_rn(y11 - __half2float(h11)));
    }
}

// ---------------- launcher ----------------------------------------------------
extern "C" void kernel_launch(void* const* d_in, const int* in_sizes, int n_in,
                              void* d_out, int out_size) {
    const float* x   = (const float*)d_in[0];
    const float* Wq  = (const float*)d_in[1];
    const float* Wkv = (const float*)d_in[2];
    const float* Wo  = (const float*)d_in[3];
    const float* qs  = (const float*)d_in[4];
    const float* ks  = (const float*)d_in[5];
    float* out = (float*)d_out;

    float* pqkv;
    cudaGetSymbolAddress((void**)&pqkv, g_qkv_raw);

    __half *pxh, *pxl, *pw1, *pwo, *paoh, *paol;
    cudaGetSymbolAddress((void**)&pxh, g_xh16);
    cudaGetSymbolAddress((void**)&pxl, g_xl16);
    cudaGetSymbolAddress((void**)&pw1, g_w116);
    cudaGetSymbolAddress((void**)&pwo, g_wo16);
    cudaGetSymbolAddress((void**)&paoh, g_aoh16);
    cudaGetSymbolAddress((void**)&paol, g_aol16);

    cudaFuncSetAttribute(attn_mma_kernel,
                         cudaFuncAttributeMaxDynamicSharedMemorySize, ATT_SMEM);
    cudaFuncSetAttribute(gemm_f16_2x,
                         cudaFuncAttributeMaxDynamicSharedMemorySize, GEMM_SMEM);

    int M = BATCH * S_LEN;  // 4096

    // 0) fused convert: X -> fp16 split, weights -> single fp16
    cvt_all<<<6656, 256>>>(x, Wq, Wkv, Wo);

    // 1) merged QKV projection (fp16 2-term, B loaded once)
    gemm_f16_2x<<<dim3(QKV_W / GBN, M / GBM), 128, GEMM_SMEM>>>(
        pxh, pxl, pw1, pqkv, M, QKV_W, DM);

    // 2) fused rmsnorm+rope (Q, K single fp16) + V fp16 rearrange
    postproc_kernel<<<11264, 256>>>(qs, ks);

    // 3) fp16 mma causal GQA attention (2-stage pipelined K/V, 2 CTAs/SM)
    attn_mma_kernel<<<dim3(S_LEN / 128, NH, BATCH), 256, ATT_SMEM>>>();

    // 4) output projection (fp16 2-term)
    gemm_f16_2x<<<dim3(DM / GBN, M / GBM), 128, GEMM_SMEM>>>(
        paoh, paol, pwo, out, M, DM, DM);
}

// round 14
// speedup vs baseline: 10.2595x; 1.3832x over previous
#include <cuda_runtime.h>
#include <cuda_fp16.h>
#include <math.h>
#include <stdint.h>

#define BATCH 2
#define S_LEN 2048
#define DM 1024
#define NH 16
#define NKV 4
#define HD 64
#define KV_W 512     // 2 * NKV * HD
#define QKV_W 1536   // DM + KV_W

// ---------------- scratch (device globals; no allocs allowed) ----------------
__device__ float g_qkv_raw[BATCH * S_LEN * QKV_W];  // X @ [Wq | Wkv]

// fp16 buffers (all single precision; error budget calibrated)
__device__ __half g_x16[BATCH * S_LEN * DM];
__device__ __half g_w116[DM * QKV_W];   // [Wq | Wkv]
__device__ __half g_wo16[DM * DM];      // Wo
__device__ __half g_ao16[BATCH * S_LEN * DM];

// fp16 attention operands
__device__ __half g_q16[BATCH * NH * S_LEN * HD];
__device__ __half g_k16[BATCH * NKV * S_LEN * HD];
__device__ __half g_v16[BATCH * NKV * S_LEN * HD];

// ---------------- helpers ------------------------------------------------------
__device__ __forceinline__ uint32_t smem_u32(const void* p) {
    return (uint32_t)__cvta_generic_to_shared(p);
}
__device__ __forceinline__ void cpa16(uint32_t s, const void* g) {
    asm volatile("cp.async.cg.shared.global [%0], [%1], 16;" :: "r"(s), "l"(g));
}
#define CP_COMMIT asm volatile("cp.async.commit_group;")
#define CP_WAIT0  asm volatile("cp.async.wait_group 0;")
#define CP_WAIT1  asm volatile("cp.async.wait_group 1;")

__device__ __forceinline__ void ldsm_x4(uint32_t& r0, uint32_t& r1,
                                        uint32_t& r2, uint32_t& r3, uint32_t a) {
    asm volatile("ldmatrix.sync.aligned.m8n8.x4.shared.b16 {%0,%1,%2,%3},[%4];"
                 : "=r"(r0), "=r"(r1), "=r"(r2), "=r"(r3) : "r"(a));
}
__device__ __forceinline__ void ldsm_x4_t(uint32_t& r0, uint32_t& r1,
                                          uint32_t& r2, uint32_t& r3, uint32_t a) {
    asm volatile("ldmatrix.sync.aligned.m8n8.x4.trans.shared.b16 {%0,%1,%2,%3},[%4];"
                 : "=r"(r0), "=r"(r1), "=r"(r2), "=r"(r3) : "r"(a));
}
__device__ __forceinline__ void mma_f16(float* c, const uint32_t* a,
                                        const uint32_t* b) {
    asm volatile(
        "mma.sync.aligned.m16n8k16.row.col.f32.f16.f16.f32 "
        "{%0,%1,%2,%3},{%4,%5,%6,%7},{%8,%9},{%0,%1,%2,%3};"
        : "+f"(c[0]), "+f"(c[1]), "+f"(c[2]), "+f"(c[3])
        : "r"(a[0]), "r"(a[1]), "r"(a[2]), "r"(a[3]), "r"(b[0]), "r"(b[1]));
}

__device__ __forceinline__ void cvt_write_h(float4 v, __half* dst, size_t o) {
    *(__half2*)(dst + o) = __halves2half2(__float2half_rn(v.x), __float2half_rn(v.y));
    *(__half2*)(dst + o + 2) = __halves2half2(__float2half_rn(v.z), __float2half_rn(v.w));
}

// regions: [0,4096) X ; [4096,5120) Wq->w1 ; [5120,5632) Wkv->w1 ; [5632,6656) Wo
__global__ void cvt_all(const float* __restrict__ x, const float* __restrict__ Wq,
                        const float* __restrict__ Wkv, const float* __restrict__ Wo) {
    int bx = blockIdx.x;
    int tid = threadIdx.x;
    if (bx < 4096) {
        int i = bx * 256 + tid;
        float4 v = *(const float4*)(x + (size_t)i * 4);
        cvt_write_h(v, g_x16, (size_t)i * 4);
    } else if (bx < 5120) {
        int i = (bx - 4096) * 256 + tid;
        int r = (i * 4) / DM, c = (i * 4) % DM;
        float4 v = *(const float4*)(Wq + (size_t)r * DM + c);
        cvt_write_h(v, g_w116, (size_t)r * QKV_W + c);
    } else if (bx < 5632) {
        int i = (bx - 5120) * 256 + tid;
        int r = (i * 4) / KV_W, c = (i * 4) % KV_W;
        float4 v = *(const float4*)(Wkv + (size_t)r * KV_W + c);
        cvt_write_h(v, g_w116, (size_t)r * QKV_W + DM + c);
    } else {
        int i = (bx - 5632) * 256 + tid;
        float4 v = *(const float4*)(Wo + (size_t)i * 4);
        cvt_write_h(v, g_wo16, (size_t)i * 4);
    }
}

// ---------------- single-fp16 mma GEMM, 64x64 warp tiles, 2 CTAs/SM ------------
#define GBM 128
#define GBN 128
#define GBK 32

__global__ __launch_bounds__(128, 2) void gemm_f16(
    const __half* __restrict__ A, const __half* __restrict__ B,
    float* __restrict__ C, int M, int N, int K) {
    __shared__ __align__(16) __half As[2][GBM][GBK + 8];   // 20.0 KB
    __shared__ __align__(16) __half Bs[2][GBK][GBN + 8];   // 17.0 KB

    int tid = threadIdx.x;
    int wid = tid >> 5, lane = tid & 31;
    int bm = blockIdx.y * GBM, bn = blockIdx.x * GBN;
    int wm = (wid & 1) * 64;
    int wn = (wid >> 1) * 64;

    int T = K / GBK;

    auto prefetch = [&](int t, int buf) {
        int kl = t * GBK;
#pragma unroll
        for (int i = 0; i < 4; i++) {
            int idx = tid + i * 128;                 // 0..511
            int ar = idx >> 2, ac = (idx & 3) * 8;   // 128 x 32
            cpa16(smem_u32(&As[buf][ar][ac]), A + (size_t)(bm + ar) * K + kl + ac);
            int br = idx >> 4, bc = (idx & 15) * 8;  // 32 x 128
            cpa16(smem_u32(&Bs[buf][br][bc]), B + (size_t)(kl + br) * N + bn + bc);
        }
    };

    float acc[4][8][4];
#pragma unroll
    for (int i = 0; i < 4; i++)
#pragma unroll
        for (int j = 0; j < 8; j++)
#pragma unroll
            for (int e = 0; e < 4; e++) acc[i][j][e] = 0.0f;

    prefetch(0, 0);
    CP_COMMIT;

    for (int t = 0; t < T; t++) {
        int buf = t & 1;
        CP_WAIT0;
        __syncthreads();
        if (t + 1 < T) {
            prefetch(t + 1, buf ^ 1);
            CP_COMMIT;
        }

#pragma unroll
        for (int k0 = 0; k0 < GBK; k0 += 16) {
            uint32_t a[4][4];
#pragma unroll
            for (int mt = 0; mt < 4; mt++) {
                int row = wm + mt * 16 + (lane & 15);
                int col = k0 + (lane >> 4) * 8;
                ldsm_x4(a[mt][0], a[mt][1], a[mt][2], a[mt][3],
                        smem_u32(&As[buf][row][col]));
            }
            uint32_t b[8][2];
#pragma unroll
            for (int np = 0; np < 4; np++) {
                int r = k0 + (lane & 15);
                int col = wn + np * 16 + (lane >> 4) * 8;
                uint32_t t0, t1, t2, t3;
                ldsm_x4_t(t0, t1, t2, t3, smem_u32(&Bs[buf][r][col]));
                b[np * 2 + 0][0] = t0; b[np * 2 + 0][1] = t1;
                b[np * 2 + 1][0] = t2; b[np * 2 + 1][1] = t3;
            }
#pragma unroll
            for (int mt = 0; mt < 4; mt++)
#pragma unroll
                for (int nt = 0; nt < 8; nt++)
                    mma_f16(acc[mt][nt], a[mt], b[nt]);
        }
    }

    int g = lane >> 2, tg = lane & 3;
#pragma unroll
    for (int mt = 0; mt < 4; mt++) {
#pragma unroll
        for (int nt = 0; nt < 8; nt++) {
            int row = bm + wm + mt * 16 + g;
            int col = bn + wn + nt * 8 + tg * 2;
            *(float2*)&C[(size_t)row * N + col] =
                make_float2(acc[mt][nt][0], acc[mt][nt][1]);
            *(float2*)&C[(size_t)(row + 8) * N + col] =
                make_float2(acc[mt][nt][2], acc[mt][nt][3]);
        }
    }
}

// ---------------- fused RMSNorm+RoPE (Q,K) + V rearrange -----------------------
__device__ const double c_inv8[8] = {
    1.0, 0.74989420933245582, 0.56234132519034912, 0.42169650342858224,
    0.31622776601683794, 0.23713737056616552, 0.17782794100389229,
    0.13335214321633241};
__device__ const double c_p10[4] = {1.0, 0.1, 0.01, 0.001};

__device__ __forceinline__ void normrope_row(
    int gw, int lane, __half* __restrict__ out,
    const float* __restrict__ scale, int nheads, int col0, float post) {
    int h = gw % nheads;
    int s = (gw / nheads) % S_LEN;
    int b = gw / (nheads * S_LEN);

    const float* ip = g_qkv_raw + ((size_t)(b * S_LEN + s)) * QKV_W + col0 + h * HD;
    float x1 = ip[lane];
    float x2 = ip[lane + 32];
    float ss = x1 * x1 + x2 * x2;
#pragma unroll
    for (int o = 16; o; o >>= 1) ss += __shfl_xor_sync(0xffffffffu, ss, o);
    float inv = rsqrtf(ss * (1.0f / 64.0f) + 1e-5f);
    x1 *= inv * scale[lane];
    x2 *= inv * scale[lane + 32];

    float invf = (float)(c_inv8[lane & 7] * c_p10[lane >> 3]);
    float f = (float)s * invf;
    float c, sn;
    sincosf(f, &sn, &c);   // sincosf(x, SIN*, COS*)

    size_t base = (((size_t)(b * nheads + h)) * S_LEN + s) * HD;
    out[base + lane] = __float2half_rn((x1 * c - x2 * sn) * post);
    out[base + lane + 32] = __float2half_rn((x1 * sn + x2 * c) * post);
}

// blocks: [0,8192) Q ; [8192,10240) K ; [10240,11264) V copy
__global__ void postproc_kernel(const float* __restrict__ qs,
                                const float* __restrict__ ks) {
    int bx = blockIdx.x;
    int tid = threadIdx.x;
    int wid = tid >> 5, lane = tid & 31;
    if (bx < 8192) {
        normrope_row(bx * 8 + wid, lane, g_q16, qs, NH, 0, 0.125f);
    } else if (bx < 10240) {
        normrope_row((bx - 8192) * 8 + wid, lane, g_k16, ks, NKV, DM, 1.0f);
    } else {
        int idx = (bx - 10240) * 256 + tid;   // float4 index
        int c4 = idx & 15;
        int tmp = idx >> 4;
        int s = tmp % S_LEN;
        int bk = tmp / S_LEN;
        int kvh = bk % NKV;
        int b = bk / NKV;
        float4 v = *(const float4*)(g_qkv_raw + ((size_t)(b * S_LEN + s)) * QKV_W +
                                    (DM + NKV * HD) + kvh * HD + c4 * 4);
        cvt_write_h(v, g_v16, ((size_t)bk * S_LEN + s) * HD + c4 * 4);
    }
}

// ---------------- fp16 mma.sync causal GQA flash attention ---------------------
// S = Q @ K^T ; O += P @ V. l kept as per-thread partial, reduced once at end
// (corr is row-uniform so partials stay consistent).
#define SPAD 72   // 64 + 8
#define ATT_SMEM (2 * 2 * 64 * SPAD * 2)   // 36864 bytes

__global__ __launch_bounds__(256, 2) void attn_mma_kernel() {
    extern __shared__ __align__(16) __half dsm[];

    int b = blockIdx.z, h = blockIdx.y;
    int mb = (int)(gridDim.x - 1) - (int)blockIdx.x;  // heavy CTAs first
    int kvh = h >> 2;
    int tid = threadIdx.x;
    int wid = tid >> 5, lane = tid & 31;
    int g = lane >> 2, tg = lane & 3;

    const __half* qp = g_q16 + (((size_t)(b * NH + h)) * S_LEN + mb * 128) * HD;
    const __half* kp = g_k16 + ((size_t)(b * NKV + kvh)) * S_LEN * HD;
    const __half* vp = g_v16 + ((size_t)(b * NKV + kvh)) * S_LEN * HD;

    // ---- stage Q tile [128][64] through smem, grab a-frags ----
    __half* qs = dsm;   // [128][SPAD]
#pragma unroll
    for (int i = 0; i < 4; i++) {
        int idx = tid + i * 256;          // 0..1023
        int r = idx >> 3;                 // 0..127
        int c8 = (idx & 7) * 8;
        cpa16(smem_u32(qs + (size_t)r * SPAD + c8), qp + (size_t)r * HD + c8);
    }
    CP_COMMIT; CP_WAIT0;
    __syncthreads();

    uint32_t qha[4][4];
    {
        int row = wid * 16 + (lane & 15);
#pragma unroll
        for (int kt = 0; kt < 4; kt++) {
            int col = kt * 16 + (lane >> 4) * 8;
            ldsm_x4(qha[kt][0], qha[kt][1], qha[kt][2], qha[kt][3],
                    smem_u32(qs + (size_t)row * SPAD + col));
        }
    }
    __syncthreads();

    float oacc[8][4];
#pragma unroll
    for (int nt = 0; nt < 8; nt++)
#pragma unroll
        for (int e = 0; e < 4; e++) oacc[nt][e] = 0.0f;
    float m_i[2] = {-1e30f, -1e30f};
    float l_i[2] = {0.0f, 0.0f};   // per-thread partial sums

    int grow = mb * 128 + wid * 16;
    int row0 = grow + g, row1 = grow + g + 8;

    auto load_kv = [&](int t, int stage) {
        int n0 = t * 64;
        __half* base = dsm + (size_t)stage * 2 * 64 * SPAD;
#pragma unroll
        for (int i = 0; i < 2; i++) {
            int idx = tid + i * 256;
            int r = idx >> 3;
            int c8 = (idx & 7) * 8;
            cpa16(smem_u32(base + (size_t)r * SPAD + c8),
                  kp + (size_t)(n0 + r) * HD + c8);
            cpa16(smem_u32(base + (size_t)(64 + r) * SPAD + c8),
                  vp + (size_t)(n0 + r) * HD + c8);
        }
    };

    int ntiles = mb * 2 + 2;
    load_kv(0, 0);
    CP_COMMIT;

    for (int t = 0; t < ntiles; t++) {
        int stage = t & 1;
        if (t + 1 < ntiles) {
            load_kv(t + 1, stage ^ 1);
            CP_COMMIT;
            CP_WAIT1;
        } else {
            CP_WAIT0;
        }
        __syncthreads();

        __half* sK = dsm + (size_t)stage * 2 * 64 * SPAD;
        __half* sV = sK + 64 * SPAD;
        int n0 = t * 64;

        // ---- S = Q K^T ----
        float sacc[8][4];
#pragma unroll
        for (int nt = 0; nt < 8; nt++)
#pragma unroll
            for (int e = 0; e < 4; e++) sacc[nt][e] = 0.0f;

#pragma unroll
        for (int kt = 0; kt < 4; kt++) {
            uint32_t kb[8][2];
            {
                int rr = (lane & 7) + ((lane >> 4) << 3);
                int cc = kt * 16 + (((lane >> 3) & 1) << 3);
#pragma unroll
                for (int nb = 0; nb < 4; nb++) {
                    uint32_t t0, t1, t2, t3;
                    ldsm_x4(t0, t1, t2, t3,
                            smem_u32(sK + (size_t)(nb * 16 + rr) * SPAD + cc));
                    kb[nb * 2 + 0][0] = t0; kb[nb * 2 + 0][1] = t1;
                    kb[nb * 2 + 1][0] = t2; kb[nb * 2 + 1][1] = t3;
                }
            }
#pragma unroll
            for (int nt = 0; nt < 8; nt++)
                mma_f16(sacc[nt], qha[kt], kb[nt]);
        }

        // ---- causal mask + online softmax (row max via quad shfl) ----
        float rm[2] = {-1e30f, -1e30f};
#pragma unroll
        for (int nt = 0; nt < 8; nt++) {
            int col = n0 + nt * 8 + tg * 2;
            if (col > row0) sacc[nt][0] = -1e30f;
            if (col + 1 > row0) sacc[nt][1] = -1e30f;
            if (col > row1) sacc[nt][2] = -1e30f;
            if (col + 1 > row1) sacc[nt][3] = -1e30f;
            rm[0] = fmaxf(rm[0], fmaxf(sacc[nt][0], sacc[nt][1]));
            rm[1] = fmaxf(rm[1], fmaxf(sacc[nt][2], sacc[nt][3]));
        }
#pragma unroll
        for (int o = 1; o <= 2; o <<= 1) {
            rm[0] = fmaxf(rm[0], __shfl_xor_sync(0xffffffffu, rm[0], o));
            rm[1] = fmaxf(rm[1], __shfl_xor_sync(0xffffffffu, rm[1], o));
        }
        float m_new0 = fmaxf(m_i[0], rm[0]);
        float m_new1 = fmaxf(m_i[1], rm[1]);
        float corr0 = __expf(m_i[0] - m_new0);
        float corr1 = __expf(m_i[1] - m_new1);
        float ls0 = 0.0f, ls1 = 0.0f;
#pragma unroll
        for (int nt = 0; nt < 8; nt++) {
            sacc[nt][0] = __expf(sacc[nt][0] - m_new0);
            sacc[nt][1] = __expf(sacc[nt][1] - m_new0);
            sacc[nt][2] = __expf(sacc[nt][2] - m_new1);
            sacc[nt][3] = __expf(sacc[nt][3] - m_new1);
            ls0 += sacc[nt][0] + sacc[nt][1];
            ls1 += sacc[nt][2] + sacc[nt][3];
        }
        // deferred: no quad reduction here -- per-thread partials only
        l_i[0] = l_i[0] * corr0 + ls0;
        l_i[1] = l_i[1] * corr1 + ls1;
        m_i[0] = m_new0; m_i[1] = m_new1;
#pragma unroll
        for (int nt = 0; nt < 8; nt++) {
            oacc[nt][0] *= corr0; oacc[nt][1] *= corr0;
            oacc[nt][2] *= corr1; oacc[nt][3] *= corr1;
        }

        // ---- O += P V ----
#pragma unroll
        for (int kt = 0; kt < 4; kt++) {
            uint32_t pha[4];
#pragma unroll
            for (int half = 0; half < 2; half++) {
                const float* pp = sacc[kt * 2 + half];
                __half2 a01 = __halves2half2(__float2half_rn(pp[0]),
                                             __float2half_rn(pp[1]));
                __half2 a23 = __halves2half2(__float2half_rn(pp[2]),
                                             __float2half_rn(pp[3]));
                pha[half * 2 + 0] = *(uint32_t*)&a01;
                pha[half * 2 + 1] = *(uint32_t*)&a23;
            }
            uint32_t vb[8][2];
            {
                int rr = kt * 16 + (lane & 15);
                int c0 = (lane >> 4) * 8;
#pragma unroll
                for (int nb = 0; nb < 4; nb++) {
                    uint32_t t0, t1, t2, t3;
                    ldsm_x4_t(t0, t1, t2, t3,
                              smem_u32(sV + (size_t)rr * SPAD + nb * 16 + c0));
                    vb[nb * 2 + 0][0] = t0; vb[nb * 2 + 0][1] = t1;
                    vb[nb * 2 + 1][0] = t2; vb[nb * 2 + 1][1] = t3;
                }
            }
#pragma unroll
            for (int nt = 0; nt < 8; nt++)
                mma_f16(oacc[nt], pha, vb[nt]);
        }
        __syncthreads();
    }

    // ---- final l reduction across the quad, then epilogue (single fp16) ----
#pragma unroll
    for (int o = 1; o <= 2; o <<= 1) {
        l_i[0] += __shfl_xor_sync(0xffffffffu, l_i[0], o);
        l_i[1] += __shfl_xor_sync(0xffffffffu, l_i[1], o);
    }
    float inv0 = 1.0f / l_i[0];
    float inv1 = 1.0f / l_i[1];
#pragma unroll
    for (int nt = 0; nt < 8; nt++) {
        int col = h * HD + nt * 8 + tg * 2;
        size_t o0 = ((size_t)(b * S_LEN + row0)) * DM + col;
        size_t o1 = ((size_t)(b * S_LEN + row1)) * DM + col;
        *(__half2*)&g_ao16[o0] = __halves2half2(
            __float2half_rn(oacc[nt][0] * inv0), __float2half_rn(oacc[nt][1] * inv0));
        *(__half2*)&g_ao16[o1] = __halves2half2(
            __float2half_rn(oacc[nt][2] * inv1), __float2half_rn(oacc[nt][3] * inv1));
    }
}

// ---------------- launcher ----------------------------------------------------
extern "C" void kernel_launch(void* const* d_in, const int* in_sizes, int n_in,
                              void* d_out, int out_size) {
    const float* x   = (const float*)d_in[0];
    const float* Wq  = (const float*)d_in[1];
    const float* Wkv = (const float*)d_in[2];
    const float* Wo  = (const float*)d_in[3];
    const float* qs  = (const float*)d_in[4];
    const float* ks  = (const float*)d_in[5];
    float* out = (float*)d_out;

    float* pqkv;
    cudaGetSymbolAddress((void**)&pqkv, g_qkv_raw);

    __half *px, *pw1, *pwo, *pao;
    cudaGetSymbolAddress((void**)&px, g_x16);
    cudaGetSymbolAddress((void**)&pw1, g_w116);
    cudaGetSymbolAddress((void**)&pwo, g_wo16);
    cudaGetSymbolAddress((void**)&pao, g_ao16);

    cudaFuncSetAttribute(attn_mma_kernel,
                         cudaFuncAttributeMaxDynamicSharedMemorySize, ATT_SMEM);

    int M = BATCH * S_LEN;  // 4096

    // 0) fused convert: everything to single fp16
    cvt_all<<<6656, 256>>>(x, Wq, Wkv, Wo);

    // 1) merged QKV projection (single fp16)
    gemm_f16<<<dim3(QKV_W / GBN, M / GBM), 128>>>(px, pw1, pqkv, M, QKV_W, DM);

    // 2) fused rmsnorm+rope (Q, K) + V rearrange
    postproc_kernel<<<11264, 256>>>(qs, ks);

    // 3) fp16 mma causal GQA attention (2-stage pipelined K/V, 2 CTAs/SM)
    attn_mma_kernel<<<dim3(S_LEN / 128, NH, BATCH), 256, ATT_SMEM>>>();

    // 4) output projection (single fp16)
    gemm_f16<<<dim3(DM / GBN, M / GBM), 128>>>(pao, pwo, out, M, DM, DM);
}

// round 16
// speedup vs baseline: 10.7574x; 1.0485x over previous
#include <cuda_runtime.h>
#include <cuda_fp16.h>
#include <math.h>
#include <stdint.h>

#define BATCH 2
#define S_LEN 2048
#define DM 1024
#define NH 16
#define NKV 4
#define HD 64
#define KV_W 512     // 2 * NKV * HD
#define QKV_W 1536   // DM + KV_W

// ---------------- scratch (device globals; no allocs allowed) ----------------
__device__ float g_qkv_raw[BATCH * S_LEN * QKV_W];  // X @ [Wq | Wkv]

// fp16 buffers (all single precision; error budget calibrated)
__device__ __half g_x16[BATCH * S_LEN * DM];
__device__ __half g_w116[DM * QKV_W];   // [Wq | Wkv]
__device__ __half g_wo16[DM * DM];      // Wo
__device__ __half g_ao16[BATCH * S_LEN * DM];

// fp16 attention operands
__device__ __half g_q16[BATCH * NH * S_LEN * HD];
__device__ __half g_k16[BATCH * NKV * S_LEN * HD];
__device__ __half g_v16[BATCH * NKV * S_LEN * HD];

// ---------------- helpers ------------------------------------------------------
__device__ __forceinline__ uint32_t smem_u32(const void* p) {
    return (uint32_t)__cvta_generic_to_shared(p);
}
__device__ __forceinline__ void cpa16(uint32_t s, const void* g) {
    asm volatile("cp.async.cg.shared.global [%0], [%1], 16;" :: "r"(s), "l"(g));
}
#define CP_COMMIT asm volatile("cp.async.commit_group;")
#define CP_WAIT0  asm volatile("cp.async.wait_group 0;")
#define CP_WAIT1  asm volatile("cp.async.wait_group 1;")

__device__ __forceinline__ void ldsm_x4(uint32_t& r0, uint32_t& r1,
                                        uint32_t& r2, uint32_t& r3, uint32_t a) {
    asm volatile("ldmatrix.sync.aligned.m8n8.x4.shared.b16 {%0,%1,%2,%3},[%4];"
                 : "=r"(r0), "=r"(r1), "=r"(r2), "=r"(r3) : "r"(a));
}
__device__ __forceinline__ void ldsm_x4_t(uint32_t& r0, uint32_t& r1,
                                          uint32_t& r2, uint32_t& r3, uint32_t a) {
    asm volatile("ldmatrix.sync.aligned.m8n8.x4.trans.shared.b16 {%0,%1,%2,%3},[%4];"
                 : "=r"(r0), "=r"(r1), "=r"(r2), "=r"(r3) : "r"(a));
}
__device__ __forceinline__ void mma_f16(float* c, const uint32_t* a,
                                        const uint32_t* b) {
    asm volatile(
        "mma.sync.aligned.m16n8k16.row.col.f32.f16.f16.f32 "
        "{%0,%1,%2,%3},{%4,%5,%6,%7},{%8,%9},{%0,%1,%2,%3};"
        : "+f"(c[0]), "+f"(c[1]), "+f"(c[2]), "+f"(c[3])
        : "r"(a[0]), "r"(a[1]), "r"(a[2]), "r"(a[3]), "r"(b[0]), "r"(b[1]));
}

__device__ __forceinline__ void cvt_write_h(float4 v, __half* dst, size_t o) {
    *(__half2*)(dst + o) = __halves2half2(__float2half_rn(v.x), __float2half_rn(v.y));
    *(__half2*)(dst + o + 2) = __halves2half2(__float2half_rn(v.z), __float2half_rn(v.w));
}

// regions: [0,4096) X ; [4096,5120) Wq->w1 ; [5120,5632) Wkv->w1 ; [5632,6656) Wo
__global__ void cvt_all(const float* __restrict__ x, const float* __restrict__ Wq,
                        const float* __restrict__ Wkv, const float* __restrict__ Wo) {
    int bx = blockIdx.x;
    int tid = threadIdx.x;
    if (bx < 4096) {
        int i = bx * 256 + tid;
        float4 v = *(const float4*)(x + (size_t)i * 4);
        cvt_write_h(v, g_x16, (size_t)i * 4);
    } else if (bx < 5120) {
        int i = (bx - 4096) * 256 + tid;
        int r = (i * 4) / DM, c = (i * 4) % DM;
        float4 v = *(const float4*)(Wq + (size_t)r * DM + c);
        cvt_write_h(v, g_w116, (size_t)r * QKV_W + c);
    } else if (bx < 5632) {
        int i = (bx - 5120) * 256 + tid;
        int r = (i * 4) / KV_W, c = (i * 4) % KV_W;
        float4 v = *(const float4*)(Wkv + (size_t)r * KV_W + c);
        cvt_write_h(v, g_w116, (size_t)r * QKV_W + DM + c);
    } else {
        int i = (bx - 5632) * 256 + tid;
        float4 v = *(const float4*)(Wo + (size_t)i * 4);
        cvt_write_h(v, g_wo16, (size_t)i * 4);
    }
}

// ---------------- single-fp16 mma GEMM, 64x64 warp tiles, 2 CTAs/SM ------------
#define GBM 128
#define GBN 128
#define GBK 32

__global__ __launch_bounds__(128, 2) void gemm_f16(
    const __half* __restrict__ A, const __half* __restrict__ B,
    float* __restrict__ C, int M, int N, int K) {
    __shared__ __align__(16) __half As[2][GBM][GBK + 8];   // 20.0 KB
    __shared__ __align__(16) __half Bs[2][GBK][GBN + 8];   // 17.0 KB

    int tid = threadIdx.x;
    int wid = tid >> 5, lane = tid & 31;
    int bm = blockIdx.y * GBM, bn = blockIdx.x * GBN;
    int wm = (wid & 1) * 64;
    int wn = (wid >> 1) * 64;

    int T = K / GBK;

    auto prefetch = [&](int t, int buf) {
        int kl = t * GBK;
#pragma unroll
        for (int i = 0; i < 4; i++) {
            int idx = tid + i * 128;                 // 0..511
            int ar = idx >> 2, ac = (idx & 3) * 8;   // 128 x 32
            cpa16(smem_u32(&As[buf][ar][ac]), A + (size_t)(bm + ar) * K + kl + ac);
            int br = idx >> 4, bc = (idx & 15) * 8;  // 32 x 128
            cpa16(smem_u32(&Bs[buf][br][bc]), B + (size_t)(kl + br) * N + bn + bc);
        }
    };

    float acc[4][8][4];
#pragma unroll
    for (int i = 0; i < 4; i++)
#pragma unroll
        for (int j = 0; j < 8; j++)
#pragma unroll
            for (int e = 0; e < 4; e++) acc[i][j][e] = 0.0f;

    prefetch(0, 0);
    CP_COMMIT;

    for (int t = 0; t < T; t++) {
        int buf = t & 1;
        CP_WAIT0;
        __syncthreads();
        if (t + 1 < T) {
            prefetch(t + 1, buf ^ 1);
            CP_COMMIT;
        }

#pragma unroll
        for (int k0 = 0; k0 < GBK; k0 += 16) {
            uint32_t a[4][4];
#pragma unroll
            for (int mt = 0; mt < 4; mt++) {
                int row = wm + mt * 16 + (lane & 15);
                int col = k0 + (lane >> 4) * 8;
                ldsm_x4(a[mt][0], a[mt][1], a[mt][2], a[mt][3],
                        smem_u32(&As[buf][row][col]));
            }
            uint32_t b[8][2];
#pragma unroll
            for (int np = 0; np < 4; np++) {
                int r = k0 + (lane & 15);
                int col = wn + np * 16 + (lane >> 4) * 8;
                uint32_t t0, t1, t2, t3;
                ldsm_x4_t(t0, t1, t2, t3, smem_u32(&Bs[buf][r][col]));
                b[np * 2 + 0][0] = t0; b[np * 2 + 0][1] = t1;
                b[np * 2 + 1][0] = t2; b[np * 2 + 1][1] = t3;
            }
#pragma unroll
            for (int mt = 0; mt < 4; mt++)
#pragma unroll
                for (int nt = 0; nt < 8; nt++)
                    mma_f16(acc[mt][nt], a[mt], b[nt]);
        }
    }

    int g = lane >> 2, tg = lane & 3;
#pragma unroll
    for (int mt = 0; mt < 4; mt++) {
#pragma unroll
        for (int nt = 0; nt < 8; nt++) {
            int row = bm + wm + mt * 16 + g;
            int col = bn + wn + nt * 8 + tg * 2;
            *(float2*)&C[(size_t)row * N + col] =
                make_float2(acc[mt][nt][0], acc[mt][nt][1]);
            *(float2*)&C[(size_t)(row + 8) * N + col] =
                make_float2(acc[mt][nt][2], acc[mt][nt][3]);
        }
    }
}

// ---------------- fused RMSNorm+RoPE (Q,K) + V rearrange -----------------------
__device__ const double c_inv8[8] = {
    1.0, 0.74989420933245582, 0.56234132519034912, 0.42169650342858224,
    0.31622776601683794, 0.23713737056616552, 0.17782794100389229,
    0.13335214321633241};
__device__ const double c_p10[4] = {1.0, 0.1, 0.01, 0.001};

__device__ __forceinline__ void normrope_row(
    int gw, int lane, __half* __restrict__ out,
    const float* __restrict__ scale, int nheads, int col0, float post) {
    int h = gw % nheads;
    int s = (gw / nheads) % S_LEN;
    int b = gw / (nheads * S_LEN);

    const float* ip = g_qkv_raw + ((size_t)(b * S_LEN + s)) * QKV_W + col0 + h * HD;
    float x1 = ip[lane];
    float x2 = ip[lane + 32];
    float ss = x1 * x1 + x2 * x2;
#pragma unroll
    for (int o = 16; o; o >>= 1) ss += __shfl_xor_sync(0xffffffffu, ss, o);
    float inv = rsqrtf(ss * (1.0f / 64.0f) + 1e-5f);
    x1 *= inv * scale[lane];
    x2 *= inv * scale[lane + 32];

    float invf = (float)(c_inv8[lane & 7] * c_p10[lane >> 3]);
    float f = (float)s * invf;
    float c, sn;
    sincosf(f, &sn, &c);   // sincosf(x, SIN*, COS*)

    size_t base = (((size_t)(b * nheads + h)) * S_LEN + s) * HD;
    out[base + lane] = __float2half_rn((x1 * c - x2 * sn) * post);
    out[base + lane + 32] = __float2half_rn((x1 * sn + x2 * c) * post);
}

// blocks: [0,8192) Q ; [8192,10240) K ; [10240,11264) V copy
__global__ void postproc_kernel(const float* __restrict__ qs,
                                const float* __restrict__ ks) {
    int bx = blockIdx.x;
    int tid = threadIdx.x;
    int wid = tid >> 5, lane = tid & 31;
    if (bx < 8192) {
        normrope_row(bx * 8 + wid, lane, g_q16, qs, NH, 0, 0.125f);
    } else if (bx < 10240) {
        normrope_row((bx - 8192) * 8 + wid, lane, g_k16, ks, NKV, DM, 1.0f);
    } else {
        int idx = (bx - 10240) * 256 + tid;   // float4 index
        int c4 = idx & 15;
        int tmp = idx >> 4;
        int s = tmp % S_LEN;
        int bk = tmp / S_LEN;
        int kvh = bk % NKV;
        int b = bk / NKV;
        float4 v = *(const float4*)(g_qkv_raw + ((size_t)(b * S_LEN + s)) * QKV_W +
                                    (DM + NKV * HD) + kvh * HD + c4 * 4);
        cvt_write_h(v, g_v16, ((size_t)bk * S_LEN + s) * HD + c4 * 4);
    }
}

// ---------------- fp16 mma.sync causal GQA flash attention ---------------------
// STATIC MAX: rmsnorm guarantees |q|=|k|=8, so |S| = |q.k|/8 <= 8 (Cauchy-
// Schwarz). Softmax uses constant shift 8 -- shift-invariant, so exact --
// eliminating per-tile max reductions, corr rescaling, and the cross-fragment
// dependency (exp of fragment kt now overlaps PV-mma of kt-1).
#define SMAX 8.0f
#define SPAD 72   // 64 + 8
#define ATT_SMEM (2 * 2 * 64 * SPAD * 2)   // 36864 bytes

__global__ __launch_bounds__(256, 2) void attn_mma_kernel() {
    extern __shared__ __align__(16) __half dsm[];

    int b = blockIdx.z, h = blockIdx.y;
    int mb = (int)(gridDim.x - 1) - (int)blockIdx.x;  // heavy CTAs first
    int kvh = h >> 2;
    int tid = threadIdx.x;
    int wid = tid >> 5, lane = tid & 31;
    int g = lane >> 2, tg = lane & 3;

    const __half* qp = g_q16 + (((size_t)(b * NH + h)) * S_LEN + mb * 128) * HD;
    const __half* kp = g_k16 + ((size_t)(b * NKV + kvh)) * S_LEN * HD;
    const __half* vp = g_v16 + ((size_t)(b * NKV + kvh)) * S_LEN * HD;

    // ---- stage Q tile [128][64] through smem, grab a-frags ----
    __half* qs = dsm;   // [128][SPAD]
#pragma unroll
    for (int i = 0; i < 4; i++) {
        int idx = tid + i * 256;          // 0..1023
        int r = idx >> 3;                 // 0..127
        int c8 = (idx & 7) * 8;
        cpa16(smem_u32(qs + (size_t)r * SPAD + c8), qp + (size_t)r * HD + c8);
    }
    CP_COMMIT; CP_WAIT0;
    __syncthreads();

    uint32_t qha[4][4];
    {
        int row = wid * 16 + (lane & 15);
#pragma unroll
        for (int kt = 0; kt < 4; kt++) {
            int col = kt * 16 + (lane >> 4) * 8;
            ldsm_x4(qha[kt][0], qha[kt][1], qha[kt][2], qha[kt][3],
                    smem_u32(qs + (size_t)row * SPAD + col));
        }
    }
    __syncthreads();

    float oacc[8][4];
#pragma unroll
    for (int nt = 0; nt < 8; nt++)
#pragma unroll
        for (int e = 0; e < 4; e++) oacc[nt][e] = 0.0f;
    float l_i[2] = {0.0f, 0.0f};   // per-thread partial sums (no rescaling needed)

    int grow = mb * 128 + wid * 16;
    int row0 = grow + g, row1 = grow + g + 8;

    auto load_kv = [&](int t, int stage) {
        int n0 = t * 64;
        __half* base = dsm + (size_t)stage * 2 * 64 * SPAD;
#pragma unroll
        for (int i = 0; i < 2; i++) {
            int idx = tid + i * 256;
            int r = idx >> 3;
            int c8 = (idx & 7) * 8;
            cpa16(smem_u32(base + (size_t)r * SPAD + c8),
                  kp + (size_t)(n0 + r) * HD + c8);
            cpa16(smem_u32(base + (size_t)(64 + r) * SPAD + c8),
                  vp + (size_t)(n0 + r) * HD + c8);
        }
    };

    int ntiles = mb * 2 + 2;
    load_kv(0, 0);
    CP_COMMIT;

    for (int t = 0; t < ntiles; t++) {
        int stage = t & 1;
        if (t + 1 < ntiles) {
            load_kv(t + 1, stage ^ 1);
            CP_COMMIT;
            CP_WAIT1;
        } else {
            CP_WAIT0;
        }
        __syncthreads();

        __half* sK = dsm + (size_t)stage * 2 * 64 * SPAD;
        __half* sV = sK + 64 * SPAD;
        int n0 = t * 64;

        // ---- S = Q K^T ----
        float sacc[8][4];
#pragma unroll
        for (int nt = 0; nt < 8; nt++)
#pragma unroll
            for (int e = 0; e < 4; e++) sacc[nt][e] = 0.0f;

#pragma unroll
        for (int kt = 0; kt < 4; kt++) {
            uint32_t kb[8][2];
            {
                int rr = (lane & 7) + ((lane >> 4) << 3);
                int cc = kt * 16 + (((lane >> 3) & 1) << 3);
#pragma unroll
                for (int nb = 0; nb < 4; nb++) {
                    uint32_t t0, t1, t2, t3;
                    ldsm_x4(t0, t1, t2, t3,
                            smem_u32(sK + (size_t)(nb * 16 + rr) * SPAD + cc));
                    kb[nb * 2 + 0][0] = t0; kb[nb * 2 + 0][1] = t1;
                    kb[nb * 2 + 1][0] = t2; kb[nb * 2 + 1][1] = t3;
                }
            }
#pragma unroll
            for (int nt = 0; nt < 8; nt++)
                mma_f16(sacc[nt], qha[kt], kb[nt]);
        }

        // ---- causal mask: only needed on diagonal tiles (warp-uniform) ----
        if (n0 + 63 > grow) {
#pragma unroll
            for (int nt = 0; nt < 8; nt++) {
                int col = n0 + nt * 8 + tg * 2;
                if (col > row0) sacc[nt][0] = -1e30f;
                if (col + 1 > row0) sacc[nt][1] = -1e30f;
                if (col > row1) sacc[nt][2] = -1e30f;
                if (col + 1 > row1) sacc[nt][3] = -1e30f;
            }
        }

        // ---- exp (static shift) fused with P pack + PV mma, per kt ----
#pragma unroll
        for (int kt = 0; kt < 4; kt++) {
            uint32_t pha[4];
#pragma unroll
            for (int half = 0; half < 2; half++) {
                float* pp = sacc[kt * 2 + half];
                pp[0] = __expf(pp[0] - SMAX);
                pp[1] = __expf(pp[1] - SMAX);
                pp[2] = __expf(pp[2] - SMAX);
                pp[3] = __expf(pp[3] - SMAX);
                l_i[0] += pp[0] + pp[1];
                l_i[1] += pp[2] + pp[3];
                __half2 a01 = __halves2half2(__float2half_rn(pp[0]),
                                             __float2half_rn(pp[1]));
                __half2 a23 = __halves2half2(__float2half_rn(pp[2]),
                                             __float2half_rn(pp[3]));
                pha[half * 2 + 0] = *(uint32_t*)&a01;
                pha[half * 2 + 1] = *(uint32_t*)&a23;
            }
            uint32_t vb[8][2];
            {
                int rr = kt * 16 + (lane & 15);
                int c0 = (lane >> 4) * 8;
#pragma unroll
                for (int nb = 0; nb < 4; nb++) {
                    uint32_t t0, t1, t2, t3;
                    ldsm_x4_t(t0, t1, t2, t3,
                              smem_u32(sV + (size_t)rr * SPAD + nb * 16 + c0));
                    vb[nb * 2 + 0][0] = t0; vb[nb * 2 + 0][1] = t1;
                    vb[nb * 2 + 1][0] = t2; vb[nb * 2 + 1][1] = t3;
                }
            }
#pragma unroll
            for (int nt = 0; nt < 8; nt++)
                mma_f16(oacc[nt], pha, vb[nt]);
        }
        __syncthreads();
    }

    // ---- final l reduction across the quad, then epilogue ----
#pragma unroll
    for (int o = 1; o <= 2; o <<= 1) {
        l_i[0] += __shfl_xor_sync(0xffffffffu, l_i[0], o);
        l_i[1] += __shfl_xor_sync(0xffffffffu, l_i[1], o);
    }
    float inv0 = 1.0f / l_i[0];
    float inv1 = 1.0f / l_i[1];
#pragma unroll
    for (int nt = 0; nt < 8; nt++) {
        int col = h * HD + nt * 8 + tg * 2;
        size_t o0 = ((size_t)(b * S_LEN + row0)) * DM + col;
        size_t o1 = ((size_t)(b * S_LEN + row1)) * DM + col;
        *(__half2*)&g_ao16[o0] = __halves2half2(
            __float2half_rn(oacc[nt][0] * inv0), __float2half_rn(oacc[nt][1] * inv0));
        *(__half2*)&g_ao16[o1] = __halves2half2(
            __float2half_rn(oacc[nt][2] * inv1), __float2half_rn(oacc[nt][3] * inv1));
    }
}

// ---------------- launcher ----------------------------------------------------
extern "C" void kernel_launch(void* const* d_in, const int* in_sizes, int n_in,
                              void* d_out, int out_size) {
    const float* x   = (const float*)d_in[0];
    const float* Wq  = (const float*)d_in[1];
    const float* Wkv = (const float*)d_in[2];
    const float* Wo  = (const float*)d_in[3];
    const float* qs  = (const float*)d_in[4];
    const float* ks  = (const float*)d_in[5];
    float* out = (float*)d_out;

    float* pqkv;
    cudaGetSymbolAddress((void**)&pqkv, g_qkv_raw);

    __half *px, *pw1, *pwo, *pao;
    cudaGetSymbolAddress((void**)&px, g_x16);
    cudaGetSymbolAddress((void**)&pw1, g_w116);
    cudaGetSymbolAddress((void**)&pwo, g_wo16);
    cudaGetSymbolAddress((void**)&pao, g_ao16);

    cudaFuncSetAttribute(attn_mma_kernel,
                         cudaFuncAttributeMaxDynamicSharedMemorySize, ATT_SMEM);

    int M = BATCH * S_LEN;  // 4096

    // 0) fused convert: everything to single fp16
    cvt_all<<<6656, 256>>>(x, Wq, Wkv, Wo);

    // 1) merged QKV projection (single fp16)
    gemm_f16<<<dim3(QKV_W / GBN, M / GBM), 128>>>(px, pw1, pqkv, M, QKV_W, DM);

    // 2) fused rmsnorm+rope (Q, K) + V rearrange
    postproc_kernel<<<11264, 256>>>(qs, ks);

    // 3) fp16 mma causal GQA attention (static-max softmax, 2-stage pipe)
    attn_mma_kernel<<<dim3(S_LEN / 128, NH, BATCH), 256, ATT_SMEM>>>();

    // 4) output projection (single fp16)
    gemm_f16<<<dim3(DM / GBN, M / GBM), 128>>>(pao, pwo, out, M, DM, DM);
}

// round 17
// speedup vs baseline: 11.7119x; 1.0887x over previous
#include <cuda_runtime.h>
#include <cuda_fp16.h>
#include <math.h>
#include <stdint.h>

#define BATCH 2
#define S_LEN 2048
#define DM 1024
#define NH 16
#define NKV 4
#define HD 64
#define KV_W 512     // 2 * NKV * HD
#define QKV_W 1536   // DM + KV_W

// ---------------- scratch (device globals; no allocs allowed) ----------------
__device__ float g_qkv_raw[BATCH * S_LEN * QKV_W];  // X @ [Wq | Wkv]

// fp16 buffers (all single precision; error budget calibrated)
__device__ __half g_x16[BATCH * S_LEN * DM];
__device__ __half g_w116[DM * QKV_W];   // [Wq | Wkv]
__device__ __half g_wo16[DM * DM];      // Wo
__device__ __half g_ao16[BATCH * S_LEN * DM];

// fp16 attention operands
__device__ __half g_q16[BATCH * NH * S_LEN * HD];
__device__ __half g_k16[BATCH * NKV * S_LEN * HD];
__device__ __half g_v16[BATCH * NKV * S_LEN * HD];

// ---------------- helpers ------------------------------------------------------
__device__ __forceinline__ uint32_t smem_u32(const void* p) {
    return (uint32_t)__cvta_generic_to_shared(p);
}
__device__ __forceinline__ void cpa16(uint32_t s, const void* g) {
    asm volatile("cp.async.cg.shared.global [%0], [%1], 16;" :: "r"(s), "l"(g));
}
#define CP_COMMIT asm volatile("cp.async.commit_group;")
#define CP_WAIT0  asm volatile("cp.async.wait_group 0;")
#define CP_WAIT1  asm volatile("cp.async.wait_group 1;")

__device__ __forceinline__ void ldsm_x4(uint32_t& r0, uint32_t& r1,
                                        uint32_t& r2, uint32_t& r3, uint32_t a) {
    asm volatile("ldmatrix.sync.aligned.m8n8.x4.shared.b16 {%0,%1,%2,%3},[%4];"
                 : "=r"(r0), "=r"(r1), "=r"(r2), "=r"(r3) : "r"(a));
}
__device__ __forceinline__ void ldsm_x4_t(uint32_t& r0, uint32_t& r1,
                                          uint32_t& r2, uint32_t& r3, uint32_t a) {
    asm volatile("ldmatrix.sync.aligned.m8n8.x4.trans.shared.b16 {%0,%1,%2,%3},[%4];"
                 : "=r"(r0), "=r"(r1), "=r"(r2), "=r"(r3) : "r"(a));
}
__device__ __forceinline__ void mma_f16(float* c, const uint32_t* a,
                                        const uint32_t* b) {
    asm volatile(
        "mma.sync.aligned.m16n8k16.row.col.f32.f16.f16.f32 "
        "{%0,%1,%2,%3},{%4,%5,%6,%7},{%8,%9},{%0,%1,%2,%3};"
        : "+f"(c[0]), "+f"(c[1]), "+f"(c[2]), "+f"(c[3])
        : "r"(a[0]), "r"(a[1]), "r"(a[2]), "r"(a[3]), "r"(b[0]), "r"(b[1]));
}
// packed f32x2 -> f16x2 (lo in low half)
#define CVT_F16X2(r, hi, lo) \
    asm("cvt.rn.f16x2.f32 %0, %1, %2;" : "=r"(r) : "f"(hi), "f"(lo))

__device__ __forceinline__ void cvt_write_h(float4 v, __half* dst, size_t o) {
    *(__half2*)(dst + o) = __halves2half2(__float2half_rn(v.x), __float2half_rn(v.y));
    *(__half2*)(dst + o + 2) = __halves2half2(__float2half_rn(v.z), __float2half_rn(v.w));
}

// regions: [0,4096) X ; [4096,5120) Wq->w1 ; [5120,5632) Wkv->w1 ; [5632,6656) Wo
__global__ void cvt_all(const float* __restrict__ x, const float* __restrict__ Wq,
                        const float* __restrict__ Wkv, const float* __restrict__ Wo) {
    int bx = blockIdx.x;
    int tid = threadIdx.x;
    if (bx < 4096) {
        int i = bx * 256 + tid;
        float4 v = *(const float4*)(x + (size_t)i * 4);
        cvt_write_h(v, g_x16, (size_t)i * 4);
    } else if (bx < 5120) {
        int i = (bx - 4096) * 256 + tid;
        int r = (i * 4) / DM, c = (i * 4) % DM;
        float4 v = *(const float4*)(Wq + (size_t)r * DM + c);
        cvt_write_h(v, g_w116, (size_t)r * QKV_W + c);
    } else if (bx < 5632) {
        int i = (bx - 5120) * 256 + tid;
        int r = (i * 4) / KV_W, c = (i * 4) % KV_W;
        float4 v = *(const float4*)(Wkv + (size_t)r * KV_W + c);
        cvt_write_h(v, g_w116, (size_t)r * QKV_W + DM + c);
    } else {
        int i = (bx - 5632) * 256 + tid;
        float4 v = *(const float4*)(Wo + (size_t)i * 4);
        cvt_write_h(v, g_wo16, (size_t)i * 4);
    }
}

// ---------------- single-fp16 mma GEMM, 64x64 warp tiles, 2 CTAs/SM ------------
#define GBM 128
#define GBN 128
#define GBK 32

__global__ __launch_bounds__(128, 2) void gemm_f16(
    const __half* __restrict__ A, const __half* __restrict__ B,
    float* __restrict__ C, int M, int N, int K) {
    __shared__ __align__(16) __half As[2][GBM][GBK + 8];
    __shared__ __align__(16) __half Bs[2][GBK][GBN + 8];

    int tid = threadIdx.x;
    int wid = tid >> 5, lane = tid & 31;
    int bm = blockIdx.y * GBM, bn = blockIdx.x * GBN;
    int wm = (wid & 1) * 64;
    int wn = (wid >> 1) * 64;

    int T = K / GBK;

    auto prefetch = [&](int t, int buf) {
        int kl = t * GBK;
#pragma unroll
        for (int i = 0; i < 4; i++) {
            int idx = tid + i * 128;
            int ar = idx >> 2, ac = (idx & 3) * 8;
            cpa16(smem_u32(&As[buf][ar][ac]), A + (size_t)(bm + ar) * K + kl + ac);
            int br = idx >> 4, bc = (idx & 15) * 8;
            cpa16(smem_u32(&Bs[buf][br][bc]), B + (size_t)(kl + br) * N + bn + bc);
        }
    };

    float acc[4][8][4];
#pragma unroll
    for (int i = 0; i < 4; i++)
#pragma unroll
        for (int j = 0; j < 8; j++)
#pragma unroll
            for (int e = 0; e < 4; e++) acc[i][j][e] = 0.0f;

    prefetch(0, 0);
    CP_COMMIT;

    for (int t = 0; t < T; t++) {
        int buf = t & 1;
        CP_WAIT0;
        __syncthreads();
        if (t + 1 < T) {
            prefetch(t + 1, buf ^ 1);
            CP_COMMIT;
        }

#pragma unroll
        for (int k0 = 0; k0 < GBK; k0 += 16) {
            uint32_t a[4][4];
#pragma unroll
            for (int mt = 0; mt < 4; mt++) {
                int row = wm + mt * 16 + (lane & 15);
                int col = k0 + (lane >> 4) * 8;
                ldsm_x4(a[mt][0], a[mt][1], a[mt][2], a[mt][3],
                        smem_u32(&As[buf][row][col]));
            }
            uint32_t b[8][2];
#pragma unroll
            for (int np = 0; np < 4; np++) {
                int r = k0 + (lane & 15);
                int col = wn + np * 16 + (lane >> 4) * 8;
                uint32_t t0, t1, t2, t3;
                ldsm_x4_t(t0, t1, t2, t3, smem_u32(&Bs[buf][r][col]));
                b[np * 2 + 0][0] = t0; b[np * 2 + 0][1] = t1;
                b[np * 2 + 1][0] = t2; b[np * 2 + 1][1] = t3;
            }
#pragma unroll
            for (int mt = 0; mt < 4; mt++)
#pragma unroll
                for (int nt = 0; nt < 8; nt++)
                    mma_f16(acc[mt][nt], a[mt], b[nt]);
        }
    }

    int g = lane >> 2, tg = lane & 3;
#pragma unroll
    for (int mt = 0; mt < 4; mt++) {
#pragma unroll
        for (int nt = 0; nt < 8; nt++) {
            int row = bm + wm + mt * 16 + g;
            int col = bn + wn + nt * 8 + tg * 2;
            *(float2*)&C[(size_t)row * N + col] =
                make_float2(acc[mt][nt][0], acc[mt][nt][1]);
            *(float2*)&C[(size_t)(row + 8) * N + col] =
                make_float2(acc[mt][nt][2], acc[mt][nt][3]);
        }
    }
}

// ---------------- fused RMSNorm+RoPE (Q,K) + V rearrange -----------------------
__device__ const double c_inv8[8] = {
    1.0, 0.74989420933245582, 0.56234132519034912, 0.42169650342858224,
    0.31622776601683794, 0.23713737056616552, 0.17782794100389229,
    0.13335214321633241};
__device__ const double c_p10[4] = {1.0, 0.1, 0.01, 0.001};

__device__ __forceinline__ void normrope_row(
    int gw, int lane, __half* __restrict__ out,
    const float* __restrict__ scale, int nheads, int col0, float post) {
    int h = gw % nheads;
    int s = (gw / nheads) % S_LEN;
    int b = gw / (nheads * S_LEN);

    const float* ip = g_qkv_raw + ((size_t)(b * S_LEN + s)) * QKV_W + col0 + h * HD;
    float x1 = ip[lane];
    float x2 = ip[lane + 32];
    float ss = x1 * x1 + x2 * x2;
#pragma unroll
    for (int o = 16; o; o >>= 1) ss += __shfl_xor_sync(0xffffffffu, ss, o);
    float inv = rsqrtf(ss * (1.0f / 64.0f) + 1e-5f);
    x1 *= inv * scale[lane];
    x2 *= inv * scale[lane + 32];

    float invf = (float)(c_inv8[lane & 7] * c_p10[lane >> 3]);
    float f = (float)s * invf;
    float c, sn;
    sincosf(f, &sn, &c);   // sincosf(x, SIN*, COS*)

    size_t base = (((size_t)(b * nheads + h)) * S_LEN + s) * HD;
    out[base + lane] = __float2half_rn((x1 * c - x2 * sn) * post);
    out[base + lane + 32] = __float2half_rn((x1 * sn + x2 * c) * post);
}

// blocks: [0,8192) Q ; [8192,10240) K ; [10240,11264) V copy
__global__ void postproc_kernel(const float* __restrict__ qs,
                                const float* __restrict__ ks) {
    int bx = blockIdx.x;
    int tid = threadIdx.x;
    int wid = tid >> 5, lane = tid & 31;
    if (bx < 8192) {
        normrope_row(bx * 8 + wid, lane, g_q16, qs, NH, 0, 0.125f);
    } else if (bx < 10240) {
        normrope_row((bx - 8192) * 8 + wid, lane, g_k16, ks, NKV, DM, 1.0f);
    } else {
        int idx = (bx - 10240) * 256 + tid;   // float4 index
        int c4 = idx & 15;
        int tmp = idx >> 4;
        int s = tmp % S_LEN;
        int bk = tmp / S_LEN;
        int kvh = bk % NKV;
        int b = bk / NKV;
        float4 v = *(const float4*)(g_qkv_raw + ((size_t)(b * S_LEN + s)) * QKV_W +
                                    (DM + NKV * HD) + kvh * HD + c4 * 4);
        cvt_write_h(v, g_v16, ((size_t)bk * S_LEN + s) * HD + c4 * 4);
    }
}

// ---------------- fp16 mma causal GQA flash attention --------------------------
// Persistent 296-CTA grid (one exact wave, 2 CTAs/SM), balanced item pairing.
// 128-key smem stages (2 x 64-key compute chunks) -> half the barriers.
// Static-max softmax (|S| <= 8 by Cauchy-Schwarz after rmsnorm).
#define SMAX 8.0f
#define SPAD 72   // 64 + 8
#define NCTA 296
#define NITEM 512
// stage: K[128][SPAD] + V[128][SPAD]; two stages
#define ATT_SMEM (2 * 2 * 128 * SPAD * 2)   // 73728 bytes

__global__ __launch_bounds__(256, 2) void attn_mma_kernel() {
    extern __shared__ __align__(16) __half dsm[];

    int bid = blockIdx.x;
    int tid = threadIdx.x;
    int wid = tid >> 5, lane = tid & 31;
    int g = lane >> 2, tg = lane & 3;

    int nitems = (bid < NITEM - NCTA) ? 2 : 1;
    for (int it = 0; it < nitems; it++) {
        int w = (it == 0) ? bid : (NITEM - 1 - bid);
        int mb = 15 - (w >> 5);            // heavy (large mb) for small w
        int bh = w & 31;
        int h = bh & 15, b = bh >> 4;
        int kvh = h >> 2;

        const __half* qp = g_q16 + (((size_t)(b * NH + h)) * S_LEN + mb * 128) * HD;
        const __half* kp = g_k16 + ((size_t)(b * NKV + kvh)) * S_LEN * HD;
        const __half* vp = g_v16 + ((size_t)(b * NKV + kvh)) * S_LEN * HD;

        // ---- stage Q tile [128][64] through smem, grab a-frags ----
        __half* qs = dsm;   // [128][SPAD] (reuses stage-0 K region)
#pragma unroll
        for (int i = 0; i < 4; i++) {
            int idx = tid + i * 256;
            int r = idx >> 3;
            int c8 = (idx & 7) * 8;
            cpa16(smem_u32(qs + (size_t)r * SPAD + c8), qp + (size_t)r * HD + c8);
        }
        CP_COMMIT; CP_WAIT0;
        __syncthreads();

        uint32_t qha[4][4];
        {
            int row = wid * 16 + (lane & 15);
#pragma unroll
            for (int kt = 0; kt < 4; kt++) {
                int col = kt * 16 + (lane >> 4) * 8;
                ldsm_x4(qha[kt][0], qha[kt][1], qha[kt][2], qha[kt][3],
                        smem_u32(qs + (size_t)row * SPAD + col));
            }
        }
        __syncthreads();   // all ldsm done before K stage-0 cpa overwrites

        float oacc[8][4];
#pragma unroll
        for (int nt = 0; nt < 8; nt++)
#pragma unroll
            for (int e = 0; e < 4; e++) oacc[nt][e] = 0.0f;
        float l_i[2] = {0.0f, 0.0f};

        int grow = mb * 128 + wid * 16;
        int row0 = grow + g, row1 = grow + g + 8;

        auto load_kv = [&](int t, int stage) {
            int n0 = t * 128;
            __half* base = dsm + (size_t)stage * 2 * 128 * SPAD;
#pragma unroll
            for (int i = 0; i < 4; i++) {
                int idx = tid + i * 256;      // 0..1023
                int r = idx >> 3;             // 0..127
                int c8 = (idx & 7) * 8;
                cpa16(smem_u32(base + (size_t)r * SPAD + c8),
                      kp + (size_t)(n0 + r) * HD + c8);
                cpa16(smem_u32(base + (size_t)(128 + r) * SPAD + c8),
                      vp + (size_t)(n0 + r) * HD + c8);
            }
        };

        int n128 = mb + 1;
        load_kv(0, 0);
        CP_COMMIT;

        for (int t = 0; t < n128; t++) {
            int stage = t & 1;
            if (t + 1 < n128) {
                load_kv(t + 1, stage ^ 1);
                CP_COMMIT;
                CP_WAIT1;
            } else {
                CP_WAIT0;
            }
            __syncthreads();

            __half* sK = dsm + (size_t)stage * 2 * 128 * SPAD;
            __half* sV = sK + 128 * SPAD;

#pragma unroll
            for (int half64 = 0; half64 < 2; half64++) {
                int n0 = t * 128 + half64 * 64;
                int roff = half64 * 64;   // row offset within 128-row stage

                // ---- S = Q K^T ----
                float sacc[8][4];
#pragma unroll
                for (int nt = 0; nt < 8; nt++)
#pragma unroll
                    for (int e = 0; e < 4; e++) sacc[nt][e] = 0.0f;

#pragma unroll
                for (int kt = 0; kt < 4; kt++) {
                    uint32_t kb[8][2];
                    {
                        int rr = roff + (lane & 7) + ((lane >> 4) << 3);
                        int cc = kt * 16 + (((lane >> 3) & 1) << 3);
#pragma unroll
                        for (int nb = 0; nb < 4; nb++) {
                            uint32_t t0, t1, t2, t3;
                            ldsm_x4(t0, t1, t2, t3,
                                    smem_u32(sK + (size_t)(nb * 16 + rr) * SPAD + cc));
                            kb[nb * 2 + 0][0] = t0; kb[nb * 2 + 0][1] = t1;
                            kb[nb * 2 + 1][0] = t2; kb[nb * 2 + 1][1] = t3;
                        }
                    }
#pragma unroll
                    for (int nt = 0; nt < 8; nt++)
                        mma_f16(sacc[nt], qha[kt], kb[nt]);
                }

                // ---- causal mask: diagonal chunks only (warp-uniform) ----
                if (n0 + 63 > grow) {
#pragma unroll
                    for (int nt = 0; nt < 8; nt++) {
                        int col = n0 + nt * 8 + tg * 2;
                        if (col > row0) sacc[nt][0] = -1e30f;
                        if (col + 1 > row0) sacc[nt][1] = -1e30f;
                        if (col > row1) sacc[nt][2] = -1e30f;
                        if (col + 1 > row1) sacc[nt][3] = -1e30f;
                    }
                }

                // ---- exp (static shift) + pack + PV mma, per kt ----
#pragma unroll
                for (int kt = 0; kt < 4; kt++) {
                    uint32_t pha[4];
#pragma unroll
                    for (int hf = 0; hf < 2; hf++) {
                        float* pp = sacc[kt * 2 + hf];
                        pp[0] = __expf(pp[0] - SMAX);
                        pp[1] = __expf(pp[1] - SMAX);
                        pp[2] = __expf(pp[2] - SMAX);
                        pp[3] = __expf(pp[3] - SMAX);
                        l_i[0] += pp[0] + pp[1];
                        l_i[1] += pp[2] + pp[3];
                        CVT_F16X2(pha[hf * 2 + 0], pp[1], pp[0]);
                        CVT_F16X2(pha[hf * 2 + 1], pp[3], pp[2]);
                    }
                    uint32_t vb[8][2];
                    {
                        int rr = roff + kt * 16 + (lane & 15);
                        int c0 = (lane >> 4) * 8;
#pragma unroll
                        for (int nb = 0; nb < 4; nb++) {
                            uint32_t t0, t1, t2, t3;
                            ldsm_x4_t(t0, t1, t2, t3,
                                      smem_u32(sV + (size_t)rr * SPAD + nb * 16 + c0));
                            vb[nb * 2 + 0][0] = t0; vb[nb * 2 + 0][1] = t1;
                            vb[nb * 2 + 1][0] = t2; vb[nb * 2 + 1][1] = t3;
                        }
                    }
#pragma unroll
                    for (int nt = 0; nt < 8; nt++)
                        mma_f16(oacc[nt], pha, vb[nt]);
                }
            }
            __syncthreads();
        }

        // ---- final l reduction across the quad, then epilogue ----
#pragma unroll
        for (int o = 1; o <= 2; o <<= 1) {
            l_i[0] += __shfl_xor_sync(0xffffffffu, l_i[0], o);
            l_i[1] += __shfl_xor_sync(0xffffffffu, l_i[1], o);
        }
        float inv0 = 1.0f / l_i[0];
        float inv1 = 1.0f / l_i[1];
#pragma unroll
        for (int nt = 0; nt < 8; nt++) {
            int col = h * HD + nt * 8 + tg * 2;
            size_t o0 = ((size_t)(b * S_LEN + row0)) * DM + col;
            size_t o1 = ((size_t)(b * S_LEN + row1)) * DM + col;
            uint32_t r0, r1;
            CVT_F16X2(r0, oacc[nt][1] * inv0, oacc[nt][0] * inv0);
            CVT_F16X2(r1, oacc[nt][3] * inv1, oacc[nt][2] * inv1);
            *(uint32_t*)&g_ao16[o0] = r0;
            *(uint32_t*)&g_ao16[o1] = r1;
        }
    }
}

// ---------------- launcher ----------------------------------------------------
extern "C" void kernel_launch(void* const* d_in, const int* in_sizes, int n_in,
                              void* d_out, int out_size) {
    const float* x   = (const float*)d_in[0];
    const float* Wq  = (const float*)d_in[1];
    const float* Wkv = (const float*)d_in[2];
    const float* Wo  = (const float*)d_in[3];
    const float* qs  = (const float*)d_in[4];
    const float* ks  = (const float*)d_in[5];
    float* out = (float*)d_out;

    float* pqkv;
    cudaGetSymbolAddress((void**)&pqkv, g_qkv_raw);

    __half *px, *pw1, *pwo, *pao;
    cudaGetSymbolAddress((void**)&px, g_x16);
    cudaGetSymbolAddress((void**)&pw1, g_w116);
    cudaGetSymbolAddress((void**)&pwo, g_wo16);
    cudaGetSymbolAddress((void**)&pao, g_ao16);

    cudaFuncSetAttribute(attn_mma_kernel,
                         cudaFuncAttributeMaxDynamicSharedMemorySize, ATT_SMEM);

    int M = BATCH * S_LEN;  // 4096

    // 0) fused convert: everything to single fp16
    cvt_all<<<6656, 256>>>(x, Wq, Wkv, Wo);

    // 1) merged QKV projection (single fp16)
    gemm_f16<<<dim3(QKV_W / GBN, M / GBM), 128>>>(px, pw1, pqkv, M, QKV_W, DM);

    // 2) fused rmsnorm+rope (Q, K) + V rearrange
    postproc_kernel<<<11264, 256>>>(qs, ks);

    // 3) persistent fp16 mma causal GQA attention (one exact wave)
    attn_mma_kernel<<<NCTA, 256, ATT_SMEM>>>();

    // 4) output projection (single fp16)
    gemm_f16<<<dim3(DM / GBN, M / GBM), 128>>>(pao, pwo, out, M, DM, DM);
}